// round 4
// baseline (speedup 1.0000x reference)
#include <cuda_runtime.h>
#include <cuda_bf16.h>
#include <cstdint>

// Problem constants
#define HB 200
#define WB 200
#define HW 40000          // H*W
#define BQ 4              // batch
#define NBT 8             // 2*batch (cat)
#define CI 128            // input channels
#define CE 64             // embed channels
#define RR 4              // neighborhood radius
#define K81 81            // 9x9 offsets

typedef unsigned long long ull;

// ---------------- packed f32x2 helpers ----------------
__device__ __forceinline__ ull pack2(float x, float y) {
    ull r; asm("mov.b64 %0,{%1,%2};" : "=l"(r) : "f"(x), "f"(y)); return r;
}
__device__ __forceinline__ float2 unpack2(ull v) {
    float2 r; asm("mov.b64 {%0,%1},%2;" : "=f"(r.x), "=f"(r.y) : "l"(v)); return r;
}
__device__ __forceinline__ void ffma2(ull& c, ull a, ull b) {
    asm("fma.rn.f32x2 %0,%1,%2,%0;" : "+l"(c) : "l"(a), "l"(b));
}

__device__ __forceinline__ uint32_t smem_u32(const void* p) {
    uint32_t a;
    asm("{ .reg .u64 t; cvta.to.shared.u64 t, %1; cvt.u32.u64 %0, t; }" : "=r"(a) : "l"(p));
    return a;
}

// warp-level bf16 MMA: D(16x8,f32) += A(16x16,bf16) * B(16x8,bf16)
__device__ __forceinline__ void mma16816(float* c, const uint32_t* a, uint32_t b0, uint32_t b1) {
    asm volatile(
        "mma.sync.aligned.m16n8k16.row.col.f32.bf16.bf16.f32 "
        "{%0,%1,%2,%3}, {%4,%5,%6,%7}, {%8,%9}, {%0,%1,%2,%3};"
        : "+f"(c[0]), "+f"(c[1]), "+f"(c[2]), "+f"(c[3])
        : "r"(a[0]), "r"(a[1]), "r"(a[2]), "r"(a[3]), "r"(b0), "r"(b1));
}
__device__ __forceinline__ void ldmatrix_x4(uint32_t* r, uint32_t addr) {
    asm volatile("ldmatrix.sync.aligned.m8n8.x4.shared.b16 {%0,%1,%2,%3}, [%4];"
                 : "=r"(r[0]), "=r"(r[1]), "=r"(r[2]), "=r"(r[3]) : "r"(addr));
}

// ---------------- scratch (device globals) ------------
__device__ float g_T1 [(size_t)NBT * CE * HW];           // ec1/ag1 out, NCHW fp32
__device__ __nv_bfloat16 g_T1B[(size_t)NBT * HW * CE];   // NHWC bf16 version
__device__ float g_E2 [(size_t)NBT * HW * CE];           // ec2 out, NHWC fp32
__device__ float g_W81[(size_t)BQ  * HW * K81];
__device__ float g_FSN[(size_t)BQ  * HW * CI];
__device__ float g_ALN[(size_t)BQ  * HW * CI];
__device__ float g_ALC[(size_t)BQ  * CI * HW];
__device__ float g_A2 [(size_t)NBT * HW * 32];           // ag2 out, NHWC fp32
__device__ float g_A3 [(size_t)NBT * HW];
__device__ __nv_bfloat16 g_WTE[9 * 64 * 64];             // ec2 weights bf16 [tap][oc][ic]
__device__ __nv_bfloat16 g_WTA[9 * 32 * 64];             // ag2 weights bf16

// ---------------- generic 32x32 tiled transpose: [n][A][B] -> [n][B][A] ------
__global__ void k_trans(const float* __restrict__ src, float* __restrict__ dst,
                        int A, int B) {
    __shared__ float t[32][33];
    int n = blockIdx.z;
    size_t base = (size_t)n * A * B;
    int a0 = blockIdx.y * 32, b0 = blockIdx.x * 32;
    int tx = threadIdx.x, ty = threadIdx.y;
#pragma unroll
    for (int i = 0; i < 4; i++) {
        int a = a0 + ty + i * 8, b = b0 + tx;
        if (a < A && b < B) t[ty + i * 8][tx] = src[base + (size_t)a * B + b];
    }
    __syncthreads();
#pragma unroll
    for (int i = 0; i < 4; i++) {
        int b = b0 + ty + i * 8, a = a0 + tx;
        if (a < A && b < B) dst[base + (size_t)b * A + a] = t[tx][ty + i * 8];
    }
}

// ---------------- NCHW fp32 [n][64][HW] -> NHWC bf16 [n][HW][64] --------------
__global__ void k_tobf16(const float* __restrict__ src, __nv_bfloat16* __restrict__ dst) {
    __shared__ float t[32][33];
    int n = blockIdx.z, at = blockIdx.y;
    const float* s = src + (size_t)n * CE * HW;
    __nv_bfloat16* d = dst + (size_t)n * HW * CE;
    int b0 = blockIdx.x * 32;
    int tx = threadIdx.x, ty = threadIdx.y;
#pragma unroll
    for (int i = 0; i < 4; i++)
        t[ty + i * 8][tx] = s[(size_t)(at * 32 + ty + i * 8) * HW + b0 + tx];
    __syncthreads();
#pragma unroll
    for (int i = 0; i < 4; i++)
        d[(size_t)(b0 + ty + i * 8) * CE + at * 32 + tx] = __float2bfloat16(t[tx][ty + i * 8]);
}

// ---------------- weight prep: [OC][64][3][3] fp32 -> [9][OC][64] bf16 --------
__global__ void k_wprep(const float* __restrict__ w, __nv_bfloat16* __restrict__ dst, int OC) {
    int i = blockIdx.x * 256 + threadIdx.x;
    int tot = 9 * OC * 64;
    if (i >= tot) return;
    int ic = i & 63;
    int rest = i >> 6;
    int oc = rest % OC;
    int tap = rest / OC;
    dst[((size_t)tap * OC + oc) * 64 + ic] = __float2bfloat16(w[((size_t)oc * 64 + ic) * 9 + tap]);
}

// ---------------- 1x1 conv + ReLU:  NCHW in -> NCHW out (OC=64) --------------
template <int IC>
__global__ __launch_bounds__(256) void k_conv1(
    const float* __restrict__ in0, const float* __restrict__ in1,
    const float* __restrict__ w, const float* __restrict__ bias,
    float* __restrict__ out)
{
    __shared__ __align__(16) float ws[IC][64];
    int n = blockIdx.y;
    const float* src = ((n < BQ) ? in0 : in1) + (size_t)(n & 3) * IC * HW;
    int tid = threadIdx.x;
    for (int i = tid; i < IC * 64; i += 256) {
        int ic = i >> 6, oc = i & 63;
        ws[ic][oc] = w[oc * IC + ic];
    }
    __syncthreads();

    int ocg = tid >> 6, j = tid & 63;
    int pb = blockIdx.x * 256;
    int p[4]; bool pv[4];
#pragma unroll
    for (int m = 0; m < 4; m++) { p[m] = pb + j + 64 * m; pv[m] = p[m] < HW; }

    ull acc[4][8];
#pragma unroll
    for (int m = 0; m < 4; m++)
#pragma unroll
        for (int u = 0; u < 8; u++) acc[m][u] = 0ull;

    for (int ic = 0; ic < IC; ic++) {
        ull x2[4];
#pragma unroll
        for (int m = 0; m < 4; m++) {
            float xv = pv[m] ? src[(size_t)ic * HW + p[m]] : 0.f;
            x2[m] = pack2(xv, xv);
        }
        const ull* wr = reinterpret_cast<const ull*>(&ws[ic][ocg * 16]);
        ull wv[8];
#pragma unroll
        for (int u = 0; u < 8; u++) wv[u] = wr[u];
#pragma unroll
        for (int m = 0; m < 4; m++)
#pragma unroll
            for (int u = 0; u < 8; u++) ffma2(acc[m][u], wv[u], x2[m]);
    }

    float* op = out + (size_t)n * 64 * HW;
#pragma unroll
    for (int m = 0; m < 4; m++) {
        if (!pv[m]) continue;
#pragma unroll
        for (int u = 0; u < 8; u++) {
            float2 v = unpack2(acc[m][u]);
            int oc = ocg * 16 + 2 * u;
            op[(size_t)oc * HW + p[m]]       = fmaxf(v.x + bias[oc], 0.f);
            op[(size_t)(oc + 1) * HW + p[m]] = fmaxf(v.y + bias[oc + 1], 0.f);
        }
    }
}

// ---------------- 3x3 conv via warp-level bf16 mma.sync -----------------------
// CTA: 128 pixels (M) x OC (N). K = 9 taps x 64 ic. A tile rebuilt per tap.
// Input NHWC bf16 [8][HW][64]; weights [9][OC][64] bf16; output NHWC fp32.
// SMEM rows padded to 72 halves (144B) for conflict-free ldmatrix / LDS.
template <int OC>
__global__ __launch_bounds__(256) void conv3_hmma(
    const __nv_bfloat16* __restrict__ inb,
    const __nv_bfloat16* __restrict__ wt,
    const float* __restrict__ bias,
    float* __restrict__ out)
{
    constexpr int LDA = 72;               // halves per A row
    constexpr int NT  = OC / 8;           // n-tiles per warp
    __shared__ __align__(16) __nv_bfloat16 As[128 * LDA];
    __shared__ __align__(16) __nv_bfloat16 Bs[OC * LDA];

    int tid = threadIdx.x;
    int wid = tid >> 5, l = tid & 31;
    int n = blockIdx.y;
    int p0 = blockIdx.x * 128;

    // A rebuild mapping: thread t handles row r=t>>1, half h=t&1 (32 halves)
    int ar = tid >> 1, ah = tid & 1;
    int ap = p0 + ar;
    bool apv = ap < HW;
    int ay = ap / WB, ax = ap - ay * WB;

    uint32_t as_base = smem_u32(As);
    uint32_t bs_base = smem_u32(Bs);

    float acc[NT][4];
#pragma unroll
    for (int t = 0; t < NT; t++)
#pragma unroll
        for (int i = 0; i < 4; i++) acc[t][i] = 0.f;

    // ldmatrix lane address for this warp (A row-major, m16k16 tiles)
    int m0 = wid * 16;

    for (int tap = 0; tap < 9; tap++) {
        int dy = tap / 3 - 1, dx = tap % 3 - 1;
        __syncthreads();
        // --- rebuild A tile
        {
            bool v = apv && ((unsigned)(ay + dy) < HB) && ((unsigned)(ax + dx) < WB);
            const uint4* src = reinterpret_cast<const uint4*>(
                inb + ((size_t)n * HW + (ap + dy * WB + dx)) * CE + ah * 32);
            uint4* dst = reinterpret_cast<uint4*>(As + ar * LDA + ah * 32);
            uint4 zz = make_uint4(0u, 0u, 0u, 0u);
#pragma unroll
            for (int c = 0; c < 4; c++) dst[c] = v ? src[c] : zz;
        }
        // --- stage B tap: OC rows x 64 halves
        if (tid < OC * 2) {
            int row = tid >> 1, h = tid & 1;
            const uint4* src = reinterpret_cast<const uint4*>(
                wt + ((size_t)tap * OC + row) * 64 + h * 32);
            uint4* dst = reinterpret_cast<uint4*>(Bs + row * LDA + h * 32);
#pragma unroll
            for (int c = 0; c < 4; c++) dst[c] = src[c];
        }
        __syncthreads();

        // --- 4 K-chunks of 16
#pragma unroll
        for (int ks = 0; ks < 4; ks++) {
            uint32_t afrag[4];
            uint32_t aaddr = as_base +
                ((m0 + (l & 15)) * LDA + ((l >> 4) * 8 + ks * 16)) * 2;
            ldmatrix_x4(afrag, aaddr);
#pragma unroll
            for (int nt = 0; nt < NT; nt++) {
                uint32_t baddr = bs_base +
                    ((nt * 8 + (l >> 2)) * LDA + (ks * 16 + (l & 3) * 2)) * 2;
                uint32_t b0 = *reinterpret_cast<const uint32_t*>((const char*)nullptr + 0); // placeholder (unused)
                (void)b0;
                uint32_t bv0, bv1;
                asm volatile("ld.shared.b32 %0, [%1];" : "=r"(bv0) : "r"(baddr));
                asm volatile("ld.shared.b32 %0, [%1];" : "=r"(bv1) : "r"(baddr + 16));
                mma16816(acc[nt], afrag, bv0, bv1);
            }
        }
    }

    // --- epilogue: bias + ReLU, NHWC fp32 stores
    int row_a = m0 + (l >> 2);       // C rows t/4 and t/4+8
    int col0 = (l & 3) * 2;
#pragma unroll
    for (int half = 0; half < 2; half++) {
        int prow = p0 + row_a + half * 8;
        if (prow >= HW) continue;
        float* ob = out + ((size_t)n * HW + prow) * OC;
#pragma unroll
        for (int nt = 0; nt < NT; nt++) {
            int c = nt * 8 + col0;
            float2 v;
            v.x = fmaxf(acc[nt][half * 2 + 0] + bias[c],     0.f);
            v.y = fmaxf(acc[nt][half * 2 + 1] + bias[c + 1], 0.f);
            *reinterpret_cast<float2*>(ob + c) = v;
        }
    }
}

// ---------------- correlation (81 offsets) + softmax, fused ------------------
__global__ __launch_bounds__(256) void k_corr(
    const float* __restrict__ e2, float* __restrict__ w81)
{
    int n = blockIdx.y;
    int warp = threadIdx.x >> 5, l = threadIdx.x & 31;
    int p = blockIdx.x * 8 + warp;
    if (p >= HW) return;
    int y = p / WB, x = p - y * WB;

    const float* esel = e2 + ((size_t)n * HW + p) * CE;
    const float* ecur = e2 + (size_t)(n + BQ) * HW * CE;
    float2 es = *(const float2*)(esel + 2 * l);

    float c0 = 0.f, c1 = 0.f, c2 = -3.0e38f;
    int k = 0;
#pragma unroll
    for (int di = -RR; di <= RR; di++) {
        int yy = y + di; bool vy = (unsigned)yy < HB;
#pragma unroll
        for (int dj = -RR; dj <= RR; dj++) {
            int xx = x + dj;
            float2 ec = make_float2(0.f, 0.f);
            if (vy && (unsigned)xx < WB)
                ec = *(const float2*)(ecur + ((size_t)(yy * WB + xx)) * CE + 2 * l);
            float ps = es.x * ec.x + es.y * ec.y;
#pragma unroll
            for (int s = 16; s > 0; s >>= 1) ps += __shfl_xor_sync(0xffffffffu, ps, s);
            if (k < 32)      { if (l == k)      c0 = ps; }
            else if (k < 64) { if (l == k - 32) c1 = ps; }
            else             { if (l == k - 64) c2 = ps; }
            k++;
        }
    }
    float mx = fmaxf(c0, fmaxf(c1, c2));
#pragma unroll
    for (int s = 16; s > 0; s >>= 1) mx = fmaxf(mx, __shfl_xor_sync(0xffffffffu, mx, s));
    float e0 = __expf(c0 - mx);
    float e1 = __expf(c1 - mx);
    float e2v = (l < 17) ? __expf(c2 - mx) : 0.f;
    float sm = e0 + e1 + e2v;
#pragma unroll
    for (int s = 16; s > 0; s >>= 1) sm += __shfl_xor_sync(0xffffffffu, sm, s);
    float inv = 1.f / sm;
    size_t base = ((size_t)n * HW + p) * K81;
    w81[base + l]      = e0 * inv;
    w81[base + 32 + l] = e1 * inv;
    if (l < 17) w81[base + 64 + l] = e2v * inv;
}

// ---------------- weighted neighborhood aggregation --------------------------
__global__ __launch_bounds__(256) void k_align(
    const float* __restrict__ w81, const float* __restrict__ fsn,
    float* __restrict__ aln)
{
    int n = blockIdx.y;
    int warp = threadIdx.x >> 5, l = threadIdx.x & 31;
    int p = blockIdx.x * 8 + warp;
    if (p >= HW) return;
    int y = p / WB, x = p - y * WB;

    const float* wp = w81 + ((size_t)n * HW + p) * K81;
    const float* fb = fsn + (size_t)n * HW * CI;
    float4 acc = make_float4(0.f, 0.f, 0.f, 0.f);
    int k = 0;
#pragma unroll
    for (int di = -RR; di <= RR; di++) {
        int yy = y + di; bool vy = (unsigned)yy < HB;
#pragma unroll
        for (int dj = -RR; dj <= RR; dj++) {
            int xx = x + dj;
            if (vy && (unsigned)xx < WB) {
                float wv = wp[k];
                float4 f = *(const float4*)(fb + ((size_t)(yy * WB + xx)) * CI + 4 * l);
                acc.x += wv * f.x; acc.y += wv * f.y;
                acc.z += wv * f.z; acc.w += wv * f.w;
            }
            k++;
        }
    }
    *(float4*)(aln + ((size_t)n * HW + p) * CI + 4 * l) = acc;
}

// ---------------- ag3: 1x1 conv 32->1 + ReLU (NHWC input) --------------------
__global__ void k_ag3(const float* __restrict__ a2, const float* __restrict__ w,
                      const float* __restrict__ bias, float* __restrict__ a3) {
    int n = blockIdx.y;
    int p = blockIdx.x * 256 + threadIdx.x;
    if (p >= HW) return;
    const float* src = a2 + ((size_t)n * HW + p) * 32;
    float s = bias[0];
#pragma unroll
    for (int c = 0; c < 32; c += 4) {
        float4 f = *(const float4*)(src + c);
        s += w[c] * f.x + w[c + 1] * f.y + w[c + 2] * f.z + w[c + 3] * f.w;
    }
    a3[(size_t)n * HW + p] = fmaxf(s, 0.f);
}

// ---------------- final 2-way softmax blend ----------------------------------
__global__ void k_final(const float* __restrict__ a3, const float* __restrict__ alc,
                        const float* __restrict__ fc, float* __restrict__ out) {
    size_t idx = (size_t)blockIdx.x * 256 + threadIdx.x;
    if (idx >= (size_t)BQ * CI * HW) return;
    int p = (int)(idx % HW);
    int nc = (int)(idx / HW);
    int n = nc / CI;
    float as = a3[(size_t)n * HW + p];
    float ac = a3[(size_t)(n + BQ) * HW + p];
    float m = fmaxf(as, ac);
    float ea = __expf(as - m), eb = __expf(ac - m);
    float inv = 1.f / (ea + eb);
    out[idx] = (ea * inv) * alc[idx] + (eb * inv) * fc[idx];
}

// ---------------- launch ------------------------------------------------------
extern "C" void kernel_launch(void* const* d_in, const int* in_sizes, int n_in,
                              void* d_out, int out_size) {
    const float* fs    = (const float*)d_in[0];
    const float* fc    = (const float*)d_in[1];
    const float* ec1_w = (const float*)d_in[2];
    const float* ec1_b = (const float*)d_in[3];
    const float* ec2_w = (const float*)d_in[4];
    const float* ec2_b = (const float*)d_in[5];
    const float* ag1_w = (const float*)d_in[6];
    const float* ag1_b = (const float*)d_in[7];
    const float* ag2_w = (const float*)d_in[8];
    const float* ag2_b = (const float*)d_in[9];
    const float* ag3_w = (const float*)d_in[10];
    const float* ag3_b = (const float*)d_in[11];
    float* out = (float*)d_out;

    float *t1, *e2, *w81, *fsn, *aln, *alc, *a2, *a3;
    __nv_bfloat16 *t1b, *wte, *wta;
    cudaGetSymbolAddress((void**)&t1,  g_T1);
    cudaGetSymbolAddress((void**)&t1b, g_T1B);
    cudaGetSymbolAddress((void**)&e2,  g_E2);
    cudaGetSymbolAddress((void**)&w81, g_W81);
    cudaGetSymbolAddress((void**)&fsn, g_FSN);
    cudaGetSymbolAddress((void**)&aln, g_ALN);
    cudaGetSymbolAddress((void**)&alc, g_ALC);
    cudaGetSymbolAddress((void**)&a2,  g_A2);
    cudaGetSymbolAddress((void**)&a3,  g_A3);
    cudaGetSymbolAddress((void**)&wte, g_WTE);
    cudaGetSymbolAddress((void**)&wta, g_WTA);

    const int PBLK = (HW + 255) / 256;   // 157
    const int MBLK = (HW + 127) / 128;   // 313

    // weight prep (independent, cheap)
    k_wprep<<<(9 * 64 * 64 + 255) / 256, 256>>>(ec2_w, wte, 64);
    k_wprep<<<(9 * 32 * 64 + 255) / 256, 256>>>(ag2_w, wta, 32);

    // feature_select NCHW -> NHWC (for align gather)
    k_trans<<<dim3(HW / 32, CI / 32, BQ), dim3(32, 8)>>>(fs, fsn, CI, HW);

    // encoder
    k_conv1<CI><<<dim3(PBLK, NBT), 256>>>(fs, fc, ec1_w, ec1_b, t1);
    k_tobf16<<<dim3(HW / 32, 2, NBT), dim3(32, 8)>>>(t1, t1b);
    conv3_hmma<64><<<dim3(MBLK, NBT), 256>>>(t1b, wte, ec2_b, e2);

    // correlation + softmax
    k_corr<<<dim3(HW / 8, BQ), 256>>>(e2, w81);

    // weighted aggregation
    k_align<<<dim3(HW / 8, BQ), 256>>>(w81, fsn, aln);
    k_trans<<<dim3(CI / 32, HW / 32, BQ), dim3(32, 8)>>>(aln, alc, HW, CI);

    // gating head
    k_conv1<CI><<<dim3(PBLK, NBT), 256>>>(alc, fc, ag1_w, ag1_b, t1);
    k_tobf16<<<dim3(HW / 32, 2, NBT), dim3(32, 8)>>>(t1, t1b);
    conv3_hmma<32><<<dim3(MBLK, NBT), 256>>>(t1b, wta, ag2_b, a2);
    k_ag3<<<dim3(PBLK, NBT), 256>>>(a2, ag3_w, ag3_b, a3);

    // final blend
    size_t tot = (size_t)BQ * CI * HW;
    k_final<<<(unsigned)((tot + 255) / 256), 256>>>(a3, alc, fc, out);
}

// round 5
// speedup vs baseline: 1.2568x; 1.2568x over previous
#include <cuda_runtime.h>
#include <cuda_bf16.h>
#include <cstdint>

// Problem constants
#define HB 200
#define WB 200
#define HW 40000          // H*W
#define BQ 4              // batch
#define NBT 8             // 2*batch (cat)
#define CI 128            // input channels
#define CE 64             // embed channels
#define RR 4              // neighborhood radius
#define K81 81            // 9x9 offsets

typedef unsigned long long ull;

__device__ __forceinline__ uint32_t smem_u32(const void* p) {
    uint32_t a;
    asm("{ .reg .u64 t; cvta.to.shared.u64 t, %1; cvt.u32.u64 %0, t; }" : "=r"(a) : "l"(p));
    return a;
}

// warp-level bf16 MMA: D(16x8,f32) += A(16x16,bf16) * B(16x8,bf16)
__device__ __forceinline__ void mma16816(float* c, const uint32_t* a, uint32_t b0, uint32_t b1) {
    asm volatile(
        "mma.sync.aligned.m16n8k16.row.col.f32.bf16.bf16.f32 "
        "{%0,%1,%2,%3}, {%4,%5,%6,%7}, {%8,%9}, {%0,%1,%2,%3};"
        : "+f"(c[0]), "+f"(c[1]), "+f"(c[2]), "+f"(c[3])
        : "r"(a[0]), "r"(a[1]), "r"(a[2]), "r"(a[3]), "r"(b0), "r"(b1));
}
__device__ __forceinline__ void ldmatrix_x4(uint32_t* r, uint32_t addr) {
    asm volatile("ldmatrix.sync.aligned.m8n8.x4.shared.b16 {%0,%1,%2,%3}, [%4];"
                 : "=r"(r[0]), "=r"(r[1]), "=r"(r[2]), "=r"(r[3]) : "r"(addr));
}
__device__ __forceinline__ uint32_t bf16x2(float x, float y) {
    uint32_t r;
    asm("cvt.rn.satfinite.bf16x2.f32 %0, %1, %2;" : "=r"(r) : "f"(y), "f"(x));
    return r;
}

// ---------------- scratch (device globals) ------------
__device__ __nv_bfloat16 g_XB [(size_t)NBT * HW * CI];   // conv1 input, NHWC bf16
__device__ __nv_bfloat16 g_T1B[(size_t)NBT * HW * CE];   // conv1 out, NHWC bf16
__device__ __nv_bfloat16 g_E2B[(size_t)NBT * HW * CE];   // ec2 out, NHWC bf16
__device__ float g_W81[(size_t)BQ  * HW * K81];
__device__ float g_FSN[(size_t)BQ  * HW * CI];           // feature_select NHWC fp32
__device__ float g_ALN[(size_t)BQ  * HW * CI];           // align NHWC fp32
__device__ float g_ALC[(size_t)BQ  * CI * HW];           // align NCHW fp32
__device__ float g_A2 [(size_t)NBT * HW * 32];           // ag2 out, NHWC fp32
__device__ float g_A3 [(size_t)NBT * HW];
__device__ __nv_bfloat16 g_WTE[9 * 64 * 64];             // ec2 weights bf16 [tap][oc][ic]
__device__ __nv_bfloat16 g_WTA[9 * 32 * 64];             // ag2 weights bf16
__device__ __nv_bfloat16 g_W1E[64 * CI];                 // ec1 weights bf16 [oc][ic]
__device__ __nv_bfloat16 g_W1A[64 * CI];                 // ag1 weights bf16

// ---------------- generic 32x32 tiled transpose: [n][A][B] -> [n][B][A] ------
__global__ void k_trans(const float* __restrict__ src, float* __restrict__ dst,
                        int A, int B) {
    __shared__ float t[32][33];
    int n = blockIdx.z;
    size_t base = (size_t)n * A * B;
    int a0 = blockIdx.y * 32, b0 = blockIdx.x * 32;
    int tx = threadIdx.x, ty = threadIdx.y;
#pragma unroll
    for (int i = 0; i < 4; i++) {
        int a = a0 + ty + i * 8, b = b0 + tx;
        if (a < A && b < B) t[ty + i * 8][tx] = src[base + (size_t)a * B + b];
    }
    __syncthreads();
#pragma unroll
    for (int i = 0; i < 4; i++) {
        int b = b0 + ty + i * 8, a = a0 + tx;
        if (a < A && b < B) dst[base + (size_t)b * A + a] = t[tx][ty + i * 8];
    }
}

// ------- NCHW fp32 [4][128][HW] (fs|fc) -> NHWC bf16 [8][HW][128] ------------
__global__ void k_prep_xb(const float* __restrict__ fs, const float* __restrict__ fc,
                          __nv_bfloat16* __restrict__ dst) {
    __shared__ float t[32][33];
    int n = blockIdx.z, ct = blockIdx.y;   // ct: channel tile 0..3
    const float* s = ((n < BQ) ? fs : fc) + (size_t)(n & 3) * CI * HW;
    __nv_bfloat16* d = dst + (size_t)n * HW * CI;
    int b0 = blockIdx.x * 32;
    int tx = threadIdx.x, ty = threadIdx.y;
#pragma unroll
    for (int i = 0; i < 4; i++)
        t[ty + i * 8][tx] = s[(size_t)(ct * 32 + ty + i * 8) * HW + b0 + tx];
    __syncthreads();
#pragma unroll
    for (int i = 0; i < 4; i++)
        d[(size_t)(b0 + ty + i * 8) * CI + ct * 32 + tx] = __float2bfloat16(t[tx][ty + i * 8]);
}

// ------- align NHWC fp32 -> XB batches 0..3 bf16 (same layout) ---------------
__global__ void k_aln2bf16(const float* __restrict__ aln, __nv_bfloat16* __restrict__ xb) {
    size_t i = ((size_t)blockIdx.x * 256 + threadIdx.x) * 4;
    if (i >= (size_t)BQ * HW * CI) return;
    float4 v = *(const float4*)(aln + i);
    uint32_t lo = bf16x2(v.x, v.y), hi = bf16x2(v.z, v.w);
    *(uint2*)(xb + i) = make_uint2(lo, hi);
}

// ---------------- weight prep: [OC][64][3][3] fp32 -> [9][OC][64] bf16 --------
__global__ void k_wprep(const float* __restrict__ w, __nv_bfloat16* __restrict__ dst, int OC) {
    int i = blockIdx.x * 256 + threadIdx.x;
    int tot = 9 * OC * 64;
    if (i >= tot) return;
    int ic = i & 63;
    int rest = i >> 6;
    int oc = rest % OC;
    int tap = rest / OC;
    dst[((size_t)tap * OC + oc) * 64 + ic] = __float2bfloat16(w[((size_t)oc * 64 + ic) * 9 + tap]);
}
// ---------------- weight prep: [64][128] fp32 -> bf16 same layout -------------
__global__ void k_wprep1(const float* __restrict__ w, __nv_bfloat16* __restrict__ dst) {
    int i = blockIdx.x * 256 + threadIdx.x;
    if (i < 64 * CI) dst[i] = __float2bfloat16(w[i]);
}

// ---------------- 1x1 conv via bf16 mma.sync ----------------------------------
// CTA: 64 pixels (M) x 64 (N), K=128. 128 threads = 4 warps, warp owns 16 rows.
// Input NHWC bf16 [8][HW][128]; weights bf16 [64][128]; output NHWC bf16 + ReLU.
__global__ __launch_bounds__(128) void conv1_hmma(
    const __nv_bfloat16* __restrict__ xb,
    const __nv_bfloat16* __restrict__ wb,
    const float* __restrict__ bias,
    __nv_bfloat16* __restrict__ out)
{
    constexpr int LDA = 136;   // halves per row (128 + 8 pad)
    __shared__ __align__(16) __nv_bfloat16 As[64 * LDA];
    __shared__ __align__(16) __nv_bfloat16 Bs[64 * LDA];

    int tid = threadIdx.x;
    int wid = tid >> 5, l = tid & 31;
    int n = blockIdx.y;
    int p0 = blockIdx.x * 64;
    int m0 = wid * 16;

    // --- stage A: 64 rows x 128 halves; thread t: row=t>>1, half=t&1 (8 uint4)
    {
        int r = tid >> 1, h = tid & 1;
        int p = p0 + r;
        bool v = p < HW;
        const uint4* src = reinterpret_cast<const uint4*>(
            xb + ((size_t)n * HW + (v ? p : 0)) * CI + h * 64);
        uint4* dst = reinterpret_cast<uint4*>(As + r * LDA + h * 64);
        uint4 zz = make_uint4(0u, 0u, 0u, 0u);
#pragma unroll
        for (int c = 0; c < 8; c++) dst[c] = v ? src[c] : zz;
    }
    // --- stage B: 64 rows x 128 halves (uint4 copies)
    {
        const uint4* src = reinterpret_cast<const uint4*>(wb);
#pragma unroll
        for (int i = 0; i < 8; i++) {
            int e = tid + i * 128;            // uint4 index, 8 halves each
            int row = e >> 4, h8 = e & 15;    // 16 uint4 per row
            *reinterpret_cast<uint4*>(Bs + row * LDA + h8 * 8) = src[e];
        }
    }
    __syncthreads();

    uint32_t as_base = smem_u32(As);
    uint32_t bs_base = smem_u32(Bs);

    float acc[8][4];
#pragma unroll
    for (int t = 0; t < 8; t++)
#pragma unroll
        for (int i = 0; i < 4; i++) acc[t][i] = 0.f;

#pragma unroll
    for (int ks = 0; ks < 8; ks++) {
        uint32_t afrag[4];
        uint32_t aaddr = as_base + ((m0 + (l & 15)) * LDA + ((l >> 4) * 8 + ks * 16)) * 2;
        ldmatrix_x4(afrag, aaddr);
#pragma unroll
        for (int nt = 0; nt < 8; nt++) {
            uint32_t baddr = bs_base + ((nt * 8 + (l >> 2)) * LDA + ks * 16 + (l & 3) * 2) * 2;
            uint32_t bv0, bv1;
            asm volatile("ld.shared.b32 %0, [%1];" : "=r"(bv0) : "r"(baddr));
            asm volatile("ld.shared.b32 %0, [%1];" : "=r"(bv1) : "r"(baddr + 16));
            mma16816(acc[nt], afrag, bv0, bv1);
        }
    }

    // --- epilogue: bias + ReLU -> NHWC bf16
    int row_a = m0 + (l >> 2);
    int col0 = (l & 3) * 2;
#pragma unroll
    for (int half = 0; half < 2; half++) {
        int prow = p0 + row_a + half * 8;
        if (prow >= HW) continue;
        __nv_bfloat16* ob = out + ((size_t)n * HW + prow) * CE;
#pragma unroll
        for (int nt = 0; nt < 8; nt++) {
            int c = nt * 8 + col0;
            float vx = fmaxf(acc[nt][half * 2 + 0] + bias[c],     0.f);
            float vy = fmaxf(acc[nt][half * 2 + 1] + bias[c + 1], 0.f);
            *reinterpret_cast<uint32_t*>(ob + c) = bf16x2(vx, vy);
        }
    }
}

// ---------------- 3x3 conv via warp-level bf16 mma.sync -----------------------
// CTA: 128 pixels (M) x OC (N). K = 9 taps x 64 ic. A tile rebuilt per tap.
template <int OC, bool BF16OUT>
__global__ __launch_bounds__(256) void conv3_hmma(
    const __nv_bfloat16* __restrict__ inb,
    const __nv_bfloat16* __restrict__ wt,
    const float* __restrict__ bias,
    void* __restrict__ out_)
{
    constexpr int LDA = 72;
    constexpr int NT  = OC / 8;
    __shared__ __align__(16) __nv_bfloat16 As[128 * LDA];
    __shared__ __align__(16) __nv_bfloat16 Bs[OC * LDA];

    int tid = threadIdx.x;
    int wid = tid >> 5, l = tid & 31;
    int n = blockIdx.y;
    int p0 = blockIdx.x * 128;

    int ar = tid >> 1, ah = tid & 1;
    int ap = p0 + ar;
    bool apv = ap < HW;
    int ay = ap / WB, ax = ap - ay * WB;

    uint32_t as_base = smem_u32(As);
    uint32_t bs_base = smem_u32(Bs);

    float acc[NT][4];
#pragma unroll
    for (int t = 0; t < NT; t++)
#pragma unroll
        for (int i = 0; i < 4; i++) acc[t][i] = 0.f;

    int m0 = wid * 16;

    for (int tap = 0; tap < 9; tap++) {
        int dy = tap / 3 - 1, dx = tap % 3 - 1;
        __syncthreads();
        {
            bool v = apv && ((unsigned)(ay + dy) < HB) && ((unsigned)(ax + dx) < WB);
            const uint4* src = reinterpret_cast<const uint4*>(
                inb + ((size_t)n * HW + (ap + dy * WB + dx)) * CE + ah * 32);
            uint4* dst = reinterpret_cast<uint4*>(As + ar * LDA + ah * 32);
            uint4 zz = make_uint4(0u, 0u, 0u, 0u);
#pragma unroll
            for (int c = 0; c < 4; c++) dst[c] = v ? src[c] : zz;
        }
        if (tid < OC * 2) {
            int row = tid >> 1, h = tid & 1;
            const uint4* src = reinterpret_cast<const uint4*>(
                wt + ((size_t)tap * OC + row) * 64 + h * 32);
            uint4* dst = reinterpret_cast<uint4*>(Bs + row * LDA + h * 32);
#pragma unroll
            for (int c = 0; c < 4; c++) dst[c] = src[c];
        }
        __syncthreads();

#pragma unroll
        for (int ks = 0; ks < 4; ks++) {
            uint32_t afrag[4];
            uint32_t aaddr = as_base + ((m0 + (l & 15)) * LDA + ((l >> 4) * 8 + ks * 16)) * 2;
            ldmatrix_x4(afrag, aaddr);
#pragma unroll
            for (int nt = 0; nt < NT; nt++) {
                uint32_t baddr = bs_base + ((nt * 8 + (l >> 2)) * LDA + ks * 16 + (l & 3) * 2) * 2;
                uint32_t bv0, bv1;
                asm volatile("ld.shared.b32 %0, [%1];" : "=r"(bv0) : "r"(baddr));
                asm volatile("ld.shared.b32 %0, [%1];" : "=r"(bv1) : "r"(baddr + 16));
                mma16816(acc[nt], afrag, bv0, bv1);
            }
        }
    }

    int row_a = m0 + (l >> 2);
    int col0 = (l & 3) * 2;
#pragma unroll
    for (int half = 0; half < 2; half++) {
        int prow = p0 + row_a + half * 8;
        if (prow >= HW) continue;
        if (BF16OUT) {
            __nv_bfloat16* ob = (__nv_bfloat16*)out_ + ((size_t)n * HW + prow) * OC;
#pragma unroll
            for (int nt = 0; nt < NT; nt++) {
                int c = nt * 8 + col0;
                float vx = fmaxf(acc[nt][half * 2 + 0] + bias[c],     0.f);
                float vy = fmaxf(acc[nt][half * 2 + 1] + bias[c + 1], 0.f);
                *reinterpret_cast<uint32_t*>(ob + c) = bf16x2(vx, vy);
            }
        } else {
            float* ob = (float*)out_ + ((size_t)n * HW + prow) * OC;
#pragma unroll
            for (int nt = 0; nt < NT; nt++) {
                int c = nt * 8 + col0;
                float2 v;
                v.x = fmaxf(acc[nt][half * 2 + 0] + bias[c],     0.f);
                v.y = fmaxf(acc[nt][half * 2 + 1] + bias[c + 1], 0.f);
                *reinterpret_cast<float2*>(ob + c) = v;
            }
        }
    }
}

// ---------------- correlation (81 offsets) + softmax, fused (bf16 in) --------
__global__ __launch_bounds__(256) void k_corr(
    const __nv_bfloat16* __restrict__ e2b, float* __restrict__ w81)
{
    int n = blockIdx.y;
    int warp = threadIdx.x >> 5, l = threadIdx.x & 31;
    int p = blockIdx.x * 8 + warp;
    if (p >= HW) return;
    int y = p / WB, x = p - y * WB;

    const __nv_bfloat16* esel = e2b + ((size_t)n * HW + p) * CE;
    const __nv_bfloat16* ecur = e2b + (size_t)(n + BQ) * HW * CE;
    float2 es = __bfloat1622float2(*(const __nv_bfloat162*)(esel + 2 * l));

    float c0 = 0.f, c1 = 0.f, c2 = -3.0e38f;
    int k = 0;
#pragma unroll
    for (int di = -RR; di <= RR; di++) {
        int yy = y + di; bool vy = (unsigned)yy < HB;
#pragma unroll
        for (int dj = -RR; dj <= RR; dj++) {
            int xx = x + dj;
            float2 ec = make_float2(0.f, 0.f);
            if (vy && (unsigned)xx < WB)
                ec = __bfloat1622float2(
                    *(const __nv_bfloat162*)(ecur + ((size_t)(yy * WB + xx)) * CE + 2 * l));
            float ps = es.x * ec.x + es.y * ec.y;
#pragma unroll
            for (int s = 16; s > 0; s >>= 1) ps += __shfl_xor_sync(0xffffffffu, ps, s);
            if (k < 32)      { if (l == k)      c0 = ps; }
            else if (k < 64) { if (l == k - 32) c1 = ps; }
            else             { if (l == k - 64) c2 = ps; }
            k++;
        }
    }
    float mx = fmaxf(c0, fmaxf(c1, c2));
#pragma unroll
    for (int s = 16; s > 0; s >>= 1) mx = fmaxf(mx, __shfl_xor_sync(0xffffffffu, mx, s));
    float e0 = __expf(c0 - mx);
    float e1 = __expf(c1 - mx);
    float e2v = (l < 17) ? __expf(c2 - mx) : 0.f;
    float sm = e0 + e1 + e2v;
#pragma unroll
    for (int s = 16; s > 0; s >>= 1) sm += __shfl_xor_sync(0xffffffffu, sm, s);
    float inv = 1.f / sm;
    size_t base = ((size_t)n * HW + p) * K81;
    w81[base + l]      = e0 * inv;
    w81[base + 32 + l] = e1 * inv;
    if (l < 17) w81[base + 64 + l] = e2v * inv;
}

// ---------------- weighted neighborhood aggregation --------------------------
__global__ __launch_bounds__(256) void k_align(
    const float* __restrict__ w81, const float* __restrict__ fsn,
    float* __restrict__ aln)
{
    int n = blockIdx.y;
    int warp = threadIdx.x >> 5, l = threadIdx.x & 31;
    int p = blockIdx.x * 8 + warp;
    if (p >= HW) return;
    int y = p / WB, x = p - y * WB;

    const float* wp = w81 + ((size_t)n * HW + p) * K81;
    const float* fb = fsn + (size_t)n * HW * CI;
    float4 acc = make_float4(0.f, 0.f, 0.f, 0.f);
    int k = 0;
#pragma unroll
    for (int di = -RR; di <= RR; di++) {
        int yy = y + di; bool vy = (unsigned)yy < HB;
#pragma unroll
        for (int dj = -RR; dj <= RR; dj++) {
            int xx = x + dj;
            if (vy && (unsigned)xx < WB) {
                float wv = wp[k];
                float4 f = *(const float4*)(fb + ((size_t)(yy * WB + xx)) * CI + 4 * l);
                acc.x += wv * f.x; acc.y += wv * f.y;
                acc.z += wv * f.z; acc.w += wv * f.w;
            }
            k++;
        }
    }
    *(float4*)(aln + ((size_t)n * HW + p) * CI + 4 * l) = acc;
}

// ---------------- ag3: 1x1 conv 32->1 + ReLU (NHWC input) --------------------
__global__ void k_ag3(const float* __restrict__ a2, const float* __restrict__ w,
                      const float* __restrict__ bias, float* __restrict__ a3) {
    int n = blockIdx.y;
    int p = blockIdx.x * 256 + threadIdx.x;
    if (p >= HW) return;
    const float* src = a2 + ((size_t)n * HW + p) * 32;
    float s = bias[0];
#pragma unroll
    for (int c = 0; c < 32; c += 4) {
        float4 f = *(const float4*)(src + c);
        s += w[c] * f.x + w[c + 1] * f.y + w[c + 2] * f.z + w[c + 3] * f.w;
    }
    a3[(size_t)n * HW + p] = fmaxf(s, 0.f);
}

// ---------------- final 2-way softmax blend ----------------------------------
__global__ void k_final(const float* __restrict__ a3, const float* __restrict__ alc,
                        const float* __restrict__ fc, float* __restrict__ out) {
    size_t idx = (size_t)blockIdx.x * 256 + threadIdx.x;
    if (idx >= (size_t)BQ * CI * HW) return;
    int p = (int)(idx % HW);
    int nc = (int)(idx / HW);
    int n = nc / CI;
    float as = a3[(size_t)n * HW + p];
    float ac = a3[(size_t)(n + BQ) * HW + p];
    float m = fmaxf(as, ac);
    float ea = __expf(as - m), eb = __expf(ac - m);
    float inv = 1.f / (ea + eb);
    out[idx] = (ea * inv) * alc[idx] + (eb * inv) * fc[idx];
}

// ---------------- launch ------------------------------------------------------
extern "C" void kernel_launch(void* const* d_in, const int* in_sizes, int n_in,
                              void* d_out, int out_size) {
    const float* fs    = (const float*)d_in[0];
    const float* fc    = (const float*)d_in[1];
    const float* ec1_w = (const float*)d_in[2];
    const float* ec1_b = (const float*)d_in[3];
    const float* ec2_w = (const float*)d_in[4];
    const float* ec2_b = (const float*)d_in[5];
    const float* ag1_w = (const float*)d_in[6];
    const float* ag1_b = (const float*)d_in[7];
    const float* ag2_w = (const float*)d_in[8];
    const float* ag2_b = (const float*)d_in[9];
    const float* ag3_w = (const float*)d_in[10];
    const float* ag3_b = (const float*)d_in[11];
    float* out = (float*)d_out;

    float *w81, *fsn, *aln, *alc, *a2, *a3;
    __nv_bfloat16 *xb, *t1b, *e2b, *wte, *wta, *w1e, *w1a;
    cudaGetSymbolAddress((void**)&xb,  g_XB);
    cudaGetSymbolAddress((void**)&t1b, g_T1B);
    cudaGetSymbolAddress((void**)&e2b, g_E2B);
    cudaGetSymbolAddress((void**)&w81, g_W81);
    cudaGetSymbolAddress((void**)&fsn, g_FSN);
    cudaGetSymbolAddress((void**)&aln, g_ALN);
    cudaGetSymbolAddress((void**)&alc, g_ALC);
    cudaGetSymbolAddress((void**)&a2,  g_A2);
    cudaGetSymbolAddress((void**)&a3,  g_A3);
    cudaGetSymbolAddress((void**)&wte, g_WTE);
    cudaGetSymbolAddress((void**)&wta, g_WTA);
    cudaGetSymbolAddress((void**)&w1e, g_W1E);
    cudaGetSymbolAddress((void**)&w1a, g_W1A);

    const int PBLK  = (HW + 255) / 256;   // 157
    const int MBLK  = (HW + 127) / 128;   // 313
    const int M64   = (HW + 63) / 64;     // 625

    // weight prep (cheap, independent)
    k_wprep<<<(9 * 64 * 64 + 255) / 256, 256>>>(ec2_w, wte, 64);
    k_wprep<<<(9 * 32 * 64 + 255) / 256, 256>>>(ag2_w, wta, 32);
    k_wprep1<<<(64 * CI + 255) / 256, 256>>>(ec1_w, w1e);
    k_wprep1<<<(64 * CI + 255) / 256, 256>>>(ag1_w, w1a);

    // input prep
    k_trans<<<dim3(HW / 32, CI / 32, BQ), dim3(32, 8)>>>(fs, fsn, CI, HW);
    k_prep_xb<<<dim3(HW / 32, 4, NBT), dim3(32, 8)>>>(fs, fc, xb);

    // encoder
    conv1_hmma<<<dim3(M64, NBT), 128>>>(xb, w1e, ec1_b, t1b);
    conv3_hmma<64, true><<<dim3(MBLK, NBT), 256>>>(t1b, wte, ec2_b, e2b);

    // correlation + softmax
    k_corr<<<dim3(HW / 8, BQ), 256>>>(e2b, w81);

    // weighted aggregation
    k_align<<<dim3(HW / 8, BQ), 256>>>(w81, fsn, aln);
    k_trans<<<dim3(CI / 32, HW / 32, BQ), dim3(32, 8)>>>(aln, alc, HW, CI);
    k_aln2bf16<<<(unsigned)(((size_t)BQ * HW * CI / 4 + 255) / 256), 256>>>(aln, xb);

    // gating head
    conv1_hmma<<<dim3(M64, NBT), 128>>>(xb, w1a, ag1_b, t1b);
    conv3_hmma<32, false><<<dim3(MBLK, NBT), 256>>>(t1b, wta, ag2_b, a2);
    k_ag3<<<dim3(PBLK, NBT), 256>>>(a2, ag3_w, ag3_b, a3);

    // final blend
    size_t tot = (size_t)BQ * CI * HW;
    k_final<<<(unsigned)((tot + 255) / 256), 256>>>(a3, alc, fc, out);
}

// round 7
// speedup vs baseline: 1.3770x; 1.0956x over previous
#include <cuda_runtime.h>
#include <cuda_bf16.h>
#include <cstdint>

// Problem constants
#define HB 200
#define WB 200
#define HW 40000          // H*W
#define BQ 4              // batch
#define NBT 8             // 2*batch (cat)
#define CI 128            // input channels
#define CE 64             // embed channels
#define RR 4              // neighborhood radius
#define K81 81            // 9x9 offsets

typedef unsigned long long ull;

__device__ __forceinline__ uint32_t smem_u32(const void* p) {
    uint32_t a;
    asm("{ .reg .u64 t; cvta.to.shared.u64 t, %1; cvt.u32.u64 %0, t; }" : "=r"(a) : "l"(p));
    return a;
}

// warp-level bf16 MMA: D(16x8,f32) += A(16x16,bf16) * B(16x8,bf16)
__device__ __forceinline__ void mma16816(float* c, const uint32_t* a, uint32_t b0, uint32_t b1) {
    asm volatile(
        "mma.sync.aligned.m16n8k16.row.col.f32.bf16.bf16.f32 "
        "{%0,%1,%2,%3}, {%4,%5,%6,%7}, {%8,%9}, {%0,%1,%2,%3};"
        : "+f"(c[0]), "+f"(c[1]), "+f"(c[2]), "+f"(c[3])
        : "r"(a[0]), "r"(a[1]), "r"(a[2]), "r"(a[3]), "r"(b0), "r"(b1));
}
__device__ __forceinline__ void ldmatrix_x4(uint32_t* r, uint32_t addr) {
    asm volatile("ldmatrix.sync.aligned.m8n8.x4.shared.b16 {%0,%1,%2,%3}, [%4];"
                 : "=r"(r[0]), "=r"(r[1]), "=r"(r[2]), "=r"(r[3]) : "r"(addr));
}
__device__ __forceinline__ uint32_t bf16x2(float x, float y) {
    uint32_t r;
    asm("cvt.rn.satfinite.bf16x2.f32 %0, %1, %2;" : "=r"(r) : "f"(y), "f"(x));
    return r;
}

// ---------------- scratch (device globals) ------------
__device__ __nv_bfloat16 g_XB [(size_t)NBT * HW * CI];   // conv1 input, NHWC bf16
__device__ __nv_bfloat16 g_T1B[(size_t)NBT * HW * CE];   // conv1 out, NHWC bf16
__device__ __nv_bfloat16 g_E2B[(size_t)NBT * HW * CE];   // ec2 out, NHWC bf16
__device__ float g_W81[(size_t)BQ  * HW * K81];
__device__ float g_FSN[(size_t)BQ  * HW * CI];           // feature_select NHWC fp32
__device__ float g_ALN[(size_t)BQ  * HW * CI];           // align NHWC fp32
__device__ float g_ALC[(size_t)BQ  * CI * HW];           // align NCHW fp32
__device__ float g_A2 [(size_t)NBT * HW * 32];           // ag2 out, NHWC fp32
__device__ float g_A3 [(size_t)NBT * HW];
__device__ __nv_bfloat16 g_WTE[9 * 64 * 64];             // ec2 weights bf16 [tap][oc][ic]
__device__ __nv_bfloat16 g_WTA[9 * 32 * 64];             // ag2 weights bf16
__device__ __nv_bfloat16 g_W1E[64 * CI];                 // ec1 weights bf16 [oc][ic]
__device__ __nv_bfloat16 g_W1A[64 * CI];                 // ag1 weights bf16

// ---------------- generic 32x32 tiled transpose: [n][A][B] -> [n][B][A] ------
__global__ void k_trans(const float* __restrict__ src, float* __restrict__ dst,
                        int A, int B) {
    __shared__ float t[32][33];
    int n = blockIdx.z;
    size_t base = (size_t)n * A * B;
    int a0 = blockIdx.y * 32, b0 = blockIdx.x * 32;
    int tx = threadIdx.x, ty = threadIdx.y;
#pragma unroll
    for (int i = 0; i < 4; i++) {
        int a = a0 + ty + i * 8, b = b0 + tx;
        if (a < A && b < B) t[ty + i * 8][tx] = src[base + (size_t)a * B + b];
    }
    __syncthreads();
#pragma unroll
    for (int i = 0; i < 4; i++) {
        int b = b0 + ty + i * 8, a = a0 + tx;
        if (a < A && b < B) dst[base + (size_t)b * A + a] = t[tx][ty + i * 8];
    }
}

// ------- NCHW fp32 [4][128][HW] (fs|fc) -> NHWC bf16 [8][HW][128] ------------
__global__ void k_prep_xb(const float* __restrict__ fs, const float* __restrict__ fc,
                          __nv_bfloat16* __restrict__ dst) {
    __shared__ float t[32][33];
    int n = blockIdx.z, ct = blockIdx.y;   // ct: channel tile 0..3
    const float* s = ((n < BQ) ? fs : fc) + (size_t)(n & 3) * CI * HW;
    __nv_bfloat16* d = dst + (size_t)n * HW * CI;
    int b0 = blockIdx.x * 32;
    int tx = threadIdx.x, ty = threadIdx.y;
#pragma unroll
    for (int i = 0; i < 4; i++)
        t[ty + i * 8][tx] = s[(size_t)(ct * 32 + ty + i * 8) * HW + b0 + tx];
    __syncthreads();
#pragma unroll
    for (int i = 0; i < 4; i++)
        d[(size_t)(b0 + ty + i * 8) * CI + ct * 32 + tx] = __float2bfloat16(t[tx][ty + i * 8]);
}

// ------- align NHWC fp32 -> XB batches 0..3 bf16 (same layout) ---------------
__global__ void k_aln2bf16(const float* __restrict__ aln, __nv_bfloat16* __restrict__ xb) {
    size_t i = ((size_t)blockIdx.x * 256 + threadIdx.x) * 4;
    if (i >= (size_t)BQ * HW * CI) return;
    float4 v = *(const float4*)(aln + i);
    uint32_t lo = bf16x2(v.x, v.y), hi = bf16x2(v.z, v.w);
    *(uint2*)(xb + i) = make_uint2(lo, hi);
}

// ---------------- weight prep: [OC][64][3][3] fp32 -> [9][OC][64] bf16 --------
__global__ void k_wprep(const float* __restrict__ w, __nv_bfloat16* __restrict__ dst, int OC) {
    int i = blockIdx.x * 256 + threadIdx.x;
    int tot = 9 * OC * 64;
    if (i >= tot) return;
    int ic = i & 63;
    int rest = i >> 6;
    int oc = rest % OC;
    int tap = rest / OC;
    dst[((size_t)tap * OC + oc) * 64 + ic] = __float2bfloat16(w[((size_t)oc * 64 + ic) * 9 + tap]);
}
// ---------------- weight prep: [64][128] fp32 -> bf16 same layout -------------
__global__ void k_wprep1(const float* __restrict__ w, __nv_bfloat16* __restrict__ dst) {
    int i = blockIdx.x * 256 + threadIdx.x;
    if (i < 64 * CI) dst[i] = __float2bfloat16(w[i]);
}

// ---------------- 1x1 conv via bf16 mma.sync ----------------------------------
// CTA: 64 pixels (M) x 64 (N), K=128. 128 threads = 4 warps, warp owns 16 rows.
__global__ __launch_bounds__(128) void conv1_hmma(
    const __nv_bfloat16* __restrict__ xb,
    const __nv_bfloat16* __restrict__ wb,
    const float* __restrict__ bias,
    __nv_bfloat16* __restrict__ out)
{
    constexpr int LDA = 136;
    __shared__ __align__(16) __nv_bfloat16 As[64 * LDA];
    __shared__ __align__(16) __nv_bfloat16 Bs[64 * LDA];

    int tid = threadIdx.x;
    int wid = tid >> 5, l = tid & 31;
    int n = blockIdx.y;
    int p0 = blockIdx.x * 64;
    int m0 = wid * 16;

    {
        int r = tid >> 1, h = tid & 1;
        int p = p0 + r;
        bool v = p < HW;
        const uint4* src = reinterpret_cast<const uint4*>(
            xb + ((size_t)n * HW + (v ? p : 0)) * CI + h * 64);
        uint4* dst = reinterpret_cast<uint4*>(As + r * LDA + h * 64);
        uint4 zz = make_uint4(0u, 0u, 0u, 0u);
#pragma unroll
        for (int c = 0; c < 8; c++) dst[c] = v ? src[c] : zz;
    }
    {
        const uint4* src = reinterpret_cast<const uint4*>(wb);
#pragma unroll
        for (int i = 0; i < 8; i++) {
            int e = tid + i * 128;
            int row = e >> 4, h8 = e & 15;
            *reinterpret_cast<uint4*>(Bs + row * LDA + h8 * 8) = src[e];
        }
    }
    __syncthreads();

    uint32_t as_base = smem_u32(As);
    uint32_t bs_base = smem_u32(Bs);

    float acc[8][4];
#pragma unroll
    for (int t = 0; t < 8; t++)
#pragma unroll
        for (int i = 0; i < 4; i++) acc[t][i] = 0.f;

#pragma unroll
    for (int ks = 0; ks < 8; ks++) {
        uint32_t afrag[4];
        uint32_t aaddr = as_base + ((m0 + (l & 15)) * LDA + ((l >> 4) * 8 + ks * 16)) * 2;
        ldmatrix_x4(afrag, aaddr);
#pragma unroll
        for (int nt = 0; nt < 8; nt++) {
            uint32_t baddr = bs_base + ((nt * 8 + (l >> 2)) * LDA + ks * 16 + (l & 3) * 2) * 2;
            uint32_t bv0, bv1;
            asm volatile("ld.shared.b32 %0, [%1];" : "=r"(bv0) : "r"(baddr));
            asm volatile("ld.shared.b32 %0, [%1];" : "=r"(bv1) : "r"(baddr + 16));
            mma16816(acc[nt], afrag, bv0, bv1);
        }
    }

    int row_a = m0 + (l >> 2);
    int col0 = (l & 3) * 2;
#pragma unroll
    for (int half = 0; half < 2; half++) {
        int prow = p0 + row_a + half * 8;
        if (prow >= HW) continue;
        __nv_bfloat16* ob = out + ((size_t)n * HW + prow) * CE;
#pragma unroll
        for (int nt = 0; nt < 8; nt++) {
            int c = nt * 8 + col0;
            float vx = fmaxf(acc[nt][half * 2 + 0] + bias[c],     0.f);
            float vy = fmaxf(acc[nt][half * 2 + 1] + bias[c + 1], 0.f);
            *reinterpret_cast<uint32_t*>(ob + c) = bf16x2(vx, vy);
        }
    }
}

// ---------------- 3x3 conv via warp-level bf16 mma.sync -----------------------
template <int OC, bool BF16OUT>
__global__ __launch_bounds__(256) void conv3_hmma(
    const __nv_bfloat16* __restrict__ inb,
    const __nv_bfloat16* __restrict__ wt,
    const float* __restrict__ bias,
    void* __restrict__ out_)
{
    constexpr int LDA = 72;
    constexpr int NT  = OC / 8;
    __shared__ __align__(16) __nv_bfloat16 As[128 * LDA];
    __shared__ __align__(16) __nv_bfloat16 Bs[OC * LDA];

    int tid = threadIdx.x;
    int wid = tid >> 5, l = tid & 31;
    int n = blockIdx.y;
    int p0 = blockIdx.x * 128;

    int ar = tid >> 1, ah = tid & 1;
    int ap = p0 + ar;
    bool apv = ap < HW;
    int ay = ap / WB, ax = ap - ay * WB;

    uint32_t as_base = smem_u32(As);
    uint32_t bs_base = smem_u32(Bs);

    float acc[NT][4];
#pragma unroll
    for (int t = 0; t < NT; t++)
#pragma unroll
        for (int i = 0; i < 4; i++) acc[t][i] = 0.f;

    int m0 = wid * 16;

    for (int tap = 0; tap < 9; tap++) {
        int dy = tap / 3 - 1, dx = tap % 3 - 1;
        __syncthreads();
        {
            bool v = apv && ((unsigned)(ay + dy) < HB) && ((unsigned)(ax + dx) < WB);
            const uint4* src = reinterpret_cast<const uint4*>(
                inb + ((size_t)n * HW + (ap + dy * WB + dx)) * CE + ah * 32);
            uint4* dst = reinterpret_cast<uint4*>(As + ar * LDA + ah * 32);
            uint4 zz = make_uint4(0u, 0u, 0u, 0u);
#pragma unroll
            for (int c = 0; c < 4; c++) dst[c] = v ? src[c] : zz;
        }
        if (tid < OC * 2) {
            int row = tid >> 1, h = tid & 1;
            const uint4* src = reinterpret_cast<const uint4*>(
                wt + ((size_t)tap * OC + row) * 64 + h * 32);
            uint4* dst = reinterpret_cast<uint4*>(Bs + row * LDA + h * 32);
#pragma unroll
            for (int c = 0; c < 4; c++) dst[c] = src[c];
        }
        __syncthreads();

#pragma unroll
        for (int ks = 0; ks < 4; ks++) {
            uint32_t afrag[4];
            uint32_t aaddr = as_base + ((m0 + (l & 15)) * LDA + ((l >> 4) * 8 + ks * 16)) * 2;
            ldmatrix_x4(afrag, aaddr);
#pragma unroll
            for (int nt = 0; nt < NT; nt++) {
                uint32_t baddr = bs_base + ((nt * 8 + (l >> 2)) * LDA + ks * 16 + (l & 3) * 2) * 2;
                uint32_t bv0, bv1;
                asm volatile("ld.shared.b32 %0, [%1];" : "=r"(bv0) : "r"(baddr));
                asm volatile("ld.shared.b32 %0, [%1];" : "=r"(bv1) : "r"(baddr + 16));
                mma16816(acc[nt], afrag, bv0, bv1);
            }
        }
    }

    int row_a = m0 + (l >> 2);
    int col0 = (l & 3) * 2;
#pragma unroll
    for (int half = 0; half < 2; half++) {
        int prow = p0 + row_a + half * 8;
        if (prow >= HW) continue;
        if (BF16OUT) {
            __nv_bfloat16* ob = (__nv_bfloat16*)out_ + ((size_t)n * HW + prow) * OC;
#pragma unroll
            for (int nt = 0; nt < NT; nt++) {
                int c = nt * 8 + col0;
                float vx = fmaxf(acc[nt][half * 2 + 0] + bias[c],     0.f);
                float vy = fmaxf(acc[nt][half * 2 + 1] + bias[c + 1], 0.f);
                *reinterpret_cast<uint32_t*>(ob + c) = bf16x2(vx, vy);
            }
        } else {
            float* ob = (float*)out_ + ((size_t)n * HW + prow) * OC;
#pragma unroll
            for (int nt = 0; nt < NT; nt++) {
                int c = nt * 8 + col0;
                float2 v;
                v.x = fmaxf(acc[nt][half * 2 + 0] + bias[c],     0.f);
                v.y = fmaxf(acc[nt][half * 2 + 1] + bias[c + 1], 0.f);
                *reinterpret_cast<float2*>(ob + c) = v;
            }
        }
    }
}

// ---------------- correlation + softmax, offset-parallel lanes ----------------
// Warp per pixel. Lanes = 8 offsets (l&7) x 4 channel-groups (l>>3, 16ch each).
// 11 rounds of 8 offsets; dot reduced over 4 lanes with 2 shuffles; logits to
// per-warp SMEM; warp softmax at the end.
__global__ __launch_bounds__(256) void k_corr(
    const __nv_bfloat16* __restrict__ e2b, float* __restrict__ w81)
{
    __shared__ float logits_s[8][88];   // padded beyond 81
    int n = blockIdx.y;
    int warp = threadIdx.x >> 5, l = threadIdx.x & 31;
    int p = blockIdx.x * 8 + warp;
    int y = p / WB, x = p - y * WB;
    int og = l & 7, cg = l >> 3;

    // load esel 16 channels -> fp32 regs
    float es[16];
    {
        const __nv_bfloat162* esel = reinterpret_cast<const __nv_bfloat162*>(
            e2b + ((size_t)n * HW + p) * CE + cg * 16);
#pragma unroll
        for (int i = 0; i < 8; i++) {
            float2 f = __bfloat1622float2(esel[i]);
            es[2 * i] = f.x; es[2 * i + 1] = f.y;
        }
    }
    const __nv_bfloat16* ecur = e2b + (size_t)(n + BQ) * HW * CE;

#pragma unroll
    for (int r = 0; r < 11; r++) {
        int k = r * 8 + og;
        int di = k / 9 - RR, dj = k % 9 - RR;
        int yy = y + di, xx = x + dj;
        bool v = (k < K81) && ((unsigned)yy < HB) && ((unsigned)xx < WB);
        float dot = 0.f;
        if (v) {
            const __nv_bfloat162* ec = reinterpret_cast<const __nv_bfloat162*>(
                ecur + ((size_t)(yy * WB + xx)) * CE + cg * 16);
#pragma unroll
            for (int i = 0; i < 8; i++) {
                float2 f = __bfloat1622float2(ec[i]);
                dot = fmaf(es[2 * i], f.x, dot);
                dot = fmaf(es[2 * i + 1], f.y, dot);
            }
        }
        dot += __shfl_xor_sync(0xffffffffu, dot, 8);
        dot += __shfl_xor_sync(0xffffffffu, dot, 16);
        if (cg == 0 && k < K81) logits_s[warp][k] = dot;
    }
    __syncwarp();

    float c0 = logits_s[warp][l];
    float c1 = logits_s[warp][32 + l];
    float c2 = (l < 17) ? logits_s[warp][64 + l] : -3.0e38f;
    float mx = fmaxf(c0, fmaxf(c1, c2));
#pragma unroll
    for (int s = 16; s > 0; s >>= 1) mx = fmaxf(mx, __shfl_xor_sync(0xffffffffu, mx, s));
    float e0 = __expf(c0 - mx);
    float e1 = __expf(c1 - mx);
    float e2v = (l < 17) ? __expf(c2 - mx) : 0.f;
    float sm = e0 + e1 + e2v;
#pragma unroll
    for (int s = 16; s > 0; s >>= 1) sm += __shfl_xor_sync(0xffffffffu, sm, s);
    float inv = 1.f / sm;
    size_t base = ((size_t)n * HW + p) * K81;
    w81[base + l]      = e0 * inv;
    w81[base + 32 + l] = e1 * inv;
    if (l < 17) w81[base + 64 + l] = e2v * inv;
}

// ---------------- weighted aggregation, warp per 4 consecutive x-pixels ------
// Lane = channel-quad (32 x float4 = 128 ch). Per di-row: load 12-quad window,
// reuse each feature quad for up to 4 outputs (dj taps).
__global__ __launch_bounds__(256) void k_align(
    const float* __restrict__ w81, const float* __restrict__ fsn,
    float* __restrict__ aln)
{
    int n = blockIdx.y;
    int warp = threadIdx.x >> 5, l = threadIdx.x & 31;
    int pg = blockIdx.x * 8 + warp;          // pixel-group id
    int p0 = pg * 4;                          // 4 | 200 -> never crosses rows
    if (p0 >= HW) return;
    int y = p0 / WB, x0 = p0 - y * WB;

    const float* wp = w81 + ((size_t)n * HW + p0) * K81;
    const float* fb = fsn + (size_t)n * HW * CI;

    float4 acc[4];
#pragma unroll
    for (int m = 0; m < 4; m++) acc[m] = make_float4(0.f, 0.f, 0.f, 0.f);

    for (int di = -RR; di <= RR; di++) {
        int yy = y + di;
        if ((unsigned)yy >= HB) continue;    // uniform across warp
        float4 fq[12];
#pragma unroll
        for (int j = 0; j < 12; j++) {
            int xx = x0 - RR + j;
            fq[j] = ((unsigned)xx < WB)
                ? *(const float4*)(fb + ((size_t)(yy * WB + xx)) * CI + 4 * l)
                : make_float4(0.f, 0.f, 0.f, 0.f);
        }
        int kbase = (di + RR) * 9;
#pragma unroll
        for (int m = 0; m < 4; m++) {
#pragma unroll
            for (int dj = 0; dj < 9; dj++) {
                float wv = wp[m * K81 + kbase + dj];
                float4 f = fq[m + dj];
                acc[m].x += wv * f.x; acc[m].y += wv * f.y;
                acc[m].z += wv * f.z; acc[m].w += wv * f.w;
            }
        }
    }
#pragma unroll
    for (int m = 0; m < 4; m++)
        *(float4*)(aln + ((size_t)n * HW + p0 + m) * CI + 4 * l) = acc[m];
}

// ---------------- ag3: 1x1 conv 32->1 + ReLU (NHWC input) --------------------
__global__ void k_ag3(const float* __restrict__ a2, const float* __restrict__ w,
                      const float* __restrict__ bias, float* __restrict__ a3) {
    int n = blockIdx.y;
    int p = blockIdx.x * 256 + threadIdx.x;
    if (p >= HW) return;
    const float* src = a2 + ((size_t)n * HW + p) * 32;
    float s = bias[0];
#pragma unroll
    for (int c = 0; c < 32; c += 4) {
        float4 f = *(const float4*)(src + c);
        s += w[c] * f.x + w[c + 1] * f.y + w[c + 2] * f.z + w[c + 3] * f.w;
    }
    a3[(size_t)n * HW + p] = fmaxf(s, 0.f);
}

// ---------------- final 2-way softmax blend ----------------------------------
__global__ void k_final(const float* __restrict__ a3, const float* __restrict__ alc,
                        const float* __restrict__ fc, float* __restrict__ out) {
    size_t idx = (size_t)blockIdx.x * 256 + threadIdx.x;
    if (idx >= (size_t)BQ * CI * HW) return;
    int p = (int)(idx % HW);
    int nc = (int)(idx / HW);
    int n = nc / CI;
    float as = a3[(size_t)n * HW + p];
    float ac = a3[(size_t)(n + BQ) * HW + p];
    float m = fmaxf(as, ac);
    float ea = __expf(as - m), eb = __expf(ac - m);
    float inv = 1.f / (ea + eb);
    out[idx] = (ea * inv) * alc[idx] + (eb * inv) * fc[idx];
}

// ---------------- launch ------------------------------------------------------
extern "C" void kernel_launch(void* const* d_in, const int* in_sizes, int n_in,
                              void* d_out, int out_size) {
    const float* fs    = (const float*)d_in[0];
    const float* fc    = (const float*)d_in[1];
    const float* ec1_w = (const float*)d_in[2];
    const float* ec1_b = (const float*)d_in[3];
    const float* ec2_w = (const float*)d_in[4];
    const float* ec2_b = (const float*)d_in[5];
    const float* ag1_w = (const float*)d_in[6];
    const float* ag1_b = (const float*)d_in[7];
    const float* ag2_w = (const float*)d_in[8];
    const float* ag2_b = (const float*)d_in[9];
    const float* ag3_w = (const float*)d_in[10];
    const float* ag3_b = (const float*)d_in[11];
    float* out = (float*)d_out;

    float *w81, *fsn, *aln, *alc, *a2, *a3;
    __nv_bfloat16 *xb, *t1b, *e2b, *wte, *wta, *w1e, *w1a;
    cudaGetSymbolAddress((void**)&xb,  g_XB);
    cudaGetSymbolAddress((void**)&t1b, g_T1B);
    cudaGetSymbolAddress((void**)&e2b, g_E2B);
    cudaGetSymbolAddress((void**)&w81, g_W81);
    cudaGetSymbolAddress((void**)&fsn, g_FSN);
    cudaGetSymbolAddress((void**)&aln, g_ALN);
    cudaGetSymbolAddress((void**)&alc, g_ALC);
    cudaGetSymbolAddress((void**)&a2,  g_A2);
    cudaGetSymbolAddress((void**)&a3,  g_A3);
    cudaGetSymbolAddress((void**)&wte, g_WTE);
    cudaGetSymbolAddress((void**)&wta, g_WTA);
    cudaGetSymbolAddress((void**)&w1e, g_W1E);
    cudaGetSymbolAddress((void**)&w1a, g_W1A);

    const int PBLK  = (HW + 255) / 256;   // 157
    const int MBLK  = (HW + 127) / 128;   // 313
    const int M64   = (HW + 63) / 64;     // 625

    // weight prep (cheap, independent)
    k_wprep<<<(9 * 64 * 64 + 255) / 256, 256>>>(ec2_w, wte, 64);
    k_wprep<<<(9 * 32 * 64 + 255) / 256, 256>>>(ag2_w, wta, 32);
    k_wprep1<<<(64 * CI + 255) / 256, 256>>>(ec1_w, w1e);
    k_wprep1<<<(64 * CI + 255) / 256, 256>>>(ag1_w, w1a);

    // input prep
    k_trans<<<dim3(HW / 32, CI / 32, BQ), dim3(32, 8)>>>(fs, fsn, CI, HW);
    k_prep_xb<<<dim3(HW / 32, 4, NBT), dim3(32, 8)>>>(fs, fc, xb);

    // encoder
    conv1_hmma<<<dim3(M64, NBT), 128>>>(xb, w1e, ec1_b, t1b);
    conv3_hmma<64, true><<<dim3(MBLK, NBT), 256>>>(t1b, wte, ec2_b, e2b);

    // correlation + softmax
    k_corr<<<dim3(HW / 8, BQ), 256>>>(e2b, w81);

    // weighted aggregation (warp per 4 pixels => HW/4 groups / 8 warps)
    k_align<<<dim3(HW / 32, BQ), 256>>>(w81, fsn, aln);
    k_trans<<<dim3(CI / 32, HW / 32, BQ), dim3(32, 8)>>>(aln, alc, HW, CI);
    k_aln2bf16<<<(unsigned)(((size_t)BQ * HW * CI / 4 + 255) / 256), 256>>>(aln, xb);

    // gating head
    conv1_hmma<<<dim3(M64, NBT), 128>>>(xb, w1a, ag1_b, t1b);
    conv3_hmma<32, false><<<dim3(MBLK, NBT), 256>>>(t1b, wta, ag2_b, a2);
    k_ag3<<<dim3(PBLK, NBT), 256>>>(a2, ag3_w, ag3_b, a3);

    // final blend
    size_t tot = (size_t)BQ * CI * HW;
    k_final<<<(unsigned)((tot + 255) / 256), 256>>>(a3, alc, fc, out);
}

// round 9
// speedup vs baseline: 1.9149x; 1.3907x over previous
#include <cuda_runtime.h>
#include <cuda_bf16.h>
#include <cstdint>

// Problem constants
#define HB 200
#define WB 200
#define HW 40000          // H*W
#define BQ 4              // batch
#define NBT 8             // 2*batch (cat)
#define CI 128            // input channels
#define CE 64             // embed channels
#define RR 4              // neighborhood radius
#define K81 81            // 9x9 offsets

typedef unsigned long long ull;

__device__ __forceinline__ uint32_t smem_u32(const void* p) {
    uint32_t a;
    asm("{ .reg .u64 t; cvta.to.shared.u64 t, %1; cvt.u32.u64 %0, t; }" : "=r"(a) : "l"(p));
    return a;
}

// warp-level bf16 MMA: D(16x8,f32) += A(16x16,bf16) * B(16x8,bf16)
__device__ __forceinline__ void mma16816(float* c, const uint32_t* a, uint32_t b0, uint32_t b1) {
    asm volatile(
        "mma.sync.aligned.m16n8k16.row.col.f32.bf16.bf16.f32 "
        "{%0,%1,%2,%3}, {%4,%5,%6,%7}, {%8,%9}, {%0,%1,%2,%3};"
        : "+f"(c[0]), "+f"(c[1]), "+f"(c[2]), "+f"(c[3])
        : "r"(a[0]), "r"(a[1]), "r"(a[2]), "r"(a[3]), "r"(b0), "r"(b1));
}
__device__ __forceinline__ void ldmatrix_x4(uint32_t* r, uint32_t addr) {
    asm volatile("ldmatrix.sync.aligned.m8n8.x4.shared.b16 {%0,%1,%2,%3}, [%4];"
                 : "=r"(r[0]), "=r"(r[1]), "=r"(r[2]), "=r"(r[3]) : "r"(addr));
}
__device__ __forceinline__ uint32_t bf16x2(float x, float y) {
    uint32_t r;
    asm("cvt.rn.satfinite.bf16x2.f32 %0, %1, %2;" : "=r"(r) : "f"(y), "f"(x));
    return r;
}

// ---------------- scratch (device globals) ------------
__device__ __nv_bfloat16 g_XB [(size_t)NBT * HW * CI];   // conv1 input, NHWC bf16
__device__ __nv_bfloat16 g_T1B[(size_t)NBT * HW * CE];   // conv1 out, NHWC bf16
__device__ __nv_bfloat16 g_E2B[(size_t)NBT * HW * CE];   // ec2 out, NHWC bf16
__device__ float g_W81[(size_t)BQ  * HW * K81];
__device__ float g_FSN[(size_t)BQ  * HW * CI];           // feature_select NHWC fp32
__device__ float g_ALN[(size_t)BQ  * HW * CI];           // align NHWC fp32
__device__ float g_A3 [(size_t)NBT * HW];
__device__ __nv_bfloat16 g_WTE[9 * 64 * 64];             // ec2 weights bf16 [tap][oc][ic]
__device__ __nv_bfloat16 g_WTA[9 * 32 * 64];             // ag2 weights bf16
__device__ __nv_bfloat16 g_W1E[64 * CI];                 // ec1 weights bf16 [oc][ic]
__device__ __nv_bfloat16 g_W1A[64 * CI];                 // ag1 weights bf16

// ---------------- generic 32x32 tiled transpose: [n][A][B] -> [n][B][A] ------
__global__ void k_trans(const float* __restrict__ src, float* __restrict__ dst,
                        int A, int B) {
    __shared__ float t[32][33];
    int n = blockIdx.z;
    size_t base = (size_t)n * A * B;
    int a0 = blockIdx.y * 32, b0 = blockIdx.x * 32;
    int tx = threadIdx.x, ty = threadIdx.y;
#pragma unroll
    for (int i = 0; i < 4; i++) {
        int a = a0 + ty + i * 8, b = b0 + tx;
        if (a < A && b < B) t[ty + i * 8][tx] = src[base + (size_t)a * B + b];
    }
    __syncthreads();
#pragma unroll
    for (int i = 0; i < 4; i++) {
        int b = b0 + ty + i * 8, a = a0 + tx;
        if (a < A && b < B) dst[base + (size_t)b * A + a] = t[tx][ty + i * 8];
    }
}

// ------- NCHW fp32 [4][128][HW] (fs|fc) -> NHWC bf16 [8][HW][128] ------------
__global__ void k_prep_xb(const float* __restrict__ fs, const float* __restrict__ fc,
                          __nv_bfloat16* __restrict__ dst) {
    __shared__ float t[32][33];
    int n = blockIdx.z, ct = blockIdx.y;   // ct: channel tile 0..3
    const float* s = ((n < BQ) ? fs : fc) + (size_t)(n & 3) * CI * HW;
    __nv_bfloat16* d = dst + (size_t)n * HW * CI;
    int b0 = blockIdx.x * 32;
    int tx = threadIdx.x, ty = threadIdx.y;
#pragma unroll
    for (int i = 0; i < 4; i++)
        t[ty + i * 8][tx] = s[(size_t)(ct * 32 + ty + i * 8) * HW + b0 + tx];
    __syncthreads();
#pragma unroll
    for (int i = 0; i < 4; i++)
        d[(size_t)(b0 + ty + i * 8) * CI + ct * 32 + tx] = __float2bfloat16(t[tx][ty + i * 8]);
}

// ---------------- weight prep: [OC][64][3][3] fp32 -> [9][OC][64] bf16 --------
__global__ void k_wprep(const float* __restrict__ w, __nv_bfloat16* __restrict__ dst, int OC) {
    int i = blockIdx.x * 256 + threadIdx.x;
    int tot = 9 * OC * 64;
    if (i >= tot) return;
    int ic = i & 63;
    int rest = i >> 6;
    int oc = rest % OC;
    int tap = rest / OC;
    dst[((size_t)tap * OC + oc) * 64 + ic] = __float2bfloat16(w[((size_t)oc * 64 + ic) * 9 + tap]);
}
// ---------------- weight prep: [64][128] fp32 -> bf16 same layout -------------
__global__ void k_wprep1(const float* __restrict__ w, __nv_bfloat16* __restrict__ dst) {
    int i = blockIdx.x * 256 + threadIdx.x;
    if (i < 64 * CI) dst[i] = __float2bfloat16(w[i]);
}

// ---------------- 1x1 conv via bf16 mma.sync ----------------------------------
// CTA: 64 pixels (M) x 64 (N), K=128. 128 threads = 4 warps, warp owns 16 rows.
__global__ __launch_bounds__(128) void conv1_hmma(
    const __nv_bfloat16* __restrict__ xb,
    const __nv_bfloat16* __restrict__ wb,
    const float* __restrict__ bias,
    __nv_bfloat16* __restrict__ out)
{
    constexpr int LDA = 136;
    __shared__ __align__(16) __nv_bfloat16 As[64 * LDA];
    __shared__ __align__(16) __nv_bfloat16 Bs[64 * LDA];

    int tid = threadIdx.x;
    int wid = tid >> 5, l = tid & 31;
    int n = blockIdx.y;
    int p0 = blockIdx.x * 64;
    int m0 = wid * 16;

    {
        int r = tid >> 1, h = tid & 1;
        int p = p0 + r;
        bool v = p < HW;
        const uint4* src = reinterpret_cast<const uint4*>(
            xb + ((size_t)n * HW + (v ? p : 0)) * CI + h * 64);
        uint4* dst = reinterpret_cast<uint4*>(As + r * LDA + h * 64);
        uint4 zz = make_uint4(0u, 0u, 0u, 0u);
#pragma unroll
        for (int c = 0; c < 8; c++) dst[c] = v ? src[c] : zz;
    }
    {
        const uint4* src = reinterpret_cast<const uint4*>(wb);
#pragma unroll
        for (int i = 0; i < 8; i++) {
            int e = tid + i * 128;
            int row = e >> 4, h8 = e & 15;
            *reinterpret_cast<uint4*>(Bs + row * LDA + h8 * 8) = src[e];
        }
    }
    __syncthreads();

    uint32_t as_base = smem_u32(As);
    uint32_t bs_base = smem_u32(Bs);

    float acc[8][4];
#pragma unroll
    for (int t = 0; t < 8; t++)
#pragma unroll
        for (int i = 0; i < 4; i++) acc[t][i] = 0.f;

#pragma unroll
    for (int ks = 0; ks < 8; ks++) {
        uint32_t afrag[4];
        uint32_t aaddr = as_base + ((m0 + (l & 15)) * LDA + ((l >> 4) * 8 + ks * 16)) * 2;
        ldmatrix_x4(afrag, aaddr);
#pragma unroll
        for (int nt = 0; nt < 8; nt++) {
            uint32_t baddr = bs_base + ((nt * 8 + (l >> 2)) * LDA + ks * 16 + (l & 3) * 2) * 2;
            uint32_t bv0, bv1;
            asm volatile("ld.shared.b32 %0, [%1];" : "=r"(bv0) : "r"(baddr));
            asm volatile("ld.shared.b32 %0, [%1];" : "=r"(bv1) : "r"(baddr + 16));
            mma16816(acc[nt], afrag, bv0, bv1);
        }
    }

    int row_a = m0 + (l >> 2);
    int col0 = (l & 3) * 2;
#pragma unroll
    for (int half = 0; half < 2; half++) {
        int prow = p0 + row_a + half * 8;
        if (prow >= HW) continue;
        __nv_bfloat16* ob = out + ((size_t)n * HW + prow) * CE;
#pragma unroll
        for (int nt = 0; nt < 8; nt++) {
            int c = nt * 8 + col0;
            float vx = fmaxf(acc[nt][half * 2 + 0] + bias[c],     0.f);
            float vy = fmaxf(acc[nt][half * 2 + 1] + bias[c + 1], 0.f);
            *reinterpret_cast<uint32_t*>(ob + c) = bf16x2(vx, vy);
        }
    }
}

// ---------------- 3x3 conv (ec2) via warp-level bf16 mma.sync -----------------
__global__ __launch_bounds__(256) void conv3_hmma64(
    const __nv_bfloat16* __restrict__ inb,
    const __nv_bfloat16* __restrict__ wt,
    const float* __restrict__ bias,
    __nv_bfloat16* __restrict__ out)
{
    constexpr int OC = 64, LDA = 72, NT = OC / 8;
    __shared__ __align__(16) __nv_bfloat16 As[128 * LDA];
    __shared__ __align__(16) __nv_bfloat16 Bs[OC * LDA];

    int tid = threadIdx.x;
    int wid = tid >> 5, l = tid & 31;
    int n = blockIdx.y;
    int p0 = blockIdx.x * 128;

    int ar = tid >> 1, ah = tid & 1;
    int ap = p0 + ar;
    bool apv = ap < HW;
    int ay = ap / WB, ax = ap - ay * WB;

    uint32_t as_base = smem_u32(As);
    uint32_t bs_base = smem_u32(Bs);

    float acc[NT][4];
#pragma unroll
    for (int t = 0; t < NT; t++)
#pragma unroll
        for (int i = 0; i < 4; i++) acc[t][i] = 0.f;

    int m0 = wid * 16;

    for (int tap = 0; tap < 9; tap++) {
        int dy = tap / 3 - 1, dx = tap % 3 - 1;
        __syncthreads();
        {
            bool v = apv && ((unsigned)(ay + dy) < HB) && ((unsigned)(ax + dx) < WB);
            const uint4* src = reinterpret_cast<const uint4*>(
                inb + ((size_t)n * HW + (ap + dy * WB + dx)) * CE + ah * 32);
            uint4* dst = reinterpret_cast<uint4*>(As + ar * LDA + ah * 32);
            uint4 zz = make_uint4(0u, 0u, 0u, 0u);
#pragma unroll
            for (int c = 0; c < 4; c++) dst[c] = v ? src[c] : zz;
        }
        if (tid < OC * 2) {
            int row = tid >> 1, h = tid & 1;
            const uint4* src = reinterpret_cast<const uint4*>(
                wt + ((size_t)tap * OC + row) * 64 + h * 32);
            uint4* dst = reinterpret_cast<uint4*>(Bs + row * LDA + h * 32);
#pragma unroll
            for (int c = 0; c < 4; c++) dst[c] = src[c];
        }
        __syncthreads();

#pragma unroll
        for (int ks = 0; ks < 4; ks++) {
            uint32_t afrag[4];
            uint32_t aaddr = as_base + ((m0 + (l & 15)) * LDA + ((l >> 4) * 8 + ks * 16)) * 2;
            ldmatrix_x4(afrag, aaddr);
#pragma unroll
            for (int nt = 0; nt < NT; nt++) {
                uint32_t baddr = bs_base + ((nt * 8 + (l >> 2)) * LDA + ks * 16 + (l & 3) * 2) * 2;
                uint32_t bv0, bv1;
                asm volatile("ld.shared.b32 %0, [%1];" : "=r"(bv0) : "r"(baddr));
                asm volatile("ld.shared.b32 %0, [%1];" : "=r"(bv1) : "r"(baddr + 16));
                mma16816(acc[nt], afrag, bv0, bv1);
            }
        }
    }

    int row_a = m0 + (l >> 2);
    int col0 = (l & 3) * 2;
#pragma unroll
    for (int half = 0; half < 2; half++) {
        int prow = p0 + row_a + half * 8;
        if (prow >= HW) continue;
        __nv_bfloat16* ob = out + ((size_t)n * HW + prow) * OC;
#pragma unroll
        for (int nt = 0; nt < NT; nt++) {
            int c = nt * 8 + col0;
            float vx = fmaxf(acc[nt][half * 2 + 0] + bias[c],     0.f);
            float vy = fmaxf(acc[nt][half * 2 + 1] + bias[c + 1], 0.f);
            *reinterpret_cast<uint32_t*>(ob + c) = bf16x2(vx, vy);
        }
    }
}

// ------- 3x3 conv (ag2, OC=32) with FUSED ag3 (32->1 conv + ReLU) -------------
// Mainloop identical; epilogue computes relu(ag2)+bias, dots with ag3 weights,
// reduces over the 4 lanes holding each row, writes a3 directly. No a2 buffer.
__global__ __launch_bounds__(256) void conv3_ag(
    const __nv_bfloat16* __restrict__ inb,
    const __nv_bfloat16* __restrict__ wt,
    const float* __restrict__ bias,
    const float* __restrict__ w3,
    const float* __restrict__ b3,
    float* __restrict__ a3)
{
    constexpr int OC = 32, LDA = 72, NT = OC / 8;
    __shared__ __align__(16) __nv_bfloat16 As[128 * LDA];
    __shared__ __align__(16) __nv_bfloat16 Bs[OC * LDA];

    int tid = threadIdx.x;
    int wid = tid >> 5, l = tid & 31;
    int n = blockIdx.y;
    int p0 = blockIdx.x * 128;

    int ar = tid >> 1, ah = tid & 1;
    int ap = p0 + ar;
    bool apv = ap < HW;
    int ay = ap / WB, ax = ap - ay * WB;

    uint32_t as_base = smem_u32(As);
    uint32_t bs_base = smem_u32(Bs);

    float acc[NT][4];
#pragma unroll
    for (int t = 0; t < NT; t++)
#pragma unroll
        for (int i = 0; i < 4; i++) acc[t][i] = 0.f;

    int m0 = wid * 16;

    for (int tap = 0; tap < 9; tap++) {
        int dy = tap / 3 - 1, dx = tap % 3 - 1;
        __syncthreads();
        {
            bool v = apv && ((unsigned)(ay + dy) < HB) && ((unsigned)(ax + dx) < WB);
            const uint4* src = reinterpret_cast<const uint4*>(
                inb + ((size_t)n * HW + (ap + dy * WB + dx)) * CE + ah * 32);
            uint4* dst = reinterpret_cast<uint4*>(As + ar * LDA + ah * 32);
            uint4 zz = make_uint4(0u, 0u, 0u, 0u);
#pragma unroll
            for (int c = 0; c < 4; c++) dst[c] = v ? src[c] : zz;
        }
        if (tid < OC * 2) {
            int row = tid >> 1, h = tid & 1;
            const uint4* src = reinterpret_cast<const uint4*>(
                wt + ((size_t)tap * OC + row) * 64 + h * 32);
            uint4* dst = reinterpret_cast<uint4*>(Bs + row * LDA + h * 32);
#pragma unroll
            for (int c = 0; c < 4; c++) dst[c] = src[c];
        }
        __syncthreads();

#pragma unroll
        for (int ks = 0; ks < 4; ks++) {
            uint32_t afrag[4];
            uint32_t aaddr = as_base + ((m0 + (l & 15)) * LDA + ((l >> 4) * 8 + ks * 16)) * 2;
            ldmatrix_x4(afrag, aaddr);
#pragma unroll
            for (int nt = 0; nt < NT; nt++) {
                uint32_t baddr = bs_base + ((nt * 8 + (l >> 2)) * LDA + ks * 16 + (l & 3) * 2) * 2;
                uint32_t bv0, bv1;
                asm volatile("ld.shared.b32 %0, [%1];" : "=r"(bv0) : "r"(baddr));
                asm volatile("ld.shared.b32 %0, [%1];" : "=r"(bv1) : "r"(baddr + 16));
                mma16816(acc[nt], afrag, bv0, bv1);
            }
        }
    }

    // --- fused ag3 epilogue
    int col0 = (l & 3) * 2;
    float dot0 = 0.f, dot1 = 0.f;
#pragma unroll
    for (int nt = 0; nt < NT; nt++) {
        int c = nt * 8 + col0;
        float b0v = bias[c], b1v = bias[c + 1];
        float w0 = w3[c], w1 = w3[c + 1];
        dot0 += fmaxf(acc[nt][0] + b0v, 0.f) * w0 + fmaxf(acc[nt][1] + b1v, 0.f) * w1;
        dot1 += fmaxf(acc[nt][2] + b0v, 0.f) * w0 + fmaxf(acc[nt][3] + b1v, 0.f) * w1;
    }
    dot0 += __shfl_xor_sync(0xffffffffu, dot0, 1);
    dot0 += __shfl_xor_sync(0xffffffffu, dot0, 2);
    dot1 += __shfl_xor_sync(0xffffffffu, dot1, 1);
    dot1 += __shfl_xor_sync(0xffffffffu, dot1, 2);
    if ((l & 3) == 0) {
        float b3v = b3[0];
        int pr0 = p0 + m0 + (l >> 2);
        if (pr0 < HW)     a3[(size_t)n * HW + pr0]     = fmaxf(dot0 + b3v, 0.f);
        if (pr0 + 8 < HW) a3[(size_t)n * HW + pr0 + 8] = fmaxf(dot1 + b3v, 0.f);
    }
}

// ---------------- correlation + softmax, SMEM-tiled e_cur halo ----------------
// Block = 8 consecutive same-row pixels (8 warps, warp per pixel).
// Shared halo: 9 rows x 16 cols x 64 ch bf16, cell stride 72 halves (144B,
// staggered to avoid bank conflicts). Borders zero-filled.
__global__ __launch_bounds__(256) void k_corr(
    const __nv_bfloat16* __restrict__ e2b, float* __restrict__ w81)
{
    __shared__ __align__(16) __nv_bfloat16 Ecur[9 * 16 * 72];
    __shared__ float logits_s[8][88];
    int n = blockIdx.y;
    int tid = threadIdx.x;
    int warp = tid >> 5, l = tid & 31;
    int p0 = blockIdx.x * 8;
    int y = p0 / WB, x0 = p0 - y * WB;   // 8 | 200: never crosses rows
    int og = l & 7, cg = l >> 3;

    const __nv_bfloat16* ecur = e2b + (size_t)(n + BQ) * HW * CE;

    // cooperative halo load: 9*16 cells x 8 uint4 each = 1152 uint4
    {
        uint4 zz = make_uint4(0u, 0u, 0u, 0u);
        for (int i = tid; i < 1152; i += 256) {
            int q = i & 7, c = (i >> 3) & 15, r = i >> 7;
            int yy = y + r - RR, xx = x0 + c - RR;
            uint4 val = zz;
            if ((unsigned)yy < HB && (unsigned)xx < WB)
                val = *reinterpret_cast<const uint4*>(
                    ecur + ((size_t)(yy * WB + xx)) * CE + q * 8);
            *reinterpret_cast<uint4*>(&Ecur[(r * 16 + c) * 72 + q * 8]) = val;
        }
    }

    // esel: 16 channels for this lane's channel-group
    int p = p0 + warp;
    float es[16];
    {
        const __nv_bfloat162* esel = reinterpret_cast<const __nv_bfloat162*>(
            e2b + ((size_t)n * HW + p) * CE + cg * 16);
#pragma unroll
        for (int i = 0; i < 8; i++) {
            float2 f = __bfloat1622float2(esel[i]);
            es[2 * i] = f.x; es[2 * i + 1] = f.y;
        }
    }
    __syncthreads();

#pragma unroll
    for (int r = 0; r < 11; r++) {
        int k = r * 8 + og;
        float dot = 0.f;
        if (k < K81) {
            int di = k / 9, dj = k % 9;      // 0..8
            int cell = di * 16 + (warp + dj);
            const __nv_bfloat162* ec = reinterpret_cast<const __nv_bfloat162*>(
                &Ecur[cell * 72 + cg * 16]);
#pragma unroll
            for (int i = 0; i < 8; i++) {
                float2 f = __bfloat1622float2(ec[i]);
                dot = fmaf(es[2 * i], f.x, dot);
                dot = fmaf(es[2 * i + 1], f.y, dot);
            }
        }
        dot += __shfl_xor_sync(0xffffffffu, dot, 8);
        dot += __shfl_xor_sync(0xffffffffu, dot, 16);
        if (cg == 0 && k < K81) logits_s[warp][k] = dot;
    }
    __syncwarp();

    float c0 = logits_s[warp][l];
    float c1 = logits_s[warp][32 + l];
    float c2 = (l < 17) ? logits_s[warp][64 + l] : -3.0e38f;
    float mx = fmaxf(c0, fmaxf(c1, c2));
#pragma unroll
    for (int s = 16; s > 0; s >>= 1) mx = fmaxf(mx, __shfl_xor_sync(0xffffffffu, mx, s));
    float e0 = __expf(c0 - mx);
    float e1 = __expf(c1 - mx);
    float e2v = (l < 17) ? __expf(c2 - mx) : 0.f;
    float sm = e0 + e1 + e2v;
#pragma unroll
    for (int s = 16; s > 0; s >>= 1) sm += __shfl_xor_sync(0xffffffffu, sm, s);
    float inv = 1.f / sm;
    size_t base = ((size_t)n * HW + p) * K81;
    w81[base + l]      = e0 * inv;
    w81[base + 32 + l] = e1 * inv;
    if (l < 17) w81[base + 64 + l] = e2v * inv;
}

// ---------------- weighted aggregation, warp per 4 consecutive x-pixels ------
// Writes fp32 aln (for final blend) AND bf16 XB batches 0..3 (for ag1).
__global__ __launch_bounds__(256) void k_align(
    const float* __restrict__ w81, const float* __restrict__ fsn,
    float* __restrict__ aln, __nv_bfloat16* __restrict__ xb)
{
    int n = blockIdx.y;
    int warp = threadIdx.x >> 5, l = threadIdx.x & 31;
    int pg = blockIdx.x * 8 + warp;
    int p0 = pg * 4;
    if (p0 >= HW) return;
    int y = p0 / WB, x0 = p0 - y * WB;

    const float* wp = w81 + ((size_t)n * HW + p0) * K81;
    const float* fb = fsn + (size_t)n * HW * CI;

    float4 acc[4];
#pragma unroll
    for (int m = 0; m < 4; m++) acc[m] = make_float4(0.f, 0.f, 0.f, 0.f);

    for (int di = -RR; di <= RR; di++) {
        int yy = y + di;
        if ((unsigned)yy >= HB) continue;
        float4 fq[12];
#pragma unroll
        for (int j = 0; j < 12; j++) {
            int xx = x0 - RR + j;
            fq[j] = ((unsigned)xx < WB)
                ? *(const float4*)(fb + ((size_t)(yy * WB + xx)) * CI + 4 * l)
                : make_float4(0.f, 0.f, 0.f, 0.f);
        }
        int kbase = (di + RR) * 9;
#pragma unroll
        for (int m = 0; m < 4; m++) {
#pragma unroll
            for (int dj = 0; dj < 9; dj++) {
                float wv = wp[m * K81 + kbase + dj];
                float4 f = fq[m + dj];
                acc[m].x += wv * f.x; acc[m].y += wv * f.y;
                acc[m].z += wv * f.z; acc[m].w += wv * f.w;
            }
        }
    }
#pragma unroll
    for (int m = 0; m < 4; m++) {
        size_t off = ((size_t)n * HW + p0 + m) * CI + 4 * l;
        *(float4*)(aln + off) = acc[m];
        *(uint2*)(xb + off) = make_uint2(bf16x2(acc[m].x, acc[m].y),
                                         bf16x2(acc[m].z, acc[m].w));
    }
}

// ------- final blend fused with NHWC->NCHW transpose --------------------------
// out[n][c][p] = ws(p)*aln[n][p][c] + wc(p)*fc[n][c][p]
__global__ void k_final(const float* __restrict__ a3, const float* __restrict__ aln,
                        const float* __restrict__ fc, float* __restrict__ out) {
    __shared__ float t[32][33];
    int n = blockIdx.z;
    int c0 = blockIdx.x * 32, p0 = blockIdx.y * 32;
    int tx = threadIdx.x, ty = threadIdx.y;
#pragma unroll
    for (int i = 0; i < 4; i++)
        t[ty + i * 8][tx] = aln[((size_t)n * HW + p0 + ty + i * 8) * CI + c0 + tx];
    // per-pixel gate weights (pixel = p0+tx)
    int p = p0 + tx;
    float as = a3[(size_t)n * HW + p];
    float ac = a3[(size_t)(n + BQ) * HW + p];
    float m = fmaxf(as, ac);
    float ea = __expf(as - m), eb = __expf(ac - m);
    float inv = 1.f / (ea + eb);
    float ws = ea * inv, wc = eb * inv;
    __syncthreads();
#pragma unroll
    for (int i = 0; i < 4; i++) {
        int c = c0 + ty + i * 8;
        size_t o = ((size_t)n * CI + c) * HW + p;
        out[o] = ws * t[tx][ty + i * 8] + wc * fc[o];
    }
}

// ---------------- launch ------------------------------------------------------
extern "C" void kernel_launch(void* const* d_in, const int* in_sizes, int n_in,
                              void* d_out, int out_size) {
    const float* fs    = (const float*)d_in[0];
    const float* fc    = (const float*)d_in[1];
    const float* ec1_w = (const float*)d_in[2];
    const float* ec1_b = (const float*)d_in[3];
    const float* ec2_w = (const float*)d_in[4];
    const float* ec2_b = (const float*)d_in[5];
    const float* ag1_w = (const float*)d_in[6];
    const float* ag1_b = (const float*)d_in[7];
    const float* ag2_w = (const float*)d_in[8];
    const float* ag2_b = (const float*)d_in[9];
    const float* ag3_w = (const float*)d_in[10];
    const float* ag3_b = (const float*)d_in[11];
    float* out = (float*)d_out;

    float *w81, *fsn, *aln, *a3;
    __nv_bfloat16 *xb, *t1b, *e2b, *wte, *wta, *w1e, *w1a;
    cudaGetSymbolAddress((void**)&xb,  g_XB);
    cudaGetSymbolAddress((void**)&t1b, g_T1B);
    cudaGetSymbolAddress((void**)&e2b, g_E2B);
    cudaGetSymbolAddress((void**)&w81, g_W81);
    cudaGetSymbolAddress((void**)&fsn, g_FSN);
    cudaGetSymbolAddress((void**)&aln, g_ALN);
    cudaGetSymbolAddress((void**)&a3,  g_A3);
    cudaGetSymbolAddress((void**)&wte, g_WTE);
    cudaGetSymbolAddress((void**)&wta, g_WTA);
    cudaGetSymbolAddress((void**)&w1e, g_W1E);
    cudaGetSymbolAddress((void**)&w1a, g_W1A);

    const int MBLK = (HW + 127) / 128;   // 313
    const int M64  = (HW + 63) / 64;     // 625

    // weight prep (cheap, independent)
    k_wprep<<<(9 * 64 * 64 + 255) / 256, 256>>>(ec2_w, wte, 64);
    k_wprep<<<(9 * 32 * 64 + 255) / 256, 256>>>(ag2_w, wta, 32);
    k_wprep1<<<(64 * CI + 255) / 256, 256>>>(ec1_w, w1e);
    k_wprep1<<<(64 * CI + 255) / 256, 256>>>(ag1_w, w1a);

    // input prep
    k_trans<<<dim3(HW / 32, CI / 32, BQ), dim3(32, 8)>>>(fs, fsn, CI, HW);
    k_prep_xb<<<dim3(HW / 32, 4, NBT), dim3(32, 8)>>>(fs, fc, xb);

    // encoder
    conv1_hmma<<<dim3(M64, NBT), 128>>>(xb, w1e, ec1_b, t1b);
    conv3_hmma64<<<dim3(MBLK, NBT), 256>>>(t1b, wte, ec2_b, e2b);

    // correlation + softmax
    k_corr<<<dim3(HW / 8, BQ), 256>>>(e2b, w81);

    // weighted aggregation (writes fp32 aln + bf16 xb[0..3])
    k_align<<<dim3(HW / 32, BQ), 256>>>(w81, fsn, aln, xb);

    // gating head (ag2+ag3 fused)
    conv1_hmma<<<dim3(M64, NBT), 128>>>(xb, w1a, ag1_b, t1b);
    conv3_ag<<<dim3(MBLK, NBT), 256>>>(t1b, wta, ag2_b, ag3_w, ag3_b, a3);

    // final blend (transpose fused)
    k_final<<<dim3(CI / 32, HW / 32, BQ), dim3(32, 8)>>>(a3, aln, fc, out);
}

// round 12
// speedup vs baseline: 2.3115x; 1.2071x over previous
#include <cuda_runtime.h>
#include <cuda_bf16.h>
#include <cstdint>

// Problem constants
#define HB 200
#define WB 200
#define HW 40000          // H*W
#define BQ 4              // batch
#define NBT 8             // 2*batch (cat)
#define CI 128            // input channels
#define CE 64             // embed channels
#define RR 4              // neighborhood radius
#define K81 81            // 9x9 offsets

typedef unsigned long long ull;

__device__ __forceinline__ uint32_t smem_u32(const void* p) {
    uint32_t a;
    asm("{ .reg .u64 t; cvta.to.shared.u64 t, %1; cvt.u32.u64 %0, t; }" : "=r"(a) : "l"(p));
    return a;
}

// warp-level bf16 MMA: D(16x8,f32) += A(16x16,bf16) * B(16x8,bf16)
__device__ __forceinline__ void mma16816(float* c, const uint32_t* a, uint32_t b0, uint32_t b1) {
    asm volatile(
        "mma.sync.aligned.m16n8k16.row.col.f32.bf16.bf16.f32 "
        "{%0,%1,%2,%3}, {%4,%5,%6,%7}, {%8,%9}, {%0,%1,%2,%3};"
        : "+f"(c[0]), "+f"(c[1]), "+f"(c[2]), "+f"(c[3])
        : "r"(a[0]), "r"(a[1]), "r"(a[2]), "r"(a[3]), "r"(b0), "r"(b1));
}
__device__ __forceinline__ void ldmatrix_x4(uint32_t* r, uint32_t addr) {
    asm volatile("ldmatrix.sync.aligned.m8n8.x4.shared.b16 {%0,%1,%2,%3}, [%4];"
                 : "=r"(r[0]), "=r"(r[1]), "=r"(r[2]), "=r"(r[3]) : "r"(addr));
}
__device__ __forceinline__ uint32_t bf16x2(float x, float y) {
    uint32_t r;
    asm("cvt.rn.satfinite.bf16x2.f32 %0, %1, %2;" : "=r"(r) : "f"(y), "f"(x));
    return r;
}

// ---------------- scratch (device globals) ------------
__device__ __nv_bfloat16 g_XB [(size_t)NBT * HW * CI];   // conv1 input, NHWC bf16
__device__ __nv_bfloat16 g_T1B[(size_t)NBT * HW * CE];   // conv1 out, NHWC bf16
__device__ __nv_bfloat16 g_E2B[(size_t)NBT * HW * CE];   // ec2 out, NHWC bf16
__device__ float g_W81[(size_t)BQ  * HW * K81];
__device__ float g_FSN[(size_t)BQ  * HW * CI];           // feature_select NHWC fp32
__device__ float g_ALN[(size_t)BQ  * HW * CI];           // align NHWC fp32
__device__ float g_A3 [(size_t)NBT * HW];
__device__ __nv_bfloat16 g_WTE[9 * 64 * 64];             // ec2 weights bf16 [tap][oc][ic]
__device__ __nv_bfloat16 g_WTA[9 * 32 * 64];             // ag2 weights bf16
__device__ __nv_bfloat16 g_W1E[64 * CI];                 // ec1 weights bf16 [oc][ic]
__device__ __nv_bfloat16 g_W1A[64 * CI];                 // ag1 weights bf16

// ------- NCHW fp32 [4][128][HW] (fs|fc) -> NHWC bf16 [8][HW][128] + fsn fp32 --
__global__ void k_prep_xb(const float* __restrict__ fs, const float* __restrict__ fc,
                          __nv_bfloat16* __restrict__ dst, float* __restrict__ fsn) {
    __shared__ float t[32][33];
    int n = blockIdx.z, ct = blockIdx.y;   // ct: channel tile 0..3
    const float* s = ((n < BQ) ? fs : fc) + (size_t)(n & 3) * CI * HW;
    __nv_bfloat16* d = dst + (size_t)n * HW * CI;
    int b0 = blockIdx.x * 32;
    int tx = threadIdx.x, ty = threadIdx.y;
#pragma unroll
    for (int i = 0; i < 4; i++)
        t[ty + i * 8][tx] = s[(size_t)(ct * 32 + ty + i * 8) * HW + b0 + tx];
    __syncthreads();
#pragma unroll
    for (int i = 0; i < 4; i++) {
        float v = t[tx][ty + i * 8];
        size_t off = (size_t)(b0 + ty + i * 8) * CI + ct * 32 + tx;
        d[(size_t)n * 0 + off] = __float2bfloat16(v);   // d already offset by n
        if (n < BQ) fsn[(size_t)n * HW * CI + off] = v;
    }
}

// ---------------- weight prep: [OC][64][3][3] fp32 -> [9][OC][64] bf16 --------
__global__ void k_wprep(const float* __restrict__ w, __nv_bfloat16* __restrict__ dst, int OC) {
    int i = blockIdx.x * 256 + threadIdx.x;
    int tot = 9 * OC * 64;
    if (i >= tot) return;
    int ic = i & 63;
    int rest = i >> 6;
    int oc = rest % OC;
    int tap = rest / OC;
    dst[((size_t)tap * OC + oc) * 64 + ic] = __float2bfloat16(w[((size_t)oc * 64 + ic) * 9 + tap]);
}
// ---------------- weight prep: [64][128] fp32 -> bf16 same layout -------------
__global__ void k_wprep1(const float* __restrict__ w, __nv_bfloat16* __restrict__ dst) {
    int i = blockIdx.x * 256 + threadIdx.x;
    if (i < 64 * CI) dst[i] = __float2bfloat16(w[i]);
}

// ---------------- 1x1 conv via bf16 mma.sync ----------------------------------
// CTA: 64 pixels (M) x 64 (N), K=128. 128 threads = 4 warps, warp owns 16 rows.
__global__ __launch_bounds__(128) void conv1_hmma(
    const __nv_bfloat16* __restrict__ xb,
    const __nv_bfloat16* __restrict__ wb,
    const float* __restrict__ bias,
    __nv_bfloat16* __restrict__ out)
{
    constexpr int LDA = 136;
    __shared__ __align__(16) __nv_bfloat16 As[64 * LDA];
    __shared__ __align__(16) __nv_bfloat16 Bs[64 * LDA];

    int tid = threadIdx.x;
    int wid = tid >> 5, l = tid & 31;
    int n = blockIdx.y;
    int p0 = blockIdx.x * 64;
    int m0 = wid * 16;

    {
        int r = tid >> 1, h = tid & 1;
        int p = p0 + r;
        bool v = p < HW;
        const uint4* src = reinterpret_cast<const uint4*>(
            xb + ((size_t)n * HW + (v ? p : 0)) * CI + h * 64);
        uint4* dst = reinterpret_cast<uint4*>(As + r * LDA + h * 64);
        uint4 zz = make_uint4(0u, 0u, 0u, 0u);
#pragma unroll
        for (int c = 0; c < 8; c++) dst[c] = v ? src[c] : zz;
    }
    {
        const uint4* src = reinterpret_cast<const uint4*>(wb);
#pragma unroll
        for (int i = 0; i < 8; i++) {
            int e = tid + i * 128;
            int row = e >> 4, h8 = e & 15;
            *reinterpret_cast<uint4*>(Bs + row * LDA + h8 * 8) = src[e];
        }
    }
    __syncthreads();

    uint32_t as_base = smem_u32(As);
    uint32_t bs_base = smem_u32(Bs);

    float acc[8][4];
#pragma unroll
    for (int t = 0; t < 8; t++)
#pragma unroll
        for (int i = 0; i < 4; i++) acc[t][i] = 0.f;

#pragma unroll
    for (int ks = 0; ks < 8; ks++) {
        uint32_t afrag[4];
        uint32_t aaddr = as_base + ((m0 + (l & 15)) * LDA + ((l >> 4) * 8 + ks * 16)) * 2;
        ldmatrix_x4(afrag, aaddr);
#pragma unroll
        for (int nt = 0; nt < 8; nt++) {
            uint32_t baddr = bs_base + ((nt * 8 + (l >> 2)) * LDA + ks * 16 + (l & 3) * 2) * 2;
            uint32_t bv0, bv1;
            asm volatile("ld.shared.b32 %0, [%1];" : "=r"(bv0) : "r"(baddr));
            asm volatile("ld.shared.b32 %0, [%1];" : "=r"(bv1) : "r"(baddr + 16));
            mma16816(acc[nt], afrag, bv0, bv1);
        }
    }

    int row_a = m0 + (l >> 2);
    int col0 = (l & 3) * 2;
#pragma unroll
    for (int half = 0; half < 2; half++) {
        int prow = p0 + row_a + half * 8;
        if (prow >= HW) continue;
        __nv_bfloat16* ob = out + ((size_t)n * HW + prow) * CE;
#pragma unroll
        for (int nt = 0; nt < 8; nt++) {
            int c = nt * 8 + col0;
            float vx = fmaxf(acc[nt][half * 2 + 0] + bias[c],     0.f);
            float vy = fmaxf(acc[nt][half * 2 + 1] + bias[c + 1], 0.f);
            *reinterpret_cast<uint32_t*>(ob + c) = bf16x2(vx, vy);
        }
    }
}

// ---------------- 3x3 conv, 2D halo-resident tile -----------------------------
// CTA = 8 rows x 16 cols of pixels (128 M-rows). Halo 10x18 cells x 64ch bf16
// loaded ONCE; 9 taps via per-lane shifted ldmatrix addresses. B double-buffered.
// FUSE_AG: epilogue fuses ag3 (32->1 dot + ReLU) and writes a3.
template <int OC, bool FUSE_AG>
__global__ __launch_bounds__(256) void conv3_tile(
    const __nv_bfloat16* __restrict__ inb,
    const __nv_bfloat16* __restrict__ wt,
    const float* __restrict__ bias,
    const float* __restrict__ w3,
    const float* __restrict__ b3,
    void* __restrict__ out_)
{
    constexpr int LDC = 72;              // halves per 64-ch cell (16B stagger)
    constexpr int NT  = OC / 8;
    __shared__ __align__(16) __nv_bfloat16 Hs[180 * LDC];        // 10x18 halo
    __shared__ __align__(16) __nv_bfloat16 Bs[2][OC * LDC];

    int tid = threadIdx.x;
    int wid = tid >> 5, l = tid & 31;
    int n = blockIdx.y;
    int tile = blockIdx.x;
    int tx0 = (tile % 13) * 16, ty0 = (tile / 13) * 8;

    const __nv_bfloat16* src_base = inb + (size_t)n * HW * CE;

    // --- halo load: 180 cells x 8 uint4
    {
        uint4 zz = make_uint4(0u, 0u, 0u, 0u);
        for (int i = tid; i < 1440; i += 256) {
            int q = i & 7, cell = i >> 3;
            int hr = cell / 18, hc = cell - hr * 18;
            int yy = ty0 - 1 + hr, xx = tx0 - 1 + hc;
            uint4 val = zz;
            if ((unsigned)yy < HB && (unsigned)xx < WB)
                val = *reinterpret_cast<const uint4*>(
                    src_base + ((size_t)(yy * WB + xx)) * CE + q * 8);
            *reinterpret_cast<uint4*>(&Hs[cell * LDC + q * 8]) = val;
        }
    }
    // --- stage B tap 0 into buffer 0
    for (int i = tid; i < OC * 8; i += 256) {
        int row = i >> 3, q = i & 7;
        *reinterpret_cast<uint4*>(&Bs[0][row * LDC + q * 8]) =
            *reinterpret_cast<const uint4*>(wt + (size_t)row * 64 + q * 8);
    }
    __syncthreads();

    uint32_t hs_base = smem_u32(Hs);
    uint32_t bs_base0 = smem_u32(&Bs[0][0]);
    uint32_t bs_base1 = smem_u32(&Bs[1][0]);

    float acc[NT][4];
#pragma unroll
    for (int t = 0; t < NT; t++)
#pragma unroll
        for (int i = 0; i < 4; i++) acc[t][i] = 0.f;

    int tc = l & 15;            // A-row pixel col within tile (rows of warp = wid)
    int chalf = (l >> 4) * 8;   // 8-col half select for ldmatrix

#pragma unroll
    for (int tap = 0; tap < 9; tap++) {
        int dy = tap / 3, dx = tap % 3;
        uint32_t bs_cur = (tap & 1) ? bs_base1 : bs_base0;
        uint32_t acell = hs_base + (((wid + dy) * 18 + (tc + dx)) * LDC + chalf) * 2;
#pragma unroll
        for (int ks = 0; ks < 4; ks++) {
            uint32_t afrag[4];
            ldmatrix_x4(afrag, acell + ks * 32);
#pragma unroll
            for (int nt = 0; nt < NT; nt++) {
                uint32_t baddr = bs_cur + ((nt * 8 + (l >> 2)) * LDC + ks * 16 + (l & 3) * 2) * 2;
                uint32_t bv0, bv1;
                asm volatile("ld.shared.b32 %0, [%1];" : "=r"(bv0) : "r"(baddr));
                asm volatile("ld.shared.b32 %0, [%1];" : "=r"(bv1) : "r"(baddr + 16));
                mma16816(acc[nt], afrag, bv0, bv1);
            }
        }
        if (tap < 8) {
            __nv_bfloat16* bdst = &Bs[(tap + 1) & 1][0];
            const __nv_bfloat16* bsrc = wt + (size_t)(tap + 1) * OC * 64;
            for (int i = tid; i < OC * 8; i += 256) {
                int row = i >> 3, q = i & 7;
                *reinterpret_cast<uint4*>(bdst + row * LDC + q * 8) =
                    *reinterpret_cast<const uint4*>(bsrc + (size_t)row * 64 + q * 8);
            }
            __syncthreads();
        }
    }

    // --- epilogue
    int y = ty0 + wid;                   // output pixel row (always < HB)
    int col0 = (l & 3) * 2;
    if (FUSE_AG) {
        float dot0 = 0.f, dot1 = 0.f;
#pragma unroll
        for (int nt = 0; nt < NT; nt++) {
            int c = nt * 8 + col0;
            float b0v = bias[c], b1v = bias[c + 1];
            float w0 = w3[c], w1 = w3[c + 1];
            dot0 += fmaxf(acc[nt][0] + b0v, 0.f) * w0 + fmaxf(acc[nt][1] + b1v, 0.f) * w1;
            dot1 += fmaxf(acc[nt][2] + b0v, 0.f) * w0 + fmaxf(acc[nt][3] + b1v, 0.f) * w1;
        }
        dot0 += __shfl_xor_sync(0xffffffffu, dot0, 1);
        dot0 += __shfl_xor_sync(0xffffffffu, dot0, 2);
        dot1 += __shfl_xor_sync(0xffffffffu, dot1, 1);
        dot1 += __shfl_xor_sync(0xffffffffu, dot1, 2);
        if ((l & 3) == 0) {
            float b3v = b3[0];
            float* a3 = (float*)out_;
            int x0p = tx0 + (l >> 2);
            if (x0p < WB)     a3[(size_t)n * HW + y * WB + x0p]     = fmaxf(dot0 + b3v, 0.f);
            if (x0p + 8 < WB) a3[(size_t)n * HW + y * WB + x0p + 8] = fmaxf(dot1 + b3v, 0.f);
        }
    } else {
#pragma unroll
        for (int half = 0; half < 2; half++) {
            int x = tx0 + (l >> 2) + half * 8;
            if (x >= WB) continue;
            __nv_bfloat16* ob = (__nv_bfloat16*)out_ + ((size_t)n * HW + y * WB + x) * OC;
#pragma unroll
            for (int nt = 0; nt < NT; nt++) {
                int c = nt * 8 + col0;
                float vx = fmaxf(acc[nt][half * 2 + 0] + bias[c],     0.f);
                float vy = fmaxf(acc[nt][half * 2 + 1] + bias[c + 1], 0.f);
                *reinterpret_cast<uint32_t*>(ob + c) = bf16x2(vx, vy);
            }
        }
    }
}

// ---------------- correlation + softmax, 2x8-pixel SMEM-tiled halo ------------
// 512 threads = 16 warps, warp per pixel (2 rows x 8 cols). Halo 10x16 cells.
__global__ __launch_bounds__(512) void k_corr(
    const __nv_bfloat16* __restrict__ e2b, float* __restrict__ w81)
{
    __shared__ __align__(16) __nv_bfloat16 Ecur[160 * 72];
    __shared__ float logits_s[16][88];
    int n = blockIdx.y;
    int tid = threadIdx.x;
    int warp = tid >> 5, l = tid & 31;
    int bx = blockIdx.x;                       // 2500 per batch
    int px0 = (bx % 25) * 8, py0 = (bx / 25) * 2;
    int wr = warp >> 3, wc = warp & 7;         // pixel in tile
    int p = (py0 + wr) * WB + px0 + wc;
    int og = l & 7, cg = l >> 3;

    const __nv_bfloat16* ecur = e2b + (size_t)(n + BQ) * HW * CE;

    // halo load: 160 cells x 8 uint4 = 1280
    {
        uint4 zz = make_uint4(0u, 0u, 0u, 0u);
        for (int i = tid; i < 1280; i += 512) {
            int q = i & 7, cell = i >> 3;
            int hr = cell >> 4, hc = cell & 15;
            int yy = py0 - RR + hr, xx = px0 - RR + hc;
            uint4 val = zz;
            if ((unsigned)yy < HB && (unsigned)xx < WB)
                val = *reinterpret_cast<const uint4*>(
                    ecur + ((size_t)(yy * WB + xx)) * CE + q * 8);
            *reinterpret_cast<uint4*>(&Ecur[cell * 72 + q * 8]) = val;
        }
    }

    // esel: 16 channels for this lane's channel-group
    float es[16];
    {
        const __nv_bfloat162* esel = reinterpret_cast<const __nv_bfloat162*>(
            e2b + ((size_t)n * HW + p) * CE + cg * 16);
#pragma unroll
        for (int i = 0; i < 8; i++) {
            float2 f = __bfloat1622float2(esel[i]);
            es[2 * i] = f.x; es[2 * i + 1] = f.y;
        }
    }
    __syncthreads();

#pragma unroll
    for (int r = 0; r < 11; r++) {
        int k = r * 8 + og;
        float dot = 0.f;
        if (k < K81) {
            int di = k / 9, dj = k % 9;        // 0..8
            int cell = (wr + di) * 16 + (wc + dj);
            const __nv_bfloat162* ec = reinterpret_cast<const __nv_bfloat162*>(
                &Ecur[cell * 72 + cg * 16]);
#pragma unroll
            for (int i = 0; i < 8; i++) {
                float2 f = __bfloat1622float2(ec[i]);
                dot = fmaf(es[2 * i], f.x, dot);
                dot = fmaf(es[2 * i + 1], f.y, dot);
            }
        }
        dot += __shfl_xor_sync(0xffffffffu, dot, 8);
        dot += __shfl_xor_sync(0xffffffffu, dot, 16);
        if (cg == 0 && k < K81) logits_s[warp][k] = dot;
    }
    __syncwarp();

    float c0 = logits_s[warp][l];
    float c1 = logits_s[warp][32 + l];
    float c2 = (l < 17) ? logits_s[warp][64 + l] : -3.0e38f;
    float mx = fmaxf(c0, fmaxf(c1, c2));
#pragma unroll
    for (int s = 16; s > 0; s >>= 1) mx = fmaxf(mx, __shfl_xor_sync(0xffffffffu, mx, s));
    float e0 = __expf(c0 - mx);
    float e1 = __expf(c1 - mx);
    float e2v = (l < 17) ? __expf(c2 - mx) : 0.f;
    float sm = e0 + e1 + e2v;
#pragma unroll
    for (int s = 16; s > 0; s >>= 1) sm += __shfl_xor_sync(0xffffffffu, sm, s);
    float inv = 1.f / sm;
    size_t base = ((size_t)n * HW + p) * K81;
    w81[base + l]      = e0 * inv;
    w81[base + 32 + l] = e1 * inv;
    if (l < 17) w81[base + 64 + l] = e2v * inv;
}

// ---------------- weighted aggregation, warp per 4 consecutive x-pixels ------
// Writes fp32 aln (for final blend) AND bf16 XB batches 0..3 (for ag1).
__global__ __launch_bounds__(256) void k_align(
    const float* __restrict__ w81, const float* __restrict__ fsn,
    float* __restrict__ aln, __nv_bfloat16* __restrict__ xb)
{
    int n = blockIdx.y;
    int warp = threadIdx.x >> 5, l = threadIdx.x & 31;
    int pg = blockIdx.x * 8 + warp;
    int p0 = pg * 4;
    if (p0 >= HW) return;
    int y = p0 / WB, x0 = p0 - y * WB;

    const float* wp = w81 + ((size_t)n * HW + p0) * K81;
    const float* fb = fsn + (size_t)n * HW * CI;

    float4 acc[4];
#pragma unroll
    for (int m = 0; m < 4; m++) acc[m] = make_float4(0.f, 0.f, 0.f, 0.f);

    for (int di = -RR; di <= RR; di++) {
        int yy = y + di;
        if ((unsigned)yy >= HB) continue;
        float4 fq[12];
#pragma unroll
        for (int j = 0; j < 12; j++) {
            int xx = x0 - RR + j;
            fq[j] = ((unsigned)xx < WB)
                ? *(const float4*)(fb + ((size_t)(yy * WB + xx)) * CI + 4 * l)
                : make_float4(0.f, 0.f, 0.f, 0.f);
        }
        int kbase = (di + RR) * 9;
#pragma unroll
        for (int m = 0; m < 4; m++) {
#pragma unroll
            for (int dj = 0; dj < 9; dj++) {
                float wv = wp[m * K81 + kbase + dj];
                float4 f = fq[m + dj];
                acc[m].x += wv * f.x; acc[m].y += wv * f.y;
                acc[m].z += wv * f.z; acc[m].w += wv * f.w;
            }
        }
    }
#pragma unroll
    for (int m = 0; m < 4; m++) {
        size_t off = ((size_t)n * HW + p0 + m) * CI + 4 * l;
        *(float4*)(aln + off) = acc[m];
        *(uint2*)(xb + off) = make_uint2(bf16x2(acc[m].x, acc[m].y),
                                         bf16x2(acc[m].z, acc[m].w));
    }
}

// ------- final blend fused with NHWC->NCHW transpose --------------------------
__global__ void k_final(const float* __restrict__ a3, const float* __restrict__ aln,
                        const float* __restrict__ fc, float* __restrict__ out) {
    __shared__ float t[32][33];
    int n = blockIdx.z;
    int c0 = blockIdx.x * 32, p0 = blockIdx.y * 32;
    int tx = threadIdx.x, ty = threadIdx.y;
#pragma unroll
    for (int i = 0; i < 4; i++)
        t[ty + i * 8][tx] = aln[((size_t)n * HW + p0 + ty + i * 8) * CI + c0 + tx];
    int p = p0 + tx;
    float as = a3[(size_t)n * HW + p];
    float ac = a3[(size_t)(n + BQ) * HW + p];
    float m = fmaxf(as, ac);
    float ea = __expf(as - m), eb = __expf(ac - m);
    float inv = 1.f / (ea + eb);
    float ws = ea * inv, wc = eb * inv;
    __syncthreads();
#pragma unroll
    for (int i = 0; i < 4; i++) {
        int c = c0 + ty + i * 8;
        size_t o = ((size_t)n * CI + c) * HW + p;
        out[o] = ws * t[tx][ty + i * 8] + wc * fc[o];
    }
}

// ---------------- launch ------------------------------------------------------
extern "C" void kernel_launch(void* const* d_in, const int* in_sizes, int n_in,
                              void* d_out, int out_size) {
    const float* fs    = (const float*)d_in[0];
    const float* fc    = (const float*)d_in[1];
    const float* ec1_w = (const float*)d_in[2];
    const float* ec1_b = (const float*)d_in[3];
    const float* ec2_w = (const float*)d_in[4];
    const float* ec2_b = (const float*)d_in[5];
    const float* ag1_w = (const float*)d_in[6];
    const float* ag1_b = (const float*)d_in[7];
    const float* ag2_w = (const float*)d_in[8];
    const float* ag2_b = (const float*)d_in[9];
    const float* ag3_w = (const float*)d_in[10];
    const float* ag3_b = (const float*)d_in[11];
    float* out = (float*)d_out;

    float *w81, *fsn, *aln, *a3;
    __nv_bfloat16 *xb, *t1b, *e2b, *wte, *wta, *w1e, *w1a;
    cudaGetSymbolAddress((void**)&xb,  g_XB);
    cudaGetSymbolAddress((void**)&t1b, g_T1B);
    cudaGetSymbolAddress((void**)&e2b, g_E2B);
    cudaGetSymbolAddress((void**)&w81, g_W81);
    cudaGetSymbolAddress((void**)&fsn, g_FSN);
    cudaGetSymbolAddress((void**)&aln, g_ALN);
    cudaGetSymbolAddress((void**)&a3,  g_A3);
    cudaGetSymbolAddress((void**)&wte, g_WTE);
    cudaGetSymbolAddress((void**)&wta, g_WTA);
    cudaGetSymbolAddress((void**)&w1e, g_W1E);
    cudaGetSymbolAddress((void**)&w1a, g_W1A);

    const int M64  = (HW + 63) / 64;     // 625
    const int T3   = 13 * 25;            // 325 conv3 tiles per batch

    // weight prep (cheap, independent)
    k_wprep<<<(9 * 64 * 64 + 255) / 256, 256>>>(ec2_w, wte, 64);
    k_wprep<<<(9 * 32 * 64 + 255) / 256, 256>>>(ag2_w, wta, 32);
    k_wprep1<<<(64 * CI + 255) / 256, 256>>>(ec1_w, w1e);
    k_wprep1<<<(64 * CI + 255) / 256, 256>>>(ag1_w, w1a);

    // input prep (also produces fsn fp32 NHWC for batches 0..3)
    k_prep_xb<<<dim3(HW / 32, 4, NBT), dim3(32, 8)>>>(fs, fc, xb, fsn);

    // encoder
    conv1_hmma<<<dim3(M64, NBT), 128>>>(xb, w1e, ec1_b, t1b);
    conv3_tile<64, false><<<dim3(T3, NBT), 256>>>(t1b, wte, ec2_b, nullptr, nullptr, e2b);

    // correlation + softmax (2x8 pixel tiles)
    k_corr<<<dim3(2500, BQ), 512>>>(e2b, w81);

    // weighted aggregation (writes fp32 aln + bf16 xb[0..3])
    k_align<<<dim3(HW / 32, BQ), 256>>>(w81, fsn, aln, xb);

    // gating head (ag2+ag3 fused)
    conv1_hmma<<<dim3(M64, NBT), 128>>>(xb, w1a, ag1_b, t1b);
    conv3_tile<32, true><<<dim3(T3, NBT), 256>>>(t1b, wta, ag2_b, ag3_w, ag3_b, a3);

    // final blend (transpose fused)
    k_final<<<dim3(CI / 32, HW / 32, BQ), dim3(32, 8)>>>(a3, aln, fc, out);
}

// round 15
// speedup vs baseline: 2.4304x; 1.0515x over previous
#include <cuda_runtime.h>
#include <cuda_bf16.h>
#include <cstdint>

// Problem constants
#define HB 200
#define WB 200
#define HW 40000          // H*W
#define BQ 4              // batch
#define NBT 8             // 2*batch (cat)
#define CI 128            // input channels
#define CE 64             // embed channels
#define RR 4              // neighborhood radius
#define K81 81            // 9x9 offsets

typedef unsigned long long ull;

__device__ __forceinline__ uint32_t smem_u32(const void* p) {
    uint32_t a;
    asm("{ .reg .u64 t; cvta.to.shared.u64 t, %1; cvt.u32.u64 %0, t; }" : "=r"(a) : "l"(p));
    return a;
}

// warp-level bf16 MMA: D(16x8,f32) += A(16x16,bf16) * B(16x8,bf16)
__device__ __forceinline__ void mma16816(float* c, const uint32_t* a, uint32_t b0, uint32_t b1) {
    asm volatile(
        "mma.sync.aligned.m16n8k16.row.col.f32.bf16.bf16.f32 "
        "{%0,%1,%2,%3}, {%4,%5,%6,%7}, {%8,%9}, {%0,%1,%2,%3};"
        : "+f"(c[0]), "+f"(c[1]), "+f"(c[2]), "+f"(c[3])
        : "r"(a[0]), "r"(a[1]), "r"(a[2]), "r"(a[3]), "r"(b0), "r"(b1));
}
__device__ __forceinline__ void ldmatrix_x4(uint32_t* r, uint32_t addr) {
    asm volatile("ldmatrix.sync.aligned.m8n8.x4.shared.b16 {%0,%1,%2,%3}, [%4];"
                 : "=r"(r[0]), "=r"(r[1]), "=r"(r[2]), "=r"(r[3]) : "r"(addr));
}
__device__ __forceinline__ uint32_t bf16x2(float x, float y) {
    uint32_t r;
    asm("cvt.rn.satfinite.bf16x2.f32 %0, %1, %2;" : "=r"(r) : "f"(y), "f"(x));
    return r;
}
// packed f32x2 helpers
__device__ __forceinline__ ull pack2(float x, float y) {
    ull r; asm("mov.b64 %0,{%1,%2};" : "=l"(r) : "f"(x), "f"(y)); return r;
}
__device__ __forceinline__ float2 unpack2(ull v) {
    float2 r; asm("mov.b64 {%0,%1},%2;" : "=f"(r.x), "=f"(r.y) : "l"(v)); return r;
}
__device__ __forceinline__ void ffma2(ull& c, ull a, ull b) {
    asm("fma.rn.f32x2 %0,%1,%2,%0;" : "+l"(c) : "l"(a), "l"(b));
}
__device__ __forceinline__ float2 bf2f(uint32_t u) {
    __nv_bfloat162 h = *reinterpret_cast<__nv_bfloat162*>(&u);
    return __bfloat1622float2(h);
}

// ---------------- scratch (device globals) ------------
__device__ __nv_bfloat16 g_XB [(size_t)NBT * HW * CI];   // conv1 input, NHWC bf16
__device__ __nv_bfloat16 g_T1B[(size_t)NBT * HW * CE];   // conv1 out, NHWC bf16
__device__ __nv_bfloat16 g_E2B[(size_t)NBT * HW * CE];   // ec2 out, NHWC bf16
__device__ float g_W81[(size_t)BQ  * HW * K81];
__device__ float g_FSN[(size_t)BQ  * HW * CI];           // feature_select NHWC fp32
__device__ float g_ALN[(size_t)BQ  * HW * CI];           // align NHWC fp32
__device__ float g_A3 [(size_t)NBT * HW];
__device__ __nv_bfloat16 g_WTE[9 * 64 * 64];             // ec2 weights bf16 [tap][oc][ic]
__device__ __nv_bfloat16 g_WTA[9 * 32 * 64];             // ag2 weights bf16
__device__ __nv_bfloat16 g_W1E[64 * CI];                 // ec1 weights bf16 [oc][ic]
__device__ __nv_bfloat16 g_W1A[64 * CI];                 // ag1 weights bf16

// ------- NCHW fp32 [4][128][HW] (fs|fc) -> NHWC bf16 [8][HW][128] + fsn fp32 --
__global__ void k_prep_xb(const float* __restrict__ fs, const float* __restrict__ fc,
                          __nv_bfloat16* __restrict__ dst, float* __restrict__ fsn) {
    __shared__ float t[32][33];
    int n = blockIdx.z, ct = blockIdx.y;   // ct: channel tile 0..3
    const float* s = ((n < BQ) ? fs : fc) + (size_t)(n & 3) * CI * HW;
    __nv_bfloat16* d = dst + (size_t)n * HW * CI;
    int b0 = blockIdx.x * 32;
    int tx = threadIdx.x, ty = threadIdx.y;
#pragma unroll
    for (int i = 0; i < 4; i++)
        t[ty + i * 8][tx] = s[(size_t)(ct * 32 + ty + i * 8) * HW + b0 + tx];
    __syncthreads();
#pragma unroll
    for (int i = 0; i < 4; i++) {
        float v = t[tx][ty + i * 8];
        size_t off = (size_t)(b0 + ty + i * 8) * CI + ct * 32 + tx;
        d[off] = __float2bfloat16(v);
        if (n < BQ) fsn[(size_t)n * HW * CI + off] = v;
    }
}

// --------- merged weight prep (all four weight tensors in one launch) ---------
__global__ void k_wprep_all(const float* __restrict__ ec2_w, const float* __restrict__ ag2_w,
                            const float* __restrict__ ec1_w, const float* __restrict__ ag1_w,
                            __nv_bfloat16* __restrict__ wte, __nv_bfloat16* __restrict__ wta,
                            __nv_bfloat16* __restrict__ w1e, __nv_bfloat16* __restrict__ w1a) {
    int i = blockIdx.x * 256 + threadIdx.x;
    if (i < 36864) {                      // ec2: 9*64*64, tap-major transform
        int ic = i & 63, rest = i >> 6;
        int oc = rest % 64, tap = rest / 64;
        wte[((size_t)tap * 64 + oc) * 64 + ic] = __float2bfloat16(ec2_w[((size_t)oc * 64 + ic) * 9 + tap]);
    } else if (i < 55296) {               // ag2: 9*32*64
        int j = i - 36864;
        int ic = j & 63, rest = j >> 6;
        int oc = rest % 32, tap = rest / 32;
        wta[((size_t)tap * 32 + oc) * 64 + ic] = __float2bfloat16(ag2_w[((size_t)oc * 64 + ic) * 9 + tap]);
    } else if (i < 63488) {               // ec1: 64*128
        int j = i - 55296;
        w1e[j] = __float2bfloat16(ec1_w[j]);
    } else if (i < 71680) {               // ag1: 64*128
        int j = i - 63488;
        w1a[j] = __float2bfloat16(ag1_w[j]);
    }
}

// ---------------- 1x1 conv via bf16 mma.sync (B via ldmatrix) -----------------
// CTA: 64 pixels (M) x 64 (N), K=128. 128 threads = 4 warps, warp owns 16 rows.
__global__ __launch_bounds__(128) void conv1_hmma(
    const __nv_bfloat16* __restrict__ xb,
    const __nv_bfloat16* __restrict__ wb,
    const float* __restrict__ bias,
    __nv_bfloat16* __restrict__ out)
{
    constexpr int LDA = 136;
    __shared__ __align__(16) __nv_bfloat16 As[64 * LDA];
    __shared__ __align__(16) __nv_bfloat16 Bs[64 * LDA];

    int tid = threadIdx.x;
    int wid = tid >> 5, l = tid & 31;
    int n = blockIdx.y;
    int p0 = blockIdx.x * 64;
    int m0 = wid * 16;

    {
        int r = tid >> 1, h = tid & 1;
        int p = p0 + r;
        bool v = p < HW;
        const uint4* src = reinterpret_cast<const uint4*>(
            xb + ((size_t)n * HW + (v ? p : 0)) * CI + h * 64);
        uint4* dst = reinterpret_cast<uint4*>(As + r * LDA + h * 64);
        uint4 zz = make_uint4(0u, 0u, 0u, 0u);
#pragma unroll
        for (int c = 0; c < 8; c++) dst[c] = v ? src[c] : zz;
    }
    {
        const uint4* src = reinterpret_cast<const uint4*>(wb);
#pragma unroll
        for (int i = 0; i < 8; i++) {
            int e = tid + i * 128;
            int row = e >> 4, h8 = e & 15;
            *reinterpret_cast<uint4*>(Bs + row * LDA + h8 * 8) = src[e];
        }
    }
    __syncthreads();

    uint32_t as_base = smem_u32(As);
    uint32_t bs_base = smem_u32(Bs);

    float acc[8][4];
#pragma unroll
    for (int t = 0; t < 8; t++)
#pragma unroll
        for (int i = 0; i < 4; i++) acc[t][i] = 0.f;

    int bro = ((l >> 4) & 1) * 8 + (l & 7);     // B tile row per lane
    int bko = ((l >> 3) & 1) * 8;                // B tile k-half per lane

#pragma unroll
    for (int ks = 0; ks < 8; ks++) {
        uint32_t afrag[4];
        uint32_t aaddr = as_base + ((m0 + (l & 15)) * LDA + ((l >> 4) * 8 + ks * 16)) * 2;
        ldmatrix_x4(afrag, aaddr);
#pragma unroll
        for (int tp = 0; tp < 4; tp++) {
            uint32_t bf[4];
            uint32_t baddr = bs_base + ((tp * 16 + bro) * LDA + ks * 16 + bko) * 2;
            ldmatrix_x4(bf, baddr);
            mma16816(acc[2 * tp],     afrag, bf[0], bf[1]);
            mma16816(acc[2 * tp + 1], afrag, bf[2], bf[3]);
        }
    }

    int row_a = m0 + (l >> 2);
    int col0 = (l & 3) * 2;
#pragma unroll
    for (int half = 0; half < 2; half++) {
        int prow = p0 + row_a + half * 8;
        if (prow >= HW) continue;
        __nv_bfloat16* ob = out + ((size_t)n * HW + prow) * CE;
#pragma unroll
        for (int nt = 0; nt < 8; nt++) {
            int c = nt * 8 + col0;
            float vx = fmaxf(acc[nt][half * 2 + 0] + bias[c],     0.f);
            float vy = fmaxf(acc[nt][half * 2 + 1] + bias[c + 1], 0.f);
            *reinterpret_cast<uint32_t*>(ob + c) = bf16x2(vx, vy);
        }
    }
}

// ---------------- 3x3 conv, 2D halo-resident tile (B via ldmatrix) ------------
// CTA = 8 rows x 16 cols of pixels (128 M-rows). Halo 10x18 cells x 64ch bf16
// loaded ONCE; 9 taps via per-lane shifted ldmatrix addresses. B double-buffered.
// FUSE_AG: epilogue fuses ag3 (32->1 dot + ReLU) and writes a3.
template <int OC, bool FUSE_AG>
__global__ __launch_bounds__(256) void conv3_tile(
    const __nv_bfloat16* __restrict__ inb,
    const __nv_bfloat16* __restrict__ wt,
    const float* __restrict__ bias,
    const float* __restrict__ w3,
    const float* __restrict__ b3,
    void* __restrict__ out_)
{
    constexpr int LDC = 72;              // halves per 64-ch cell (16B stagger)
    constexpr int NT  = OC / 8;
    constexpr int NTP = NT / 2;
    __shared__ __align__(16) __nv_bfloat16 Hs[180 * LDC];        // 10x18 halo
    __shared__ __align__(16) __nv_bfloat16 Bs[2][OC * LDC];

    int tid = threadIdx.x;
    int wid = tid >> 5, l = tid & 31;
    int n = blockIdx.y;
    int tile = blockIdx.x;
    int tx0 = (tile % 13) * 16, ty0 = (tile / 13) * 8;

    const __nv_bfloat16* src_base = inb + (size_t)n * HW * CE;

    // --- halo load: 180 cells x 8 uint4
    {
        uint4 zz = make_uint4(0u, 0u, 0u, 0u);
        for (int i = tid; i < 1440; i += 256) {
            int q = i & 7, cell = i >> 3;
            int hr = cell / 18, hc = cell - hr * 18;
            int yy = ty0 - 1 + hr, xx = tx0 - 1 + hc;
            uint4 val = zz;
            if ((unsigned)yy < HB && (unsigned)xx < WB)
                val = *reinterpret_cast<const uint4*>(
                    src_base + ((size_t)(yy * WB + xx)) * CE + q * 8);
            *reinterpret_cast<uint4*>(&Hs[cell * LDC + q * 8]) = val;
        }
    }
    // --- stage B tap 0 into buffer 0
    for (int i = tid; i < OC * 8; i += 256) {
        int row = i >> 3, q = i & 7;
        *reinterpret_cast<uint4*>(&Bs[0][row * LDC + q * 8]) =
            *reinterpret_cast<const uint4*>(wt + (size_t)row * 64 + q * 8);
    }
    __syncthreads();

    uint32_t hs_base = smem_u32(Hs);
    uint32_t bs_base0 = smem_u32(&Bs[0][0]);
    uint32_t bs_base1 = smem_u32(&Bs[1][0]);

    float acc[NT][4];
#pragma unroll
    for (int t = 0; t < NT; t++)
#pragma unroll
        for (int i = 0; i < 4; i++) acc[t][i] = 0.f;

    int tc = l & 15;            // A-row pixel col within tile (rows of warp = wid)
    int chalf = (l >> 4) * 8;   // 8-col half select for A ldmatrix
    int bro = ((l >> 4) & 1) * 8 + (l & 7);
    int bko = ((l >> 3) & 1) * 8;

#pragma unroll
    for (int tap = 0; tap < 9; tap++) {
        int dy = tap / 3, dx = tap % 3;
        uint32_t bs_cur = (tap & 1) ? bs_base1 : bs_base0;
        uint32_t acell = hs_base + (((wid + dy) * 18 + (tc + dx)) * LDC + chalf) * 2;
#pragma unroll
        for (int ks = 0; ks < 4; ks++) {
            uint32_t afrag[4];
            ldmatrix_x4(afrag, acell + ks * 32);
#pragma unroll
            for (int tp = 0; tp < NTP; tp++) {
                uint32_t bf[4];
                uint32_t baddr = bs_cur + ((tp * 16 + bro) * LDC + ks * 16 + bko) * 2;
                ldmatrix_x4(bf, baddr);
                mma16816(acc[2 * tp],     afrag, bf[0], bf[1]);
                mma16816(acc[2 * tp + 1], afrag, bf[2], bf[3]);
            }
        }
        if (tap < 8) {
            __nv_bfloat16* bdst = &Bs[(tap + 1) & 1][0];
            const __nv_bfloat16* bsrc = wt + (size_t)(tap + 1) * OC * 64;
            for (int i = tid; i < OC * 8; i += 256) {
                int row = i >> 3, q = i & 7;
                *reinterpret_cast<uint4*>(bdst + row * LDC + q * 8) =
                    *reinterpret_cast<const uint4*>(bsrc + (size_t)row * 64 + q * 8);
            }
            __syncthreads();
        }
    }

    // --- epilogue
    int y = ty0 + wid;                   // output pixel row (always < HB)
    int col0 = (l & 3) * 2;
    if (FUSE_AG) {
        float dot0 = 0.f, dot1 = 0.f;
#pragma unroll
        for (int nt = 0; nt < NT; nt++) {
            int c = nt * 8 + col0;
            float b0v = bias[c], b1v = bias[c + 1];
            float w0 = w3[c], w1 = w3[c + 1];
            dot0 += fmaxf(acc[nt][0] + b0v, 0.f) * w0 + fmaxf(acc[nt][1] + b1v, 0.f) * w1;
            dot1 += fmaxf(acc[nt][2] + b0v, 0.f) * w0 + fmaxf(acc[nt][3] + b1v, 0.f) * w1;
        }
        dot0 += __shfl_xor_sync(0xffffffffu, dot0, 1);
        dot0 += __shfl_xor_sync(0xffffffffu, dot0, 2);
        dot1 += __shfl_xor_sync(0xffffffffu, dot1, 1);
        dot1 += __shfl_xor_sync(0xffffffffu, dot1, 2);
        if ((l & 3) == 0) {
            float b3v = b3[0];
            float* a3 = (float*)out_;
            int x0p = tx0 + (l >> 2);
            if (x0p < WB)     a3[(size_t)n * HW + y * WB + x0p]     = fmaxf(dot0 + b3v, 0.f);
            if (x0p + 8 < WB) a3[(size_t)n * HW + y * WB + x0p + 8] = fmaxf(dot1 + b3v, 0.f);
        }
    } else {
#pragma unroll
        for (int half = 0; half < 2; half++) {
            int x = tx0 + (l >> 2) + half * 8;
            if (x >= WB) continue;
            __nv_bfloat16* ob = (__nv_bfloat16*)out_ + ((size_t)n * HW + y * WB + x) * OC;
#pragma unroll
            for (int nt = 0; nt < NT; nt++) {
                int c = nt * 8 + col0;
                float vx = fmaxf(acc[nt][half * 2 + 0] + bias[c],     0.f);
                float vy = fmaxf(acc[nt][half * 2 + 1] + bias[c + 1], 0.f);
                *reinterpret_cast<uint32_t*>(ob + c) = bf16x2(vx, vy);
            }
        }
    }
}

// ---------------- correlation + softmax, 2x8-pixel SMEM-tiled halo ------------
// 512 threads = 16 warps, warp per pixel (2 rows x 8 cols). Halo 10x16 cells.
__global__ __launch_bounds__(512) void k_corr(
    const __nv_bfloat16* __restrict__ e2b, float* __restrict__ w81)
{
    __shared__ __align__(16) __nv_bfloat16 Ecur[160 * 72];
    __shared__ float logits_s[16][88];
    int n = blockIdx.y;
    int tid = threadIdx.x;
    int warp = tid >> 5, l = tid & 31;
    int bx = blockIdx.x;                       // 2500 per batch
    int px0 = (bx % 25) * 8, py0 = (bx / 25) * 2;
    int wr = warp >> 3, wc = warp & 7;         // pixel in tile
    int p = (py0 + wr) * WB + px0 + wc;
    int og = l & 7, cg = l >> 3;

    const __nv_bfloat16* ecur = e2b + (size_t)(n + BQ) * HW * CE;

    // halo load: 160 cells x 8 uint4 = 1280
    {
        uint4 zz = make_uint4(0u, 0u, 0u, 0u);
        for (int i = tid; i < 1280; i += 512) {
            int q = i & 7, cell = i >> 3;
            int hr = cell >> 4, hc = cell & 15;
            int yy = py0 - RR + hr, xx = px0 - RR + hc;
            uint4 val = zz;
            if ((unsigned)yy < HB && (unsigned)xx < WB)
                val = *reinterpret_cast<const uint4*>(
                    ecur + ((size_t)(yy * WB + xx)) * CE + q * 8);
            *reinterpret_cast<uint4*>(&Ecur[cell * 72 + q * 8]) = val;
        }
    }

    // esel: 16 channels for this lane's channel-group, packed as f32x2 pairs
    ull es2[8];
    {
        const uint4* esel = reinterpret_cast<const uint4*>(
            e2b + ((size_t)n * HW + p) * CE + cg * 16);
        uint4 ea = esel[0], eb = esel[1];
        uint32_t w[8] = {ea.x, ea.y, ea.z, ea.w, eb.x, eb.y, eb.z, eb.w};
#pragma unroll
        for (int i = 0; i < 8; i++) {
            float2 f = bf2f(w[i]);
            es2[i] = pack2(f.x, f.y);
        }
    }
    __syncthreads();

#pragma unroll
    for (int r = 0; r < 11; r++) {
        int k = r * 8 + og;
        float dot = 0.f;
        if (k < K81) {
            int di = k / 9, dj = k % 9;        // 0..8
            int cell = (wr + di) * 16 + (wc + dj);
            const uint4* ec4 = reinterpret_cast<const uint4*>(&Ecur[cell * 72 + cg * 16]);
            uint4 c0v = ec4[0], c1v = ec4[1];
            uint32_t w[8] = {c0v.x, c0v.y, c0v.z, c0v.w, c1v.x, c1v.y, c1v.z, c1v.w};
            ull acc2 = 0ull;
#pragma unroll
            for (int i = 0; i < 8; i++) {
                float2 f = bf2f(w[i]);
                ffma2(acc2, es2[i], pack2(f.x, f.y));
            }
            float2 rr = unpack2(acc2);
            dot = rr.x + rr.y;
        }
        dot += __shfl_xor_sync(0xffffffffu, dot, 8);
        dot += __shfl_xor_sync(0xffffffffu, dot, 16);
        if (cg == 0 && k < K81) logits_s[warp][k] = dot;
    }
    __syncwarp();

    float c0 = logits_s[warp][l];
    float c1 = logits_s[warp][32 + l];
    float c2 = (l < 17) ? logits_s[warp][64 + l] : -3.0e38f;
    float mx = fmaxf(c0, fmaxf(c1, c2));
#pragma unroll
    for (int s = 16; s > 0; s >>= 1) mx = fmaxf(mx, __shfl_xor_sync(0xffffffffu, mx, s));
    float e0 = __expf(c0 - mx);
    float e1 = __expf(c1 - mx);
    float e2v = (l < 17) ? __expf(c2 - mx) : 0.f;
    float sm = e0 + e1 + e2v;
#pragma unroll
    for (int s = 16; s > 0; s >>= 1) sm += __shfl_xor_sync(0xffffffffu, sm, s);
    float inv = 1.f / sm;
    size_t base = ((size_t)n * HW + p) * K81;
    w81[base + l]      = e0 * inv;
    w81[base + 32 + l] = e1 * inv;
    if (l < 17) w81[base + 64 + l] = e2v * inv;
}

// ---------------- weighted aggregation, warp per 4 consecutive x-pixels ------
// f32x2-packed accumulation. Writes fp32 aln AND bf16 XB batches 0..3.
__global__ __launch_bounds__(256) void k_align(
    const float* __restrict__ w81, const float* __restrict__ fsn,
    float* __restrict__ aln, __nv_bfloat16* __restrict__ xb)
{
    int n = blockIdx.y;
    int warp = threadIdx.x >> 5, l = threadIdx.x & 31;
    int pg = blockIdx.x * 8 + warp;
    int p0 = pg * 4;
    if (p0 >= HW) return;
    int y = p0 / WB, x0 = p0 - y * WB;

    const float* wp = w81 + ((size_t)n * HW + p0) * K81;
    const float* fb = fsn + (size_t)n * HW * CI;

    ull acc2[4][2];
#pragma unroll
    for (int m = 0; m < 4; m++) { acc2[m][0] = 0ull; acc2[m][1] = 0ull; }

    for (int di = -RR; di <= RR; di++) {
        int yy = y + di;
        if ((unsigned)yy >= HB) continue;
        float4 fq[12];
#pragma unroll
        for (int j = 0; j < 12; j++) {
            int xx = x0 - RR + j;
            fq[j] = ((unsigned)xx < WB)
                ? *(const float4*)(fb + ((size_t)(yy * WB + xx)) * CI + 4 * l)
                : make_float4(0.f, 0.f, 0.f, 0.f);
        }
        int kbase = (di + RR) * 9;
#pragma unroll
        for (int m = 0; m < 4; m++) {
#pragma unroll
            for (int dj = 0; dj < 9; dj++) {
                float wv = wp[m * K81 + kbase + dj];
                ull wv2 = pack2(wv, wv);
                float4 f = fq[m + dj];
                ffma2(acc2[m][0], pack2(f.x, f.y), wv2);
                ffma2(acc2[m][1], pack2(f.z, f.w), wv2);
            }
        }
    }
#pragma unroll
    for (int m = 0; m < 4; m++) {
        float2 lo = unpack2(acc2[m][0]), hi = unpack2(acc2[m][1]);
        size_t off = ((size_t)n * HW + p0 + m) * CI + 4 * l;
        float4 v = make_float4(lo.x, lo.y, hi.x, hi.y);
        *(float4*)(aln + off) = v;
        *(uint2*)(xb + off) = make_uint2(bf16x2(v.x, v.y), bf16x2(v.z, v.w));
    }
}

// ------- final blend fused with NHWC->NCHW transpose --------------------------
__global__ void k_final(const float* __restrict__ a3, const float* __restrict__ aln,
                        const float* __restrict__ fc, float* __restrict__ out) {
    __shared__ float t[32][33];
    int n = blockIdx.z;
    int c0 = blockIdx.x * 32, p0 = blockIdx.y * 32;
    int tx = threadIdx.x, ty = threadIdx.y;
#pragma unroll
    for (int i = 0; i < 4; i++)
        t[ty + i * 8][tx] = aln[((size_t)n * HW + p0 + ty + i * 8) * CI + c0 + tx];
    int p = p0 + tx;
    float as = a3[(size_t)n * HW + p];
    float ac = a3[(size_t)(n + BQ) * HW + p];
    float m = fmaxf(as, ac);
    float ea = __expf(as - m), eb = __expf(ac - m);
    float inv = 1.f / (ea + eb);
    float ws = ea * inv, wc = eb * inv;
    __syncthreads();
#pragma unroll
    for (int i = 0; i < 4; i++) {
        int c = c0 + ty + i * 8;
        size_t o = ((size_t)n * CI + c) * HW + p;
        out[o] = ws * t[tx][ty + i * 8] + wc * fc[o];
    }
}

// ---------------- launch ------------------------------------------------------
extern "C" void kernel_launch(void* const* d_in, const int* in_sizes, int n_in,
                              void* d_out, int out_size) {
    const float* fs    = (const float*)d_in[0];
    const float* fc    = (const float*)d_in[1];
    const float* ec1_w = (const float*)d_in[2];
    const float* ec1_b = (const float*)d_in[3];
    const float* ec2_w = (const float*)d_in[4];
    const float* ec2_b = (const float*)d_in[5];
    const float* ag1_w = (const float*)d_in[6];
    const float* ag1_b = (const float*)d_in[7];
    const float* ag2_w = (const float*)d_in[8];
    const float* ag2_b = (const float*)d_in[9];
    const float* ag3_w = (const float*)d_in[10];
    const float* ag3_b = (const float*)d_in[11];
    float* out = (float*)d_out;

    float *w81, *fsn, *aln, *a3;
    __nv_bfloat16 *xb, *t1b, *e2b, *wte, *wta, *w1e, *w1a;
    cudaGetSymbolAddress((void**)&xb,  g_XB);
    cudaGetSymbolAddress((void**)&t1b, g_T1B);
    cudaGetSymbolAddress((void**)&e2b, g_E2B);
    cudaGetSymbolAddress((void**)&w81, g_W81);
    cudaGetSymbolAddress((void**)&fsn, g_FSN);
    cudaGetSymbolAddress((void**)&aln, g_ALN);
    cudaGetSymbolAddress((void**)&a3,  g_A3);
    cudaGetSymbolAddress((void**)&wte, g_WTE);
    cudaGetSymbolAddress((void**)&wta, g_WTA);
    cudaGetSymbolAddress((void**)&w1e, g_W1E);
    cudaGetSymbolAddress((void**)&w1a, g_W1A);

    const int M64  = (HW + 63) / 64;     // 625
    const int T3   = 13 * 25;            // 325 conv3 tiles per batch

    // merged weight prep
    k_wprep_all<<<(71680 + 255) / 256, 256>>>(ec2_w, ag2_w, ec1_w, ag1_w, wte, wta, w1e, w1a);

    // input prep (also produces fsn fp32 NHWC for batches 0..3)
    k_prep_xb<<<dim3(HW / 32, 4, NBT), dim3(32, 8)>>>(fs, fc, xb, fsn);

    // encoder
    conv1_hmma<<<dim3(M64, NBT), 128>>>(xb, w1e, ec1_b, t1b);
    conv3_tile<64, false><<<dim3(T3, NBT), 256>>>(t1b, wte, ec2_b, nullptr, nullptr, e2b);

    // correlation + softmax (2x8 pixel tiles)
    k_corr<<<dim3(2500, BQ), 512>>>(e2b, w81);

    // weighted aggregation (writes fp32 aln + bf16 xb[0..3])
    k_align<<<dim3(HW / 32, BQ), 256>>>(w81, fsn, aln, xb);

    // gating head (ag2+ag3 fused)
    conv1_hmma<<<dim3(M64, NBT), 128>>>(xb, w1a, ag1_b, t1b);
    conv3_tile<32, true><<<dim3(T3, NBT), 256>>>(t1b, wta, ag2_b, ag3_w, ag3_b, a3);

    // final blend (transpose fused)
    k_final<<<dim3(CI / 32, HW / 32, BQ), dim3(32, 8)>>>(a3, aln, fc, out);
}

// round 16
// speedup vs baseline: 2.5469x; 1.0479x over previous
#include <cuda_runtime.h>
#include <cuda_bf16.h>
#include <cstdint>

// Problem constants
#define HB 200
#define WB 200
#define HW 40000          // H*W
#define BQ 4              // batch
#define NBT 8             // 2*batch (cat)
#define CI 128            // input channels
#define CE 64             // embed channels
#define RR 4              // neighborhood radius
#define K81 81            // 9x9 offsets

typedef unsigned long long ull;

__device__ __forceinline__ uint32_t smem_u32(const void* p) {
    uint32_t a;
    asm("{ .reg .u64 t; cvta.to.shared.u64 t, %1; cvt.u32.u64 %0, t; }" : "=r"(a) : "l"(p));
    return a;
}

// warp-level bf16 MMA: D(16x8,f32) += A(16x16,bf16) * B(16x8,bf16)
__device__ __forceinline__ void mma16816(float* c, const uint32_t* a, uint32_t b0, uint32_t b1) {
    asm volatile(
        "mma.sync.aligned.m16n8k16.row.col.f32.bf16.bf16.f32 "
        "{%0,%1,%2,%3}, {%4,%5,%6,%7}, {%8,%9}, {%0,%1,%2,%3};"
        : "+f"(c[0]), "+f"(c[1]), "+f"(c[2]), "+f"(c[3])
        : "r"(a[0]), "r"(a[1]), "r"(a[2]), "r"(a[3]), "r"(b0), "r"(b1));
}
__device__ __forceinline__ void ldmatrix_x4(uint32_t* r, uint32_t addr) {
    asm volatile("ldmatrix.sync.aligned.m8n8.x4.shared.b16 {%0,%1,%2,%3}, [%4];"
                 : "=r"(r[0]), "=r"(r[1]), "=r"(r[2]), "=r"(r[3]) : "r"(addr));
}
__device__ __forceinline__ uint32_t bf16x2(float x, float y) {
    uint32_t r;
    asm("cvt.rn.satfinite.bf16x2.f32 %0, %1, %2;" : "=r"(r) : "f"(y), "f"(x));
    return r;
}
// packed f32x2 helpers
__device__ __forceinline__ ull pack2(float x, float y) {
    ull r; asm("mov.b64 %0,{%1,%2};" : "=l"(r) : "f"(x), "f"(y)); return r;
}
__device__ __forceinline__ float2 unpack2(ull v) {
    float2 r; asm("mov.b64 {%0,%1},%2;" : "=f"(r.x), "=f"(r.y) : "l"(v)); return r;
}
__device__ __forceinline__ void ffma2(ull& c, ull a, ull b) {
    asm("fma.rn.f32x2 %0,%1,%2,%0;" : "+l"(c) : "l"(a), "l"(b));
}
__device__ __forceinline__ float2 bf2f(uint32_t u) {
    __nv_bfloat162 h = *reinterpret_cast<__nv_bfloat162*>(&u);
    return __bfloat1622float2(h);
}

// ---------------- scratch (device globals) ------------
__device__ __nv_bfloat16 g_XB [(size_t)NBT * HW * CI];   // conv1 input, NHWC bf16
__device__ __nv_bfloat16 g_T1B[(size_t)NBT * HW * CE];   // conv1 out, NHWC bf16
__device__ __nv_bfloat16 g_E2B[(size_t)NBT * HW * CE];   // ec2 out, NHWC bf16
__device__ float g_W81[(size_t)BQ  * HW * K81];
__device__ float g_FSN[(size_t)BQ  * HW * CI];           // feature_select NHWC fp32
__device__ float g_ALN[(size_t)BQ  * HW * CI];           // align NHWC fp32
__device__ float g_A3 [(size_t)NBT * HW];
__device__ __nv_bfloat16 g_WTE[9 * 64 * 64];             // ec2 weights bf16 [tap][oc][ic]
__device__ __nv_bfloat16 g_WTA[9 * 32 * 64];             // ag2 weights bf16
__device__ __nv_bfloat16 g_W1E[64 * CI];                 // ec1 weights bf16 [oc][ic]
__device__ __nv_bfloat16 g_W1A[64 * CI];                 // ag1 weights bf16

// ------- NCHW fp32 [4][128][HW] (fs|fc) -> NHWC bf16 [8][HW][128] + fsn fp32 --
__global__ void k_prep_xb(const float* __restrict__ fs, const float* __restrict__ fc,
                          __nv_bfloat16* __restrict__ dst, float* __restrict__ fsn) {
    __shared__ float t[32][33];
    int n = blockIdx.z, ct = blockIdx.y;   // ct: channel tile 0..3
    const float* s = ((n < BQ) ? fs : fc) + (size_t)(n & 3) * CI * HW;
    __nv_bfloat16* d = dst + (size_t)n * HW * CI;
    int b0 = blockIdx.x * 32;
    int tx = threadIdx.x, ty = threadIdx.y;
#pragma unroll
    for (int i = 0; i < 4; i++)
        t[ty + i * 8][tx] = s[(size_t)(ct * 32 + ty + i * 8) * HW + b0 + tx];
    __syncthreads();
#pragma unroll
    for (int i = 0; i < 4; i++) {
        float v = t[tx][ty + i * 8];
        size_t off = (size_t)(b0 + ty + i * 8) * CI + ct * 32 + tx;
        d[off] = __float2bfloat16(v);
        if (n < BQ) fsn[(size_t)n * HW * CI + off] = v;
    }
}

// --------- merged weight prep (all four weight tensors in one launch) ---------
__global__ void k_wprep_all(const float* __restrict__ ec2_w, const float* __restrict__ ag2_w,
                            const float* __restrict__ ec1_w, const float* __restrict__ ag1_w,
                            __nv_bfloat16* __restrict__ wte, __nv_bfloat16* __restrict__ wta,
                            __nv_bfloat16* __restrict__ w1e, __nv_bfloat16* __restrict__ w1a) {
    int i = blockIdx.x * 256 + threadIdx.x;
    if (i < 36864) {                      // ec2: 9*64*64, tap-major transform
        int ic = i & 63, rest = i >> 6;
        int oc = rest % 64, tap = rest / 64;
        wte[((size_t)tap * 64 + oc) * 64 + ic] = __float2bfloat16(ec2_w[((size_t)oc * 64 + ic) * 9 + tap]);
    } else if (i < 55296) {               // ag2: 9*32*64
        int j = i - 36864;
        int ic = j & 63, rest = j >> 6;
        int oc = rest % 32, tap = rest / 32;
        wta[((size_t)tap * 32 + oc) * 64 + ic] = __float2bfloat16(ag2_w[((size_t)oc * 64 + ic) * 9 + tap]);
    } else if (i < 63488) {               // ec1: 64*128
        int j = i - 55296;
        w1e[j] = __float2bfloat16(ec1_w[j]);
    } else if (i < 71680) {               // ag1: 64*128
        int j = i - 63488;
        w1a[j] = __float2bfloat16(ag1_w[j]);
    }
}

// ---------------- 1x1 conv via bf16 mma.sync, 2 M-tiles per warp --------------
// CTA: 128 pixels (M) x 64 (N), K=128. 128 threads = 4 warps; warp owns 32 rows
// (two 16-row A tiles) so each B fragment feeds 2x the MMAs. Dynamic SMEM 52KB.
__global__ __launch_bounds__(128) void conv1_hmma(
    const __nv_bfloat16* __restrict__ xb,
    const __nv_bfloat16* __restrict__ wb,
    const float* __restrict__ bias,
    __nv_bfloat16* __restrict__ out)
{
    constexpr int LDA = 136;
    extern __shared__ __align__(16) char smem_c1[];
    __nv_bfloat16* As = reinterpret_cast<__nv_bfloat16*>(smem_c1);               // 128*136
    __nv_bfloat16* Bs = reinterpret_cast<__nv_bfloat16*>(smem_c1 + 128 * LDA * 2); // 64*136

    int tid = threadIdx.x;
    int wid = tid >> 5, l = tid & 31;
    int n = blockIdx.y;
    int p0 = blockIdx.x * 128;
    int m0 = wid * 32;

    {   // stage A: 128 rows x 128 halves; thread = row, 16 uint4 each
        int r = tid;
        int p = p0 + r;
        bool v = p < HW;
        const uint4* src = reinterpret_cast<const uint4*>(
            xb + ((size_t)n * HW + (v ? p : 0)) * CI);
        uint4* dst = reinterpret_cast<uint4*>(As + r * LDA);
        uint4 zz = make_uint4(0u, 0u, 0u, 0u);
#pragma unroll
        for (int c = 0; c < 16; c++) dst[c] = v ? src[c] : zz;
    }
    {   // stage B: 64 rows x 128 halves = 1024 uint4
        const uint4* src = reinterpret_cast<const uint4*>(wb);
#pragma unroll
        for (int i = 0; i < 8; i++) {
            int e = tid + i * 128;
            int row = e >> 4, h8 = e & 15;
            *reinterpret_cast<uint4*>(Bs + row * LDA + h8 * 8) = src[e];
        }
    }
    __syncthreads();

    uint32_t as_base = smem_u32(As);
    uint32_t bs_base = smem_u32(Bs);

    float acc[2][8][4];
#pragma unroll
    for (int at = 0; at < 2; at++)
#pragma unroll
        for (int t = 0; t < 8; t++)
#pragma unroll
            for (int i = 0; i < 4; i++) acc[at][t][i] = 0.f;

    int bro = ((l >> 4) & 1) * 8 + (l & 7);     // B tile row per lane
    int bko = ((l >> 3) & 1) * 8;                // B tile k-half per lane

#pragma unroll
    for (int ks = 0; ks < 8; ks++) {
        uint32_t afrag[2][4];
#pragma unroll
        for (int at = 0; at < 2; at++) {
            uint32_t aaddr = as_base +
                ((m0 + at * 16 + (l & 15)) * LDA + ((l >> 4) * 8 + ks * 16)) * 2;
            ldmatrix_x4(afrag[at], aaddr);
        }
#pragma unroll
        for (int tp = 0; tp < 4; tp++) {
            uint32_t bf[4];
            uint32_t baddr = bs_base + ((tp * 16 + bro) * LDA + ks * 16 + bko) * 2;
            ldmatrix_x4(bf, baddr);
#pragma unroll
            for (int at = 0; at < 2; at++) {
                mma16816(acc[at][2 * tp],     afrag[at], bf[0], bf[1]);
                mma16816(acc[at][2 * tp + 1], afrag[at], bf[2], bf[3]);
            }
        }
    }

    int col0 = (l & 3) * 2;
#pragma unroll
    for (int at = 0; at < 2; at++) {
        int row_a = m0 + at * 16 + (l >> 2);
#pragma unroll
        for (int half = 0; half < 2; half++) {
            int prow = p0 + row_a + half * 8;
            if (prow >= HW) continue;
            __nv_bfloat16* ob = out + ((size_t)n * HW + prow) * CE;
#pragma unroll
            for (int nt = 0; nt < 8; nt++) {
                int c = nt * 8 + col0;
                float vx = fmaxf(acc[at][nt][half * 2 + 0] + bias[c],     0.f);
                float vy = fmaxf(acc[at][nt][half * 2 + 1] + bias[c + 1], 0.f);
                *reinterpret_cast<uint32_t*>(ob + c) = bf16x2(vx, vy);
            }
        }
    }
}

// ---------------- 3x3 conv, 16x16 halo-resident tile, 2 rows per warp ---------
// CTA = 16x16 pixels (8 warps x 2 tile-rows). Halo 18x18 cells x 64ch bf16
// loaded ONCE (dynamic SMEM); B double-buffered; each B fragment feeds 2 A tiles.
// FUSE_AG: epilogue fuses ag3 (32->1 dot + ReLU) and writes a3.
template <int OC, bool FUSE_AG>
__global__ __launch_bounds__(256) void conv3_tile(
    const __nv_bfloat16* __restrict__ inb,
    const __nv_bfloat16* __restrict__ wt,
    const float* __restrict__ bias,
    const float* __restrict__ w3,
    const float* __restrict__ b3,
    void* __restrict__ out_)
{
    constexpr int LDC = 72;              // halves per 64-ch cell (16B stagger)
    constexpr int NT  = OC / 8;
    constexpr int NTP = NT / 2;
    constexpr int HCELLS = 18 * 18;      // 324
    extern __shared__ __align__(16) char smem_c3[];
    __nv_bfloat16* Hs = reinterpret_cast<__nv_bfloat16*>(smem_c3);                    // 324*72
    __nv_bfloat16* Bs0 = reinterpret_cast<__nv_bfloat16*>(smem_c3 + HCELLS * LDC * 2);
    __nv_bfloat16* Bs1 = Bs0 + OC * LDC;

    int tid = threadIdx.x;
    int wid = tid >> 5, l = tid & 31;
    int n = blockIdx.y;
    int tile = blockIdx.x;
    int tx0 = (tile % 13) * 16, ty0 = (tile / 13) * 16;

    const __nv_bfloat16* src_base = inb + (size_t)n * HW * CE;

    // --- halo load: 324 cells x 8 uint4 = 2592
    {
        uint4 zz = make_uint4(0u, 0u, 0u, 0u);
        for (int i = tid; i < HCELLS * 8; i += 256) {
            int q = i & 7, cell = i >> 3;
            int hr = cell / 18, hc = cell - hr * 18;
            int yy = ty0 - 1 + hr, xx = tx0 - 1 + hc;
            uint4 val = zz;
            if ((unsigned)yy < HB && (unsigned)xx < WB)
                val = *reinterpret_cast<const uint4*>(
                    src_base + ((size_t)(yy * WB + xx)) * CE + q * 8);
            *reinterpret_cast<uint4*>(&Hs[cell * LDC + q * 8]) = val;
        }
    }
    // --- stage B tap 0 into buffer 0
    for (int i = tid; i < OC * 8; i += 256) {
        int row = i >> 3, q = i & 7;
        *reinterpret_cast<uint4*>(&Bs0[row * LDC + q * 8]) =
            *reinterpret_cast<const uint4*>(wt + (size_t)row * 64 + q * 8);
    }
    __syncthreads();

    uint32_t hs_base = smem_u32(Hs);
    uint32_t bs_base0 = smem_u32(Bs0);
    uint32_t bs_base1 = smem_u32(Bs1);

    float acc[2][NT][4];
#pragma unroll
    for (int at = 0; at < 2; at++)
#pragma unroll
        for (int t = 0; t < NT; t++)
#pragma unroll
            for (int i = 0; i < 4; i++) acc[at][t][i] = 0.f;

    int tc = l & 15;            // A-col within tile
    int chalf = (l >> 4) * 8;   // 8-col half select for A ldmatrix
    int bro = ((l >> 4) & 1) * 8 + (l & 7);
    int bko = ((l >> 3) & 1) * 8;

#pragma unroll
    for (int tap = 0; tap < 9; tap++) {
        int dy = tap / 3, dx = tap % 3;
        uint32_t bs_cur = (tap & 1) ? bs_base1 : bs_base0;
        uint32_t acell0 = hs_base + (((2 * wid + dy) * 18 + (tc + dx)) * LDC + chalf) * 2;
        uint32_t acell1 = acell0 + 18 * LDC * 2;
#pragma unroll
        for (int ks = 0; ks < 4; ks++) {
            uint32_t afrag[2][4];
            ldmatrix_x4(afrag[0], acell0 + ks * 32);
            ldmatrix_x4(afrag[1], acell1 + ks * 32);
#pragma unroll
            for (int tp = 0; tp < NTP; tp++) {
                uint32_t bf[4];
                uint32_t baddr = bs_cur + ((tp * 16 + bro) * LDC + ks * 16 + bko) * 2;
                ldmatrix_x4(bf, baddr);
#pragma unroll
                for (int at = 0; at < 2; at++) {
                    mma16816(acc[at][2 * tp],     afrag[at], bf[0], bf[1]);
                    mma16816(acc[at][2 * tp + 1], afrag[at], bf[2], bf[3]);
                }
            }
        }
        if (tap < 8) {
            __nv_bfloat16* bdst = (tap & 1) ? Bs0 : Bs1;   // write the other buffer
            const __nv_bfloat16* bsrc = wt + (size_t)(tap + 1) * OC * 64;
            for (int i = tid; i < OC * 8; i += 256) {
                int row = i >> 3, q = i & 7;
                *reinterpret_cast<uint4*>(bdst + row * LDC + q * 8) =
                    *reinterpret_cast<const uint4*>(bsrc + (size_t)row * 64 + q * 8);
            }
            __syncthreads();
        }
    }

    // --- epilogue
    int col0 = (l & 3) * 2;
#pragma unroll
    for (int at = 0; at < 2; at++) {
        int y = ty0 + 2 * wid + at;
        if (y >= HB) continue;
        if (FUSE_AG) {
            float dot0 = 0.f, dot1 = 0.f;
#pragma unroll
            for (int nt = 0; nt < NT; nt++) {
                int c = nt * 8 + col0;
                float b0v = bias[c], b1v = bias[c + 1];
                float w0 = w3[c], w1 = w3[c + 1];
                dot0 += fmaxf(acc[at][nt][0] + b0v, 0.f) * w0 + fmaxf(acc[at][nt][1] + b1v, 0.f) * w1;
                dot1 += fmaxf(acc[at][nt][2] + b0v, 0.f) * w0 + fmaxf(acc[at][nt][3] + b1v, 0.f) * w1;
            }
            dot0 += __shfl_xor_sync(0xffffffffu, dot0, 1);
            dot0 += __shfl_xor_sync(0xffffffffu, dot0, 2);
            dot1 += __shfl_xor_sync(0xffffffffu, dot1, 1);
            dot1 += __shfl_xor_sync(0xffffffffu, dot1, 2);
            if ((l & 3) == 0) {
                float b3v = b3[0];
                float* a3 = (float*)out_;
                int x0p = tx0 + (l >> 2);
                if (x0p < WB)     a3[(size_t)n * HW + y * WB + x0p]     = fmaxf(dot0 + b3v, 0.f);
                if (x0p + 8 < WB) a3[(size_t)n * HW + y * WB + x0p + 8] = fmaxf(dot1 + b3v, 0.f);
            }
        } else {
#pragma unroll
            for (int half = 0; half < 2; half++) {
                int x = tx0 + (l >> 2) + half * 8;
                if (x >= WB) continue;
                __nv_bfloat16* ob = (__nv_bfloat16*)out_ + ((size_t)n * HW + y * WB + x) * OC;
#pragma unroll
                for (int nt = 0; nt < NT; nt++) {
                    int c = nt * 8 + col0;
                    float vx = fmaxf(acc[at][nt][half * 2 + 0] + bias[c],     0.f);
                    float vy = fmaxf(acc[at][nt][half * 2 + 1] + bias[c + 1], 0.f);
                    *reinterpret_cast<uint32_t*>(ob + c) = bf16x2(vx, vy);
                }
            }
        }
    }
}

// ---------------- correlation + softmax, 2x8-pixel SMEM-tiled halo ------------
// 512 threads = 16 warps, warp per pixel (2 rows x 8 cols). Halo 10x16 cells.
__global__ __launch_bounds__(512) void k_corr(
    const __nv_bfloat16* __restrict__ e2b, float* __restrict__ w81)
{
    __shared__ __align__(16) __nv_bfloat16 Ecur[160 * 72];
    __shared__ float logits_s[16][88];
    int n = blockIdx.y;
    int tid = threadIdx.x;
    int warp = tid >> 5, l = tid & 31;
    int bx = blockIdx.x;                       // 2500 per batch
    int px0 = (bx % 25) * 8, py0 = (bx / 25) * 2;
    int wr = warp >> 3, wc = warp & 7;         // pixel in tile
    int p = (py0 + wr) * WB + px0 + wc;
    int og = l & 7, cg = l >> 3;

    const __nv_bfloat16* ecur = e2b + (size_t)(n + BQ) * HW * CE;

    // halo load: 160 cells x 8 uint4 = 1280
    {
        uint4 zz = make_uint4(0u, 0u, 0u, 0u);
        for (int i = tid; i < 1280; i += 512) {
            int q = i & 7, cell = i >> 3;
            int hr = cell >> 4, hc = cell & 15;
            int yy = py0 - RR + hr, xx = px0 - RR + hc;
            uint4 val = zz;
            if ((unsigned)yy < HB && (unsigned)xx < WB)
                val = *reinterpret_cast<const uint4*>(
                    ecur + ((size_t)(yy * WB + xx)) * CE + q * 8);
            *reinterpret_cast<uint4*>(&Ecur[cell * 72 + q * 8]) = val;
        }
    }

    // esel: 16 channels for this lane's channel-group, packed as f32x2 pairs
    ull es2[8];
    {
        const uint4* esel = reinterpret_cast<const uint4*>(
            e2b + ((size_t)n * HW + p) * CE + cg * 16);
        uint4 ea = esel[0], eb = esel[1];
        uint32_t w[8] = {ea.x, ea.y, ea.z, ea.w, eb.x, eb.y, eb.z, eb.w};
#pragma unroll
        for (int i = 0; i < 8; i++) {
            float2 f = bf2f(w[i]);
            es2[i] = pack2(f.x, f.y);
        }
    }
    __syncthreads();

#pragma unroll
    for (int r = 0; r < 11; r++) {
        int k = r * 8 + og;
        float dot = 0.f;
        if (k < K81) {
            int di = k / 9, dj = k % 9;        // 0..8
            int cell = (wr + di) * 16 + (wc + dj);
            const uint4* ec4 = reinterpret_cast<const uint4*>(&Ecur[cell * 72 + cg * 16]);
            uint4 c0v = ec4[0], c1v = ec4[1];
            uint32_t w[8] = {c0v.x, c0v.y, c0v.z, c0v.w, c1v.x, c1v.y, c1v.z, c1v.w};
            ull acc2 = 0ull;
#pragma unroll
            for (int i = 0; i < 8; i++) {
                float2 f = bf2f(w[i]);
                ffma2(acc2, es2[i], pack2(f.x, f.y));
            }
            float2 rr = unpack2(acc2);
            dot = rr.x + rr.y;
        }
        dot += __shfl_xor_sync(0xffffffffu, dot, 8);
        dot += __shfl_xor_sync(0xffffffffu, dot, 16);
        if (cg == 0 && k < K81) logits_s[warp][k] = dot;
    }
    __syncwarp();

    float c0 = logits_s[warp][l];
    float c1 = logits_s[warp][32 + l];
    float c2 = (l < 17) ? logits_s[warp][64 + l] : -3.0e38f;
    float mx = fmaxf(c0, fmaxf(c1, c2));
#pragma unroll
    for (int s = 16; s > 0; s >>= 1) mx = fmaxf(mx, __shfl_xor_sync(0xffffffffu, mx, s));
    float e0 = __expf(c0 - mx);
    float e1 = __expf(c1 - mx);
    float e2v = (l < 17) ? __expf(c2 - mx) : 0.f;
    float sm = e0 + e1 + e2v;
#pragma unroll
    for (int s = 16; s > 0; s >>= 1) sm += __shfl_xor_sync(0xffffffffu, sm, s);
    float inv = 1.f / sm;
    size_t base = ((size_t)n * HW + p) * K81;
    w81[base + l]      = e0 * inv;
    w81[base + 32 + l] = e1 * inv;
    if (l < 17) w81[base + 64 + l] = e2v * inv;
}

// ---------------- weighted aggregation, warp per 4 consecutive x-pixels ------
// f32x2-packed accumulation. Writes fp32 aln AND bf16 XB batches 0..3.
__global__ __launch_bounds__(256) void k_align(
    const float* __restrict__ w81, const float* __restrict__ fsn,
    float* __restrict__ aln, __nv_bfloat16* __restrict__ xb)
{
    int n = blockIdx.y;
    int warp = threadIdx.x >> 5, l = threadIdx.x & 31;
    int pg = blockIdx.x * 8 + warp;
    int p0 = pg * 4;
    if (p0 >= HW) return;
    int y = p0 / WB, x0 = p0 - y * WB;

    const float* wp = w81 + ((size_t)n * HW + p0) * K81;
    const float* fb = fsn + (size_t)n * HW * CI;

    ull acc2[4][2];
#pragma unroll
    for (int m = 0; m < 4; m++) { acc2[m][0] = 0ull; acc2[m][1] = 0ull; }

    for (int di = -RR; di <= RR; di++) {
        int yy = y + di;
        if ((unsigned)yy >= HB) continue;
        float4 fq[12];
#pragma unroll
        for (int j = 0; j < 12; j++) {
            int xx = x0 - RR + j;
            fq[j] = ((unsigned)xx < WB)
                ? *(const float4*)(fb + ((size_t)(yy * WB + xx)) * CI + 4 * l)
                : make_float4(0.f, 0.f, 0.f, 0.f);
        }
        int kbase = (di + RR) * 9;
#pragma unroll
        for (int m = 0; m < 4; m++) {
#pragma unroll
            for (int dj = 0; dj < 9; dj++) {
                float wv = wp[m * K81 + kbase + dj];
                ull wv2 = pack2(wv, wv);
                float4 f = fq[m + dj];
                ffma2(acc2[m][0], pack2(f.x, f.y), wv2);
                ffma2(acc2[m][1], pack2(f.z, f.w), wv2);
            }
        }
    }
#pragma unroll
    for (int m = 0; m < 4; m++) {
        float2 lo = unpack2(acc2[m][0]), hi = unpack2(acc2[m][1]);
        size_t off = ((size_t)n * HW + p0 + m) * CI + 4 * l;
        float4 v = make_float4(lo.x, lo.y, hi.x, hi.y);
        *(float4*)(aln + off) = v;
        *(uint2*)(xb + off) = make_uint2(bf16x2(v.x, v.y), bf16x2(v.z, v.w));
    }
}

// ------- final blend fused with NHWC->NCHW transpose --------------------------
__global__ void k_final(const float* __restrict__ a3, const float* __restrict__ aln,
                        const float* __restrict__ fc, float* __restrict__ out) {
    __shared__ float t[32][33];
    int n = blockIdx.z;
    int c0 = blockIdx.x * 32, p0 = blockIdx.y * 32;
    int tx = threadIdx.x, ty = threadIdx.y;
#pragma unroll
    for (int i = 0; i < 4; i++)
        t[ty + i * 8][tx] = aln[((size_t)n * HW + p0 + ty + i * 8) * CI + c0 + tx];
    int p = p0 + tx;
    float as = a3[(size_t)n * HW + p];
    float ac = a3[(size_t)(n + BQ) * HW + p];
    float m = fmaxf(as, ac);
    float ea = __expf(as - m), eb = __expf(ac - m);
    float inv = 1.f / (ea + eb);
    float ws = ea * inv, wc = eb * inv;
    __syncthreads();
#pragma unroll
    for (int i = 0; i < 4; i++) {
        int c = c0 + ty + i * 8;
        size_t o = ((size_t)n * CI + c) * HW + p;
        out[o] = ws * t[tx][ty + i * 8] + wc * fc[o];
    }
}

// ---------------- launch ------------------------------------------------------
extern "C" void kernel_launch(void* const* d_in, const int* in_sizes, int n_in,
                              void* d_out, int out_size) {
    const float* fs    = (const float*)d_in[0];
    const float* fc    = (const float*)d_in[1];
    const float* ec1_w = (const float*)d_in[2];
    const float* ec1_b = (const float*)d_in[3];
    const float* ec2_w = (const float*)d_in[4];
    const float* ec2_b = (const float*)d_in[5];
    const float* ag1_w = (const float*)d_in[6];
    const float* ag1_b = (const float*)d_in[7];
    const float* ag2_w = (const float*)d_in[8];
    const float* ag2_b = (const float*)d_in[9];
    const float* ag3_w = (const float*)d_in[10];
    const float* ag3_b = (const float*)d_in[11];
    float* out = (float*)d_out;

    float *w81, *fsn, *aln, *a3;
    __nv_bfloat16 *xb, *t1b, *e2b, *wte, *wta, *w1e, *w1a;
    cudaGetSymbolAddress((void**)&xb,  g_XB);
    cudaGetSymbolAddress((void**)&t1b, g_T1B);
    cudaGetSymbolAddress((void**)&e2b, g_E2B);
    cudaGetSymbolAddress((void**)&w81, g_W81);
    cudaGetSymbolAddress((void**)&fsn, g_FSN);
    cudaGetSymbolAddress((void**)&aln, g_ALN);
    cudaGetSymbolAddress((void**)&a3,  g_A3);
    cudaGetSymbolAddress((void**)&wte, g_WTE);
    cudaGetSymbolAddress((void**)&wta, g_WTA);
    cudaGetSymbolAddress((void**)&w1e, g_W1E);
    cudaGetSymbolAddress((void**)&w1a, g_W1A);

    const int M128 = (HW + 127) / 128;   // 313
    const int T3   = 13 * 13;            // 169 conv3 tiles per batch (16x16)

    // dynamic SMEM sizes
    const int SM_C1  = 128 * 136 * 2 + 64 * 136 * 2;          // 52224
    const int SM_C64 = 324 * 72 * 2 + 2 * 64 * 72 * 2;        // 65088
    const int SM_C32 = 324 * 72 * 2 + 2 * 32 * 72 * 2;        // 55872
    static bool attr_set = false;
    if (!attr_set) {
        cudaFuncSetAttribute(conv1_hmma, cudaFuncAttributeMaxDynamicSharedMemorySize, SM_C1);
        cudaFuncSetAttribute(conv3_tile<64, false>, cudaFuncAttributeMaxDynamicSharedMemorySize, SM_C64);
        cudaFuncSetAttribute(conv3_tile<32, true>, cudaFuncAttributeMaxDynamicSharedMemorySize, SM_C32);
        attr_set = true;
    }

    // merged weight prep
    k_wprep_all<<<(71680 + 255) / 256, 256>>>(ec2_w, ag2_w, ec1_w, ag1_w, wte, wta, w1e, w1a);

    // input prep (also produces fsn fp32 NHWC for batches 0..3)
    k_prep_xb<<<dim3(HW / 32, 4, NBT), dim3(32, 8)>>>(fs, fc, xb, fsn);

    // encoder
    conv1_hmma<<<dim3(M128, NBT), 128, SM_C1>>>(xb, w1e, ec1_b, t1b);
    conv3_tile<64, false><<<dim3(T3, NBT), 256, SM_C64>>>(t1b, wte, ec2_b, nullptr, nullptr, e2b);

    // correlation + softmax (2x8 pixel tiles)
    k_corr<<<dim3(2500, BQ), 512>>>(e2b, w81);

    // weighted aggregation (writes fp32 aln + bf16 xb[0..3])
    k_align<<<dim3(HW / 32, BQ), 256>>>(w81, fsn, aln, xb);

    // gating head (ag2+ag3 fused)
    conv1_hmma<<<dim3(M128, NBT), 128, SM_C1>>>(xb, w1a, ag1_b, t1b);
    conv3_tile<32, true><<<dim3(T3, NBT), 256, SM_C32>>>(t1b, wta, ag2_b, ag3_w, ag3_b, a3);

    // final blend (transpose fused)
    k_final<<<dim3(CI / 32, HW / 32, BQ), dim3(32, 8)>>>(a3, aln, fc, out);
}

// round 17
// speedup vs baseline: 2.5656x; 1.0073x over previous
#include <cuda_runtime.h>
#include <cuda_bf16.h>
#include <cstdint>

// Problem constants
#define HB 200
#define WB 200
#define HW 40000          // H*W
#define BQ 4              // batch
#define NBT 8             // 2*batch (cat)
#define CI 128            // input channels
#define CE 64             // embed channels
#define RR 4              // neighborhood radius
#define K81 81            // 9x9 offsets

typedef unsigned long long ull;

__device__ __forceinline__ uint32_t smem_u32(const void* p) {
    uint32_t a;
    asm("{ .reg .u64 t; cvta.to.shared.u64 t, %1; cvt.u32.u64 %0, t; }" : "=r"(a) : "l"(p));
    return a;
}

// warp-level bf16 MMA: D(16x8,f32) += A(16x16,bf16) * B(16x8,bf16)
__device__ __forceinline__ void mma16816(float* c, const uint32_t* a, uint32_t b0, uint32_t b1) {
    asm volatile(
        "mma.sync.aligned.m16n8k16.row.col.f32.bf16.bf16.f32 "
        "{%0,%1,%2,%3}, {%4,%5,%6,%7}, {%8,%9}, {%0,%1,%2,%3};"
        : "+f"(c[0]), "+f"(c[1]), "+f"(c[2]), "+f"(c[3])
        : "r"(a[0]), "r"(a[1]), "r"(a[2]), "r"(a[3]), "r"(b0), "r"(b1));
}
__device__ __forceinline__ void ldmatrix_x4(uint32_t* r, uint32_t addr) {
    asm volatile("ldmatrix.sync.aligned.m8n8.x4.shared.b16 {%0,%1,%2,%3}, [%4];"
                 : "=r"(r[0]), "=r"(r[1]), "=r"(r[2]), "=r"(r[3]) : "r"(addr));
}
__device__ __forceinline__ uint32_t bf16x2(float x, float y) {
    uint32_t r;
    asm("cvt.rn.satfinite.bf16x2.f32 %0, %1, %2;" : "=r"(r) : "f"(y), "f"(x));
    return r;
}
// packed f32x2 helpers
__device__ __forceinline__ ull pack2(float x, float y) {
    ull r; asm("mov.b64 %0,{%1,%2};" : "=l"(r) : "f"(x), "f"(y)); return r;
}
__device__ __forceinline__ float2 unpack2(ull v) {
    float2 r; asm("mov.b64 {%0,%1},%2;" : "=f"(r.x), "=f"(r.y) : "l"(v)); return r;
}
__device__ __forceinline__ void ffma2(ull& c, ull a, ull b) {
    asm("fma.rn.f32x2 %0,%1,%2,%0;" : "+l"(c) : "l"(a), "l"(b));
}
__device__ __forceinline__ float2 bf2f(uint32_t u) {
    __nv_bfloat162 h = *reinterpret_cast<__nv_bfloat162*>(&u);
    return __bfloat1622float2(h);
}

// ---------------- scratch (device globals) ------------
__device__ __nv_bfloat16 g_XB [(size_t)NBT * HW * CI];   // conv1 input, NHWC bf16
__device__ __nv_bfloat16 g_T1B[(size_t)NBT * HW * CE];   // conv1 out, NHWC bf16
__device__ __nv_bfloat16 g_E2B[(size_t)NBT * HW * CE];   // ec2 out, NHWC bf16
__device__ float g_W81[(size_t)BQ  * HW * K81];
__device__ float g_FSN[(size_t)BQ  * HW * CI];           // feature_select NHWC fp32
__device__ float g_ALN[(size_t)BQ  * HW * CI];           // align NHWC fp32
__device__ float g_A3 [(size_t)NBT * HW];
__device__ __nv_bfloat16 g_WTE[9 * 64 * 64];             // ec2 weights bf16 [tap][oc][ic]
__device__ __nv_bfloat16 g_WTA[9 * 32 * 64];             // ag2 weights bf16
__device__ __nv_bfloat16 g_W1E[64 * CI];                 // ec1 weights bf16 [oc][ic]
__device__ __nv_bfloat16 g_W1A[64 * CI];                 // ag1 weights bf16

// ------- NCHW fp32 [4][128][HW] (fs|fc) -> NHWC bf16 [8][HW][128] + fsn fp32 --
__global__ void k_prep_xb(const float* __restrict__ fs, const float* __restrict__ fc,
                          __nv_bfloat16* __restrict__ dst, float* __restrict__ fsn) {
    __shared__ float t[32][33];
    int n = blockIdx.z, ct = blockIdx.y;   // ct: channel tile 0..3
    const float* s = ((n < BQ) ? fs : fc) + (size_t)(n & 3) * CI * HW;
    __nv_bfloat16* d = dst + (size_t)n * HW * CI;
    int b0 = blockIdx.x * 32;
    int tx = threadIdx.x, ty = threadIdx.y;
#pragma unroll
    for (int i = 0; i < 4; i++)
        t[ty + i * 8][tx] = s[(size_t)(ct * 32 + ty + i * 8) * HW + b0 + tx];
    __syncthreads();
#pragma unroll
    for (int i = 0; i < 4; i++) {
        float v = t[tx][ty + i * 8];
        size_t off = (size_t)(b0 + ty + i * 8) * CI + ct * 32 + tx;
        d[off] = __float2bfloat16(v);
        if (n < BQ) fsn[(size_t)n * HW * CI + off] = v;
    }
}

// --------- merged weight prep (all four weight tensors in one launch) ---------
__global__ void k_wprep_all(const float* __restrict__ ec2_w, const float* __restrict__ ag2_w,
                            const float* __restrict__ ec1_w, const float* __restrict__ ag1_w,
                            __nv_bfloat16* __restrict__ wte, __nv_bfloat16* __restrict__ wta,
                            __nv_bfloat16* __restrict__ w1e, __nv_bfloat16* __restrict__ w1a) {
    int i = blockIdx.x * 256 + threadIdx.x;
    if (i < 36864) {                      // ec2: 9*64*64, tap-major transform
        int ic = i & 63, rest = i >> 6;
        int oc = rest % 64, tap = rest / 64;
        wte[((size_t)tap * 64 + oc) * 64 + ic] = __float2bfloat16(ec2_w[((size_t)oc * 64 + ic) * 9 + tap]);
    } else if (i < 55296) {               // ag2: 9*32*64
        int j = i - 36864;
        int ic = j & 63, rest = j >> 6;
        int oc = rest % 32, tap = rest / 32;
        wta[((size_t)tap * 32 + oc) * 64 + ic] = __float2bfloat16(ag2_w[((size_t)oc * 64 + ic) * 9 + tap]);
    } else if (i < 63488) {               // ec1: 64*128
        int j = i - 55296;
        w1e[j] = __float2bfloat16(ec1_w[j]);
    } else if (i < 71680) {               // ag1: 64*128
        int j = i - 63488;
        w1a[j] = __float2bfloat16(ag1_w[j]);
    }
}

// ---------------- 1x1 conv via bf16 mma.sync, 2 M-tiles per warp --------------
// CTA: 128 pixels (M) x 64 (N), K=128. 128 threads = 4 warps; warp owns 32 rows
// (two 16-row A tiles) so each B fragment feeds 2x the MMAs. Dynamic SMEM 52KB.
__global__ __launch_bounds__(128) void conv1_hmma(
    const __nv_bfloat16* __restrict__ xb,
    const __nv_bfloat16* __restrict__ wb,
    const float* __restrict__ bias,
    __nv_bfloat16* __restrict__ out)
{
    constexpr int LDA = 136;
    extern __shared__ __align__(16) char smem_c1[];
    __nv_bfloat16* As = reinterpret_cast<__nv_bfloat16*>(smem_c1);               // 128*136
    __nv_bfloat16* Bs = reinterpret_cast<__nv_bfloat16*>(smem_c1 + 128 * LDA * 2); // 64*136

    int tid = threadIdx.x;
    int wid = tid >> 5, l = tid & 31;
    int n = blockIdx.y;
    int p0 = blockIdx.x * 128;
    int m0 = wid * 32;

    {   // stage A: 128 rows x 128 halves; thread = row, 16 uint4 each
        int r = tid;
        int p = p0 + r;
        bool v = p < HW;
        const uint4* src = reinterpret_cast<const uint4*>(
            xb + ((size_t)n * HW + (v ? p : 0)) * CI);
        uint4* dst = reinterpret_cast<uint4*>(As + r * LDA);
        uint4 zz = make_uint4(0u, 0u, 0u, 0u);
#pragma unroll
        for (int c = 0; c < 16; c++) dst[c] = v ? src[c] : zz;
    }
    {   // stage B: 64 rows x 128 halves = 1024 uint4
        const uint4* src = reinterpret_cast<const uint4*>(wb);
#pragma unroll
        for (int i = 0; i < 8; i++) {
            int e = tid + i * 128;
            int row = e >> 4, h8 = e & 15;
            *reinterpret_cast<uint4*>(Bs + row * LDA + h8 * 8) = src[e];
        }
    }
    __syncthreads();

    uint32_t as_base = smem_u32(As);
    uint32_t bs_base = smem_u32(Bs);

    float acc[2][8][4];
#pragma unroll
    for (int at = 0; at < 2; at++)
#pragma unroll
        for (int t = 0; t < 8; t++)
#pragma unroll
            for (int i = 0; i < 4; i++) acc[at][t][i] = 0.f;

    int bro = ((l >> 4) & 1) * 8 + (l & 7);     // B tile row per lane
    int bko = ((l >> 3) & 1) * 8;                // B tile k-half per lane

#pragma unroll
    for (int ks = 0; ks < 8; ks++) {
        uint32_t afrag[2][4];
#pragma unroll
        for (int at = 0; at < 2; at++) {
            uint32_t aaddr = as_base +
                ((m0 + at * 16 + (l & 15)) * LDA + ((l >> 4) * 8 + ks * 16)) * 2;
            ldmatrix_x4(afrag[at], aaddr);
        }
#pragma unroll
        for (int tp = 0; tp < 4; tp++) {
            uint32_t bf[4];
            uint32_t baddr = bs_base + ((tp * 16 + bro) * LDA + ks * 16 + bko) * 2;
            ldmatrix_x4(bf, baddr);
#pragma unroll
            for (int at = 0; at < 2; at++) {
                mma16816(acc[at][2 * tp],     afrag[at], bf[0], bf[1]);
                mma16816(acc[at][2 * tp + 1], afrag[at], bf[2], bf[3]);
            }
        }
    }

    int col0 = (l & 3) * 2;
#pragma unroll
    for (int at = 0; at < 2; at++) {
        int row_a = m0 + at * 16 + (l >> 2);
#pragma unroll
        for (int half = 0; half < 2; half++) {
            int prow = p0 + row_a + half * 8;
            if (prow >= HW) continue;
            __nv_bfloat16* ob = out + ((size_t)n * HW + prow) * CE;
#pragma unroll
            for (int nt = 0; nt < 8; nt++) {
                int c = nt * 8 + col0;
                float vx = fmaxf(acc[at][nt][half * 2 + 0] + bias[c],     0.f);
                float vy = fmaxf(acc[at][nt][half * 2 + 1] + bias[c + 1], 0.f);
                *reinterpret_cast<uint32_t*>(ob + c) = bf16x2(vx, vy);
            }
        }
    }
}

// ---------------- 3x3 conv, 16x16 halo-resident tile, 2 rows per warp ---------
// CTA = 16x16 pixels (8 warps x 2 tile-rows). Halo 18x18 cells x 64ch bf16
// loaded ONCE (dynamic SMEM).
// OC=32 (FUSE_AG): ALL 9 B taps preloaded -> sync-free mainloop.
// OC=64: B double-buffered with register prefetch of next tap before the MMAs.
// FUSE_AG: epilogue fuses ag3 (32->1 dot + ReLU) and writes a3.
template <int OC, bool FUSE_AG>
__global__ __launch_bounds__(256) void conv3_tile(
    const __nv_bfloat16* __restrict__ inb,
    const __nv_bfloat16* __restrict__ wt,
    const float* __restrict__ bias,
    const float* __restrict__ w3,
    const float* __restrict__ b3,
    void* __restrict__ out_)
{
    constexpr int LDC = 72;              // halves per 64-ch cell (16B stagger)
    constexpr int NT  = OC / 8;
    constexpr int NTP = NT / 2;
    constexpr int HCELLS = 18 * 18;      // 324
    constexpr bool PRELOAD_B = (OC == 32);
    extern __shared__ __align__(16) char smem_c3[];
    __nv_bfloat16* Hs = reinterpret_cast<__nv_bfloat16*>(smem_c3);                    // 324*72
    __nv_bfloat16* Bs0 = reinterpret_cast<__nv_bfloat16*>(smem_c3 + HCELLS * LDC * 2);
    __nv_bfloat16* Bs1 = Bs0 + OC * LDC;

    int tid = threadIdx.x;
    int wid = tid >> 5, l = tid & 31;
    int n = blockIdx.y;
    int tile = blockIdx.x;
    int tx0 = (tile % 13) * 16, ty0 = (tile / 13) * 16;

    const __nv_bfloat16* src_base = inb + (size_t)n * HW * CE;

    // --- halo load: 324 cells x 8 uint4 = 2592
    {
        uint4 zz = make_uint4(0u, 0u, 0u, 0u);
        for (int i = tid; i < HCELLS * 8; i += 256) {
            int q = i & 7, cell = i >> 3;
            int hr = cell / 18, hc = cell - hr * 18;
            int yy = ty0 - 1 + hr, xx = tx0 - 1 + hc;
            uint4 val = zz;
            if ((unsigned)yy < HB && (unsigned)xx < WB)
                val = *reinterpret_cast<const uint4*>(
                    src_base + ((size_t)(yy * WB + xx)) * CE + q * 8);
            *reinterpret_cast<uint4*>(&Hs[cell * LDC + q * 8]) = val;
        }
    }
    // --- stage B: all taps (OC=32) or tap 0 (OC=64)
    if (PRELOAD_B) {
        for (int i = tid; i < 9 * OC * 8; i += 256) {   // 2304 uint4
            int q = i & 7, gr = i >> 3;                 // gr = tap*OC + row
            *reinterpret_cast<uint4*>(&Bs0[gr * LDC + q * 8]) =
                *reinterpret_cast<const uint4*>(wt + (size_t)gr * 64 + q * 8);
        }
    } else {
        for (int i = tid; i < OC * 8; i += 256) {
            int row = i >> 3, q = i & 7;
            *reinterpret_cast<uint4*>(&Bs0[row * LDC + q * 8]) =
                *reinterpret_cast<const uint4*>(wt + (size_t)row * 64 + q * 8);
        }
    }
    __syncthreads();

    uint32_t hs_base = smem_u32(Hs);
    uint32_t bs_base0 = smem_u32(Bs0);
    uint32_t bs_base1 = smem_u32(Bs1);

    float acc[2][NT][4];
#pragma unroll
    for (int at = 0; at < 2; at++)
#pragma unroll
        for (int t = 0; t < NT; t++)
#pragma unroll
            for (int i = 0; i < 4; i++) acc[at][t][i] = 0.f;

    int tc = l & 15;            // A-col within tile
    int chalf = (l >> 4) * 8;   // 8-col half select for A ldmatrix
    int bro = ((l >> 4) & 1) * 8 + (l & 7);
    int bko = ((l >> 3) & 1) * 8;

#pragma unroll
    for (int tap = 0; tap < 9; tap++) {
        int dy = tap / 3, dx = tap % 3;
        uint32_t bs_cur;
        if (PRELOAD_B) bs_cur = bs_base0 + (tap * OC * LDC) * 2;
        else           bs_cur = (tap & 1) ? bs_base1 : bs_base0;

        // register prefetch of next tap's B (OC=64 path only)
        uint4 bpre0, bpre1;
        if (!PRELOAD_B && tap < 8) {
            const uint4* bsrc = reinterpret_cast<const uint4*>(wt + (size_t)(tap + 1) * OC * 64);
            bpre0 = bsrc[tid];
            bpre1 = bsrc[tid + 256];
        }

        uint32_t acell0 = hs_base + (((2 * wid + dy) * 18 + (tc + dx)) * LDC + chalf) * 2;
        uint32_t acell1 = acell0 + 18 * LDC * 2;
#pragma unroll
        for (int ks = 0; ks < 4; ks++) {
            uint32_t afrag[2][4];
            ldmatrix_x4(afrag[0], acell0 + ks * 32);
            ldmatrix_x4(afrag[1], acell1 + ks * 32);
#pragma unroll
            for (int tp = 0; tp < NTP; tp++) {
                uint32_t bf[4];
                uint32_t baddr = bs_cur + ((tp * 16 + bro) * LDC + ks * 16 + bko) * 2;
                ldmatrix_x4(bf, baddr);
#pragma unroll
                for (int at = 0; at < 2; at++) {
                    mma16816(acc[at][2 * tp],     afrag[at], bf[0], bf[1]);
                    mma16816(acc[at][2 * tp + 1], afrag[at], bf[2], bf[3]);
                }
            }
        }
        if (!PRELOAD_B && tap < 8) {
            __nv_bfloat16* bdst = (tap & 1) ? Bs0 : Bs1;   // write the other buffer
            {
                int row0 = tid >> 3, q0 = tid & 7;
                *reinterpret_cast<uint4*>(bdst + row0 * LDC + q0 * 8) = bpre0;
                int i1 = tid + 256;
                int row1 = i1 >> 3, q1 = i1 & 7;
                *reinterpret_cast<uint4*>(bdst + row1 * LDC + q1 * 8) = bpre1;
            }
            __syncthreads();
        }
    }

    // --- epilogue
    int col0 = (l & 3) * 2;
#pragma unroll
    for (int at = 0; at < 2; at++) {
        int y = ty0 + 2 * wid + at;
        if (y >= HB) continue;
        if (FUSE_AG) {
            float dot0 = 0.f, dot1 = 0.f;
#pragma unroll
            for (int nt = 0; nt < NT; nt++) {
                int c = nt * 8 + col0;
                float b0v = bias[c], b1v = bias[c + 1];
                float w0 = w3[c], w1 = w3[c + 1];
                dot0 += fmaxf(acc[at][nt][0] + b0v, 0.f) * w0 + fmaxf(acc[at][nt][1] + b1v, 0.f) * w1;
                dot1 += fmaxf(acc[at][nt][2] + b0v, 0.f) * w0 + fmaxf(acc[at][nt][3] + b1v, 0.f) * w1;
            }
            dot0 += __shfl_xor_sync(0xffffffffu, dot0, 1);
            dot0 += __shfl_xor_sync(0xffffffffu, dot0, 2);
            dot1 += __shfl_xor_sync(0xffffffffu, dot1, 1);
            dot1 += __shfl_xor_sync(0xffffffffu, dot1, 2);
            if ((l & 3) == 0) {
                float b3v = b3[0];
                float* a3 = (float*)out_;
                int x0p = tx0 + (l >> 2);
                if (x0p < WB)     a3[(size_t)n * HW + y * WB + x0p]     = fmaxf(dot0 + b3v, 0.f);
                if (x0p + 8 < WB) a3[(size_t)n * HW + y * WB + x0p + 8] = fmaxf(dot1 + b3v, 0.f);
            }
        } else {
#pragma unroll
            for (int half = 0; half < 2; half++) {
                int x = tx0 + (l >> 2) + half * 8;
                if (x >= WB) continue;
                __nv_bfloat16* ob = (__nv_bfloat16*)out_ + ((size_t)n * HW + y * WB + x) * OC;
#pragma unroll
                for (int nt = 0; nt < NT; nt++) {
                    int c = nt * 8 + col0;
                    float vx = fmaxf(acc[at][nt][half * 2 + 0] + bias[c],     0.f);
                    float vy = fmaxf(acc[at][nt][half * 2 + 1] + bias[c + 1], 0.f);
                    *reinterpret_cast<uint32_t*>(ob + c) = bf16x2(vx, vy);
                }
            }
        }
    }
}

// ---------------- correlation + softmax, 2x8-pixel SMEM-tiled halo ------------
// 512 threads = 16 warps, warp per pixel (2 rows x 8 cols). Halo 10x16 cells.
__global__ __launch_bounds__(512) void k_corr(
    const __nv_bfloat16* __restrict__ e2b, float* __restrict__ w81)
{
    __shared__ __align__(16) __nv_bfloat16 Ecur[160 * 72];
    __shared__ float logits_s[16][88];
    int n = blockIdx.y;
    int tid = threadIdx.x;
    int warp = tid >> 5, l = tid & 31;
    int bx = blockIdx.x;                       // 2500 per batch
    int px0 = (bx % 25) * 8, py0 = (bx / 25) * 2;
    int wr = warp >> 3, wc = warp & 7;         // pixel in tile
    int p = (py0 + wr) * WB + px0 + wc;
    int og = l & 7, cg = l >> 3;

    const __nv_bfloat16* ecur = e2b + (size_t)(n + BQ) * HW * CE;

    // halo load: 160 cells x 8 uint4 = 1280
    {
        uint4 zz = make_uint4(0u, 0u, 0u, 0u);
        for (int i = tid; i < 1280; i += 512) {
            int q = i & 7, cell = i >> 3;
            int hr = cell >> 4, hc = cell & 15;
            int yy = py0 - RR + hr, xx = px0 - RR + hc;
            uint4 val = zz;
            if ((unsigned)yy < HB && (unsigned)xx < WB)
                val = *reinterpret_cast<const uint4*>(
                    ecur + ((size_t)(yy * WB + xx)) * CE + q * 8);
            *reinterpret_cast<uint4*>(&Ecur[cell * 72 + q * 8]) = val;
        }
    }

    // esel: 16 channels for this lane's channel-group, packed as f32x2 pairs
    ull es2[8];
    {
        const uint4* esel = reinterpret_cast<const uint4*>(
            e2b + ((size_t)n * HW + p) * CE + cg * 16);
        uint4 ea = esel[0], eb = esel[1];
        uint32_t w[8] = {ea.x, ea.y, ea.z, ea.w, eb.x, eb.y, eb.z, eb.w};
#pragma unroll
        for (int i = 0; i < 8; i++) {
            float2 f = bf2f(w[i]);
            es2[i] = pack2(f.x, f.y);
        }
    }
    __syncthreads();

#pragma unroll
    for (int r = 0; r < 11; r++) {
        int k = r * 8 + og;
        float dot = 0.f;
        if (k < K81) {
            int di = k / 9, dj = k % 9;        // 0..8
            int cell = (wr + di) * 16 + (wc + dj);
            const uint4* ec4 = reinterpret_cast<const uint4*>(&Ecur[cell * 72 + cg * 16]);
            uint4 c0v = ec4[0], c1v = ec4[1];
            uint32_t w[8] = {c0v.x, c0v.y, c0v.z, c0v.w, c1v.x, c1v.y, c1v.z, c1v.w};
            ull acc2 = 0ull;
#pragma unroll
            for (int i = 0; i < 8; i++) {
                float2 f = bf2f(w[i]);
                ffma2(acc2, es2[i], pack2(f.x, f.y));
            }
            float2 rr = unpack2(acc2);
            dot = rr.x + rr.y;
        }
        dot += __shfl_xor_sync(0xffffffffu, dot, 8);
        dot += __shfl_xor_sync(0xffffffffu, dot, 16);
        if (cg == 0 && k < K81) logits_s[warp][k] = dot;
    }
    __syncwarp();

    float c0 = logits_s[warp][l];
    float c1 = logits_s[warp][32 + l];
    float c2 = (l < 17) ? logits_s[warp][64 + l] : -3.0e38f;
    float mx = fmaxf(c0, fmaxf(c1, c2));
#pragma unroll
    for (int s = 16; s > 0; s >>= 1) mx = fmaxf(mx, __shfl_xor_sync(0xffffffffu, mx, s));
    float e0 = __expf(c0 - mx);
    float e1 = __expf(c1 - mx);
    float e2v = (l < 17) ? __expf(c2 - mx) : 0.f;
    float sm = e0 + e1 + e2v;
#pragma unroll
    for (int s = 16; s > 0; s >>= 1) sm += __shfl_xor_sync(0xffffffffu, sm, s);
    float inv = 1.f / sm;
    size_t base = ((size_t)n * HW + p) * K81;
    w81[base + l]      = e0 * inv;
    w81[base + 32 + l] = e1 * inv;
    if (l < 17) w81[base + 64 + l] = e2v * inv;
}

// ---------------- weighted aggregation, warp per 4 consecutive x-pixels ------
// f32x2-packed accumulation. Writes fp32 aln AND bf16 XB batches 0..3.
__global__ __launch_bounds__(256) void k_align(
    const float* __restrict__ w81, const float* __restrict__ fsn,
    float* __restrict__ aln, __nv_bfloat16* __restrict__ xb)
{
    int n = blockIdx.y;
    int warp = threadIdx.x >> 5, l = threadIdx.x & 31;
    int pg = blockIdx.x * 8 + warp;
    int p0 = pg * 4;
    if (p0 >= HW) return;
    int y = p0 / WB, x0 = p0 - y * WB;

    const float* wp = w81 + ((size_t)n * HW + p0) * K81;
    const float* fb = fsn + (size_t)n * HW * CI;

    ull acc2[4][2];
#pragma unroll
    for (int m = 0; m < 4; m++) { acc2[m][0] = 0ull; acc2[m][1] = 0ull; }

    for (int di = -RR; di <= RR; di++) {
        int yy = y + di;
        if ((unsigned)yy >= HB) continue;
        float4 fq[12];
#pragma unroll
        for (int j = 0; j < 12; j++) {
            int xx = x0 - RR + j;
            fq[j] = ((unsigned)xx < WB)
                ? *(const float4*)(fb + ((size_t)(yy * WB + xx)) * CI + 4 * l)
                : make_float4(0.f, 0.f, 0.f, 0.f);
        }
        int kbase = (di + RR) * 9;
#pragma unroll
        for (int m = 0; m < 4; m++) {
#pragma unroll
            for (int dj = 0; dj < 9; dj++) {
                float wv = wp[m * K81 + kbase + dj];
                ull wv2 = pack2(wv, wv);
                float4 f = fq[m + dj];
                ffma2(acc2[m][0], pack2(f.x, f.y), wv2);
                ffma2(acc2[m][1], pack2(f.z, f.w), wv2);
            }
        }
    }
#pragma unroll
    for (int m = 0; m < 4; m++) {
        float2 lo = unpack2(acc2[m][0]), hi = unpack2(acc2[m][1]);
        size_t off = ((size_t)n * HW + p0 + m) * CI + 4 * l;
        float4 v = make_float4(lo.x, lo.y, hi.x, hi.y);
        *(float4*)(aln + off) = v;
        *(uint2*)(xb + off) = make_uint2(bf16x2(v.x, v.y), bf16x2(v.z, v.w));
    }
}

// ------- final blend fused with NHWC->NCHW transpose --------------------------
__global__ void k_final(const float* __restrict__ a3, const float* __restrict__ aln,
                        const float* __restrict__ fc, float* __restrict__ out) {
    __shared__ float t[32][33];
    int n = blockIdx.z;
    int c0 = blockIdx.x * 32, p0 = blockIdx.y * 32;
    int tx = threadIdx.x, ty = threadIdx.y;
#pragma unroll
    for (int i = 0; i < 4; i++)
        t[ty + i * 8][tx] = aln[((size_t)n * HW + p0 + ty + i * 8) * CI + c0 + tx];
    int p = p0 + tx;
    float as = a3[(size_t)n * HW + p];
    float ac = a3[(size_t)(n + BQ) * HW + p];
    float m = fmaxf(as, ac);
    float ea = __expf(as - m), eb = __expf(ac - m);
    float inv = 1.f / (ea + eb);
    float ws = ea * inv, wc = eb * inv;
    __syncthreads();
#pragma unroll
    for (int i = 0; i < 4; i++) {
        int c = c0 + ty + i * 8;
        size_t o = ((size_t)n * CI + c) * HW + p;
        out[o] = ws * t[tx][ty + i * 8] + wc * fc[o];
    }
}

// ---------------- launch ------------------------------------------------------
extern "C" void kernel_launch(void* const* d_in, const int* in_sizes, int n_in,
                              void* d_out, int out_size) {
    const float* fs    = (const float*)d_in[0];
    const float* fc    = (const float*)d_in[1];
    const float* ec1_w = (const float*)d_in[2];
    const float* ec1_b = (const float*)d_in[3];
    const float* ec2_w = (const float*)d_in[4];
    const float* ec2_b = (const float*)d_in[5];
    const float* ag1_w = (const float*)d_in[6];
    const float* ag1_b = (const float*)d_in[7];
    const float* ag2_w = (const float*)d_in[8];
    const float* ag2_b = (const float*)d_in[9];
    const float* ag3_w = (const float*)d_in[10];
    const float* ag3_b = (const float*)d_in[11];
    float* out = (float*)d_out;

    float *w81, *fsn, *aln, *a3;
    __nv_bfloat16 *xb, *t1b, *e2b, *wte, *wta, *w1e, *w1a;
    cudaGetSymbolAddress((void**)&xb,  g_XB);
    cudaGetSymbolAddress((void**)&t1b, g_T1B);
    cudaGetSymbolAddress((void**)&e2b, g_E2B);
    cudaGetSymbolAddress((void**)&w81, g_W81);
    cudaGetSymbolAddress((void**)&fsn, g_FSN);
    cudaGetSymbolAddress((void**)&aln, g_ALN);
    cudaGetSymbolAddress((void**)&a3,  g_A3);
    cudaGetSymbolAddress((void**)&wte, g_WTE);
    cudaGetSymbolAddress((void**)&wta, g_WTA);
    cudaGetSymbolAddress((void**)&w1e, g_W1E);
    cudaGetSymbolAddress((void**)&w1a, g_W1A);

    const int M128 = (HW + 127) / 128;   // 313
    const int T3   = 13 * 13;            // 169 conv3 tiles per batch (16x16)

    // dynamic SMEM sizes
    const int SM_C1  = 128 * 136 * 2 + 64 * 136 * 2;          // 52224
    const int SM_C64 = 324 * 72 * 2 + 2 * 64 * 72 * 2;        // 65088
    const int SM_C32 = 324 * 72 * 2 + 9 * 32 * 72 * 2;        // 88128 (all taps)
    static bool attr_set = false;
    if (!attr_set) {
        cudaFuncSetAttribute(conv1_hmma, cudaFuncAttributeMaxDynamicSharedMemorySize, SM_C1);
        cudaFuncSetAttribute(conv3_tile<64, false>, cudaFuncAttributeMaxDynamicSharedMemorySize, SM_C64);
        cudaFuncSetAttribute(conv3_tile<32, true>, cudaFuncAttributeMaxDynamicSharedMemorySize, SM_C32);
        attr_set = true;
    }

    // merged weight prep
    k_wprep_all<<<(71680 + 255) / 256, 256>>>(ec2_w, ag2_w, ec1_w, ag1_w, wte, wta, w1e, w1a);

    // input prep (also produces fsn fp32 NHWC for batches 0..3)
    k_prep_xb<<<dim3(HW / 32, 4, NBT), dim3(32, 8)>>>(fs, fc, xb, fsn);

    // encoder
    conv1_hmma<<<dim3(M128, NBT), 128, SM_C1>>>(xb, w1e, ec1_b, t1b);
    conv3_tile<64, false><<<dim3(T3, NBT), 256, SM_C64>>>(t1b, wte, ec2_b, nullptr, nullptr, e2b);

    // correlation + softmax (2x8 pixel tiles)
    k_corr<<<dim3(2500, BQ), 512>>>(e2b, w81);

    // weighted aggregation (writes fp32 aln + bf16 xb[0..3])
    k_align<<<dim3(HW / 32, BQ), 256>>>(w81, fsn, aln, xb);

    // gating head (ag2+ag3 fused, sync-free mainloop)
    conv1_hmma<<<dim3(M128, NBT), 128, SM_C1>>>(xb, w1a, ag1_b, t1b);
    conv3_tile<32, true><<<dim3(T3, NBT), 256, SM_C32>>>(t1b, wta, ag2_b, ag3_w, ag3_b, a3);

    // final blend (transpose fused)
    k_final<<<dim3(CI / 32, HW / 32, BQ), dim3(32, 8)>>>(a3, aln, fc, out);
}